// round 3
// baseline (speedup 1.0000x reference)
#include <cuda_runtime.h>
#include <math_constants.h>

#define BATCH 2
#define NP    4096
#define NQ    16384
#define FDIM  448            // 64 + 128 + 256
#define AGGP  720            // 707 padded to multiple of 16
#define NPTS  (BATCH * NQ)   // 32768 total query points
#define MPTS  (BATCH * NP)   // 8192 original points

// ---------------- scratch (device globals; no allocation allowed) ----------
__device__ float g_fall[MPTS * FDIM];          // point-major (f1|f2|f3)
__device__ int   g_gmax[BATCH * 256];          // global max (float bits, vals>=0)
__device__ int   g_knni[NPTS * 3];
__device__ float g_knnw[NPTS * 3];
__device__ float g_r1p[256 * AGGP];            // zero-padded r1 weights
__device__ float g_agg[NPTS * AGGP];
__device__ float g_h1[NPTS * 256];
__device__ float g_h2[NPTS * 128];

#define FMA_F32X2(d, a, b, c) \
    asm("fma.rn.f32x2 %0, %1, %2, %3;" : "=l"(d) : "l"(a), "l"(b), "l"(c))

// ---------------- mlp1: 3 -> 64, warp per point, writes point-major ----------
__global__ void __launch_bounds__(256) mlp1_kernel(const float* __restrict__ op,
                                                   const float* __restrict__ w1,
                                                   const float* __restrict__ b1) {
    __shared__ float sw[192];
    __shared__ float sb[64];
    int t = threadIdx.x;
    if (t < 192) sw[t] = w1[t];
    if (t < 64)  sb[t] = b1[t];
    __syncthreads();
    int pfl  = blockIdx.x * 8 + (t >> 5);   // flat point 0..MPTS-1
    int lane = t & 31;
    int b  = pfl >> 12;
    int pt = pfl & (NP - 1);
    float x = op[b * 3 * NP + 0 * NP + pt];
    float y = op[b * 3 * NP + 1 * NP + pt];
    float z = op[b * 3 * NP + 2 * NP + pt];
    float* dst = g_fall + (size_t)pfl * FDIM;
#pragma unroll
    for (int u = 0; u < 2; u++) {
        int c = lane + u * 32;
        float v = fmaf(sw[c * 3 + 0], x, fmaf(sw[c * 3 + 1], y, fmaf(sw[c * 3 + 2], z, sb[c])));
        dst[c] = fmaxf(v, 0.0f);
    }
}

// ---------------- global max over f3 (point-major) ---------------------------
__global__ void gmax_zero_kernel() {
    int t = threadIdx.x + blockIdx.x * blockDim.x;
    if (t < BATCH * 256) g_gmax[t] = 0;   // relu outputs >= 0
}

__global__ void __launch_bounds__(256) gmax_kernel() {
    int c  = threadIdx.x;                 // channel 0..255
    int p0 = blockIdx.x * 128;            // flat point chunk (128 within one batch)
    int b  = p0 >> 12;
    float m = 0.0f;
    const float* src = g_fall + (size_t)p0 * FDIM + 192 + c;
#pragma unroll 4
    for (int p = 0; p < 128; p++) m = fmaxf(m, src[(size_t)p * FDIM]);
    atomicMax(&g_gmax[b * 256 + c], __float_as_int(m));
}

__global__ void pad_r1_kernel(const float* __restrict__ r1) {
    int tid = blockIdx.x * blockDim.x + threadIdx.x;   // over 256*AGGP
    if (tid >= 256 * AGGP) return;
    int r = tid / AGGP, k = tid - r * AGGP;
    g_r1p[tid] = (k < 707) ? r1[r * 707 + k] : 0.0f;
}

// ---------------- KNN (top-3), float4 smem (x,y,z,|o|^2), dot-form -----------
__global__ void __launch_bounds__(256) knn_kernel(const float* __restrict__ op,
                                                  const float* __restrict__ qp) {
    extern __shared__ float4 sp[];        // NP * 16B = 64 KB
    int b = blockIdx.y;
    int tid = threadIdx.x;
    for (int i = tid; i < NP; i += 256) {
        float x = op[b * 3 * NP + 0 * NP + i];
        float y = op[b * 3 * NP + 1 * NP + i];
        float z = op[b * 3 * NP + 2 * NP + i];
        sp[i] = make_float4(x, y, z, fmaf(x, x, fmaf(y, y, z * z)));
    }
    __syncthreads();

    int q = blockIdx.x * 256 + tid;
    float qx = qp[b * 3 * NQ + 0 * NQ + q];
    float qy = qp[b * 3 * NQ + 1 * NQ + q];
    float qz = qp[b * 3 * NQ + 2 * NQ + q];
    float nx = -2.0f * qx, ny = -2.0f * qy, nz = -2.0f * qz;

    // d' = |o|^2 - 2 o.q  (monotone with true distance; |q|^2 constant)
    float d0 = CUDART_INF_F, d1 = CUDART_INF_F, d2 = CUDART_INF_F;
    int i0 = 0, i1 = 0, i2 = 0;
#pragma unroll 8
    for (int j = 0; j < NP; j++) {
        float4 o = sp[j];
        float d = fmaf(o.x, nx, fmaf(o.y, ny, fmaf(o.z, nz, o.w)));
        if (d < d2) {
            if (d < d1) {
                d2 = d1; i2 = i1;
                if (d < d0) { d1 = d0; i1 = i0; d0 = d; i0 = j; }
                else        { d1 = d;  i1 = j; }
            } else { d2 = d; i2 = j; }
        }
    }
    int   ii[3] = {i0, i1, i2};
    float rc[3];
    float s = 0.0f;
#pragma unroll
    for (int k = 0; k < 3; k++) {
        float4 o = sp[ii[k]];
        float dx = o.x - qx, dy = o.y - qy, dz = o.z - qz;
        float dist = sqrtf(fmaf(dx, dx, fmaf(dy, dy, dz * dz)));
        rc[k] = 1.0f / (dist + 1e-8f);
        s += rc[k];
    }
    float inv = 1.0f / s;
    int base = (b * NQ + q) * 3;
#pragma unroll
    for (int k = 0; k < 3; k++) {
        g_knni[base + k] = ii[k];
        g_knnw[base + k] = rc[k] * inv;
    }
}

// ---------------- interp + concat into agg (warp per query) ------------------
__global__ void __launch_bounds__(256) agg_kernel(const float* __restrict__ qp) {
    int warp = blockIdx.x * 8 + (threadIdx.x >> 5);   // 0..NPTS-1
    int lane = threadIdx.x & 31;
    int b  = warp >> 14;
    int qi = warp & (NQ - 1);

    int   ik = 0; float wk = 0.0f;
    if (lane < 3) { ik = g_knni[warp * 3 + lane]; wk = g_knnw[warp * 3 + lane]; }
    int   ia = __shfl_sync(0xffffffffu, ik, 0);
    int   ib = __shfl_sync(0xffffffffu, ik, 1);
    int   ic = __shfl_sync(0xffffffffu, ik, 2);
    float wa = __shfl_sync(0xffffffffu, wk, 0);
    float wb = __shfl_sync(0xffffffffu, wk, 1);
    float wc = __shfl_sync(0xffffffffu, wk, 2);

    const float* fa = g_fall + (size_t)(b * NP + ia) * FDIM;
    const float* fb = g_fall + (size_t)(b * NP + ib) * FDIM;
    const float* fc = g_fall + (size_t)(b * NP + ic) * FDIM;
    float* ar = g_agg + (size_t)warp * AGGP;

    if (lane < 3) ar[lane] = qp[b * 3 * NQ + lane * NQ + qi];
#pragma unroll
    for (int c = lane; c < FDIM; c += 32)
        ar[3 + c] = wa * fa[c] + wb * fb[c] + wc * fc[c];
#pragma unroll
    for (int c = lane; c < 256; c += 32)
        ar[451 + c] = __int_as_float(g_gmax[b * 256 + c]);
    if (lane < 13) ar[707 + lane] = 0.0f;   // K padding
}

// ---------------- tiled SGEMM-NT with packed f32x2 FMA -----------------------
// C[m][n] = act(bias[n] + sum_k A[m][k] * W[n][k])
// BM=128, BN=64, BK=16, per-thread 8m x 4n (2 n-pairs), 256 threads.
// A is DUPLICATED in smem (m value in both halves of a 64-bit pair) so a-reads
// are warp-broadcast; w-pairs come naturally from plain Ws (16B aligned reads).
// FUSE: apply final 64->1 layer (r4, rb4) in epilogue, writing out[m] directly.
template <bool RELU, bool FUSE>
__global__ void __launch_bounds__(256) gemm_nt(const float* __restrict__ A, int lda,
                                               const float* __restrict__ W, int ldw,
                                               const float* __restrict__ bias,
                                               float* __restrict__ C, int ldc, int K,
                                               const float* __restrict__ r4,
                                               const float* __restrict__ rb4,
                                               float* __restrict__ out) {
    __shared__ float As2[16][260];   // [k][2m] duplicated; row 1040B (16B mult)
    __shared__ float Ws[16][68];     // [k][n];            row 272B  (16B mult)
    const int t  = threadIdx.x;
    const int m0 = blockIdx.y * 128;
    const int n0 = blockIdx.x * 64;
    const int tx = t & 15;     // n group (4 cols = 2 pairs)
    const int ty = t >> 4;     // m group (8 rows)

    const int arow = t >> 1;               // A row handled by this thread (2 f4)
    const int akc0 = (t & 1) * 8;          // k offsets of the two float4s
    const int akc1 = akc0 + 4;
    const int wrow = t >> 2, wkc = (t & 3) * 4;

    unsigned long long acc[8][2];
#pragma unroll
    for (int i = 0; i < 8; i++) { acc[i][0] = 0ull; acc[i][1] = 0ull; }

    float4 ra0, ra1, rw;
    ra0 = *(const float4*)(A + (size_t)(m0 + arow) * lda + akc0);
    ra1 = *(const float4*)(A + (size_t)(m0 + arow) * lda + akc1);
    rw  = *(const float4*)(W + (size_t)(n0 + wrow) * ldw + wkc);

    for (int k0 = 0; k0 < K; k0 += 16) {
        // stage current tile (A duplicated into adjacent pair)
        *(float2*)&As2[akc0 + 0][2 * arow] = make_float2(ra0.x, ra0.x);
        *(float2*)&As2[akc0 + 1][2 * arow] = make_float2(ra0.y, ra0.y);
        *(float2*)&As2[akc0 + 2][2 * arow] = make_float2(ra0.z, ra0.z);
        *(float2*)&As2[akc0 + 3][2 * arow] = make_float2(ra0.w, ra0.w);
        *(float2*)&As2[akc1 + 0][2 * arow] = make_float2(ra1.x, ra1.x);
        *(float2*)&As2[akc1 + 1][2 * arow] = make_float2(ra1.y, ra1.y);
        *(float2*)&As2[akc1 + 2][2 * arow] = make_float2(ra1.z, ra1.z);
        *(float2*)&As2[akc1 + 3][2 * arow] = make_float2(ra1.w, ra1.w);
        Ws[wkc + 0][wrow] = rw.x; Ws[wkc + 1][wrow] = rw.y;
        Ws[wkc + 2][wrow] = rw.z; Ws[wkc + 3][wrow] = rw.w;
        __syncthreads();

        if (k0 + 16 < K) {   // prefetch next tile into regs
            ra0 = *(const float4*)(A + (size_t)(m0 + arow) * lda + k0 + 16 + akc0);
            ra1 = *(const float4*)(A + (size_t)(m0 + arow) * lda + k0 + 16 + akc1);
            rw  = *(const float4*)(W + (size_t)(n0 + wrow) * ldw + k0 + 16 + wkc);
        }

#pragma unroll
        for (int kk = 0; kk < 16; kk++) {
            const ulonglong2* ap = (const ulonglong2*)&As2[kk][ty * 16];
            ulonglong2 a01 = ap[0], a23 = ap[1], a45 = ap[2], a67 = ap[3];
            ulonglong2 wp  = *(const ulonglong2*)&Ws[kk][tx * 4];
            unsigned long long av[8] = {a01.x, a01.y, a23.x, a23.y,
                                        a45.x, a45.y, a67.x, a67.y};
#pragma unroll
            for (int i = 0; i < 8; i++) {
                FMA_F32X2(acc[i][0], av[i], wp.x, acc[i][0]);
                FMA_F32X2(acc[i][1], av[i], wp.y, acc[i][1]);
            }
        }
        __syncthreads();
    }

    float bb[4];
#pragma unroll
    for (int j = 0; j < 4; j++) bb[j] = bias[n0 + tx * 4 + j];

    if (!FUSE) {
#pragma unroll
        for (int i = 0; i < 8; i++) {
            float2 v0 = *(float2*)&acc[i][0];
            float2 v1 = *(float2*)&acc[i][1];
            float4 r = make_float4(v0.x + bb[0], v0.y + bb[1],
                                   v1.x + bb[2], v1.y + bb[3]);
            if (RELU) {
                r.x = fmaxf(r.x, 0.0f); r.y = fmaxf(r.y, 0.0f);
                r.z = fmaxf(r.z, 0.0f); r.w = fmaxf(r.w, 0.0f);
            }
            *(float4*)(C + (size_t)(m0 + ty * 8 + i) * ldc + n0 + tx * 4) = r;
        }
    } else {
        // fused final layer: out[m] = rb4 + sum_n relu(h[m][n]) * r4[n]
        float4 r4v = *(const float4*)&r4[n0 + tx * 4];
        float rb = rb4[0];
#pragma unroll
        for (int i = 0; i < 8; i++) {
            float2 v0 = *(float2*)&acc[i][0];
            float2 v1 = *(float2*)&acc[i][1];
            float p = fmaxf(v0.x + bb[0], 0.0f) * r4v.x
                    + fmaxf(v0.y + bb[1], 0.0f) * r4v.y
                    + fmaxf(v1.x + bb[2], 0.0f) * r4v.z
                    + fmaxf(v1.y + bb[3], 0.0f) * r4v.w;
            // reduce across the 16 tx lanes (contiguous within the warp)
#pragma unroll
            for (int o = 8; o >= 1; o >>= 1)
                p += __shfl_xor_sync(0xffffffffu, p, o);
            if (tx == 0) out[m0 + ty * 8 + i] = p + rb;
        }
    }
}

// ---------------- launch -----------------------------------------------------
extern "C" void kernel_launch(void* const* d_in, const int* in_sizes, int n_in,
                              void* d_out, int out_size) {
    const float* op  = (const float*)d_in[0];
    const float* qp  = (const float*)d_in[1];
    const float* w1  = (const float*)d_in[2];
    const float* b1  = (const float*)d_in[3];
    const float* w2  = (const float*)d_in[4];
    const float* b2  = (const float*)d_in[5];
    const float* w3  = (const float*)d_in[6];
    const float* b3  = (const float*)d_in[7];
    const float* r1  = (const float*)d_in[8];
    const float* rb1 = (const float*)d_in[9];
    const float* r2  = (const float*)d_in[10];
    const float* rb2 = (const float*)d_in[11];
    const float* r3  = (const float*)d_in[12];
    const float* rb3 = (const float*)d_in[13];
    const float* r4  = (const float*)d_in[14];
    const float* rb4 = (const float*)d_in[15];
    float* out = (float*)d_out;

    float *p_fall, *p_h1, *p_h2, *p_agg, *p_r1p;
    cudaGetSymbolAddress((void**)&p_fall, g_fall);
    cudaGetSymbolAddress((void**)&p_h1,  g_h1);
    cudaGetSymbolAddress((void**)&p_h2,  g_h2);
    cudaGetSymbolAddress((void**)&p_agg, g_agg);
    cudaGetSymbolAddress((void**)&p_r1p, g_r1p);

    cudaFuncSetAttribute(knn_kernel, cudaFuncAttributeMaxDynamicSharedMemorySize,
                         NP * (int)sizeof(float4));

    // feature extractor (point-major throughout)
    gmax_zero_kernel<<<2, 256>>>();
    mlp1_kernel<<<MPTS / 8, 256>>>(op, w1, b1);
    // mlp2: 64 -> 128 as GEMM over 8192 points
    gemm_nt<true, false><<<dim3(128 / 64, MPTS / 128), 256>>>(
        p_fall, FDIM, w2, 64, b2, p_fall + 64, FDIM, 64, nullptr, nullptr, nullptr);
    // mlp3: 128 -> 256 as GEMM
    gemm_nt<true, false><<<dim3(256 / 64, MPTS / 128), 256>>>(
        p_fall + 64, FDIM, w3, 128, b3, p_fall + 192, FDIM, 128, nullptr, nullptr, nullptr);
    gmax_kernel<<<MPTS / 128, 256>>>();

    // knn + interpolation
    knn_kernel<<<dim3(NQ / 256, BATCH), 256, NP * sizeof(float4)>>>(op, qp);
    pad_r1_kernel<<<(256 * AGGP + 255) / 256, 256>>>(r1);
    agg_kernel<<<NPTS / 8, 256>>>(qp);

    // regressor
    gemm_nt<true, false><<<dim3(256 / 64, NPTS / 128), 256>>>(
        p_agg, AGGP, p_r1p, AGGP, rb1, p_h1, 256, AGGP, nullptr, nullptr, nullptr);
    gemm_nt<true, false><<<dim3(128 / 64, NPTS / 128), 256>>>(
        p_h1, 256, r2, 256, rb2, p_h2, 128, 256, nullptr, nullptr, nullptr);
    // layer3 (128 -> 64, relu) with fused final layer (64 -> 1)
    gemm_nt<true, true><<<dim3(64 / 64, NPTS / 128), 256>>>(
        p_h2, 128, r3, 128, rb3, nullptr, 64, 128, r4, rb4, out);
}

// round 5
// speedup vs baseline: 2.7306x; 2.7306x over previous
#include <cuda_runtime.h>
#include <cuda_bf16.h>
#include <math_constants.h>
#include <cstdint>

#define BATCH 2
#define NP    4096
#define NQ    16384
#define FDIM  448            // 64 + 128 + 256
#define AGGP  768            // 707 padded to multiple of 32
#define NPTS  (BATCH * NQ)   // 32768 query points
#define MPTS  (BATCH * NP)   // 8192 original points

// ---------------- scratch (device globals; no allocation allowed) -----------
__device__ float g_fall[MPTS * FDIM];          // point-major fp32 (f1|f2|f3)
__device__ int   g_gmax[BATCH * 256];
__device__ int   g_knni[NPTS * 3];
__device__ float g_knnw[NPTS * 3];
__device__ __nv_bfloat16 g_f1h[MPTS * 64],   g_f1l[MPTS * 64];
__device__ __nv_bfloat16 g_f2h[MPTS * 128],  g_f2l[MPTS * 128];
__device__ __nv_bfloat16 g_aggh[(size_t)NPTS * AGGP], g_aggl[(size_t)NPTS * AGGP];
__device__ __nv_bfloat16 g_h1h[(size_t)NPTS * 256],   g_h1l[(size_t)NPTS * 256];
__device__ __nv_bfloat16 g_h2h[(size_t)NPTS * 128],   g_h2l[(size_t)NPTS * 128];
__device__ __nv_bfloat16 g_w2h[128 * 64],   g_w2l[128 * 64];
__device__ __nv_bfloat16 g_w3h[256 * 128],  g_w3l[256 * 128];
__device__ __nv_bfloat16 g_r1h[256 * AGGP], g_r1l[256 * AGGP];
__device__ __nv_bfloat16 g_r2h[128 * 256],  g_r2l[128 * 256];
__device__ __nv_bfloat16 g_r3h[64 * 128],   g_r3l[64 * 128];

// ---------------- helpers -----------------------------------------------------
__device__ __forceinline__ uint32_t smem_u32(const void* p) {
    uint32_t a;
    asm("{ .reg .u64 t; cvta.to.shared.u64 t, %1; cvt.u32.u64 %0, t; }" : "=r"(a) : "l"(p));
    return a;
}
__device__ __forceinline__ void cp16(uint32_t dst, const void* src) {
    asm volatile("cp.async.cg.shared.global [%0], [%1], 16;" :: "r"(dst), "l"(src));
}
#define CP_COMMIT() asm volatile("cp.async.commit_group;" ::: "memory")

__device__ __forceinline__ void ldm_x4(uint32_t* r, uint32_t addr) {
    asm volatile("ldmatrix.sync.aligned.m8n8.x4.shared.b16 {%0,%1,%2,%3}, [%4];"
                 : "=r"(r[0]), "=r"(r[1]), "=r"(r[2]), "=r"(r[3]) : "r"(addr));
}
__device__ __forceinline__ void mma16816(float* c, const uint32_t* a, const uint32_t* b) {
    asm volatile(
        "mma.sync.aligned.m16n8k16.row.col.f32.bf16.bf16.f32 "
        "{%0,%1,%2,%3}, {%4,%5,%6,%7}, {%8,%9}, {%0,%1,%2,%3};"
        : "+f"(c[0]), "+f"(c[1]), "+f"(c[2]), "+f"(c[3])
        : "r"(a[0]), "r"(a[1]), "r"(a[2]), "r"(a[3]), "r"(b[0]), "r"(b[1]));
}
__device__ __forceinline__ void split_bf16(float v, __nv_bfloat16& h, __nv_bfloat16& l) {
    h = __float2bfloat16(v);
    l = __float2bfloat16(v - __bfloat162float(h));
}

// ---------------- mlp1: 3 -> 64 (fp32 to g_fall + hi/lo planes) --------------
__global__ void __launch_bounds__(256) mlp1_kernel(const float* __restrict__ op,
                                                   const float* __restrict__ w1,
                                                   const float* __restrict__ b1) {
    __shared__ float sw[192];
    __shared__ float sb[64];
    int t = threadIdx.x;
    if (t < 192) sw[t] = w1[t];
    if (t < 64)  sb[t] = b1[t];
    __syncthreads();
    int pfl  = blockIdx.x * 8 + (t >> 5);
    int lane = t & 31;
    int b  = pfl >> 12;
    int pt = pfl & (NP - 1);
    float x = op[b * 3 * NP + 0 * NP + pt];
    float y = op[b * 3 * NP + 1 * NP + pt];
    float z = op[b * 3 * NP + 2 * NP + pt];
    float* dst = g_fall + (size_t)pfl * FDIM;
#pragma unroll
    for (int u = 0; u < 2; u++) {
        int c = lane + u * 32;
        float v = fmaf(sw[c*3+0], x, fmaf(sw[c*3+1], y, fmaf(sw[c*3+2], z, sb[c])));
        v = fmaxf(v, 0.0f);
        dst[c] = v;
        __nv_bfloat16 h, l; split_bf16(v, h, l);
        g_f1h[pfl * 64 + c] = h;
        g_f1l[pfl * 64 + c] = l;
    }
}

// ---------------- global max over f3 -----------------------------------------
__global__ void gmax_zero_kernel() {
    int t = threadIdx.x + blockIdx.x * blockDim.x;
    if (t < BATCH * 256) g_gmax[t] = 0;
}
__global__ void __launch_bounds__(256) gmax_kernel() {
    int c  = threadIdx.x;
    int p0 = blockIdx.x * 128;
    int b  = p0 >> 12;
    float m = 0.0f;
    const float* src = g_fall + (size_t)p0 * FDIM + 192 + c;
#pragma unroll 4
    for (int p = 0; p < 128; p++) m = fmaxf(m, src[(size_t)p * FDIM]);
    atomicMax(&g_gmax[b * 256 + c], __float_as_int(m));
}

// ---------------- weight split (+pad) ----------------------------------------
__global__ void split_w_kernel(const float* __restrict__ src, int rows, int kin, int kpad,
                               __nv_bfloat16* __restrict__ hi, __nv_bfloat16* __restrict__ lo) {
    int i = blockIdx.x * 256 + threadIdx.x;
    if (i >= rows * kpad) return;
    int r = i / kpad, k = i - r * kpad;
    float v = (k < kin) ? src[r * kin + k] : 0.0f;
    __nv_bfloat16 h, l; split_bf16(v, h, l);
    hi[i] = h; lo[i] = l;
}

// ---------------- KNN (top-3) ------------------------------------------------
__global__ void __launch_bounds__(256) knn_kernel(const float* __restrict__ op,
                                                  const float* __restrict__ qp) {
    extern __shared__ float4 sp[];        // NP * 16B = 64 KB
    int b = blockIdx.y;
    int tid = threadIdx.x;
    for (int i = tid; i < NP; i += 256) {
        float x = op[b * 3 * NP + 0 * NP + i];
        float y = op[b * 3 * NP + 1 * NP + i];
        float z = op[b * 3 * NP + 2 * NP + i];
        sp[i] = make_float4(x, y, z, fmaf(x, x, fmaf(y, y, z * z)));
    }
    __syncthreads();

    int q = blockIdx.x * 256 + tid;
    float qx = qp[b * 3 * NQ + 0 * NQ + q];
    float qy = qp[b * 3 * NQ + 1 * NQ + q];
    float qz = qp[b * 3 * NQ + 2 * NQ + q];
    float nx = -2.0f * qx, ny = -2.0f * qy, nz = -2.0f * qz;

    float d0 = CUDART_INF_F, d1 = CUDART_INF_F, d2 = CUDART_INF_F;
    int i0 = 0, i1 = 0, i2 = 0;
#pragma unroll 8
    for (int j = 0; j < NP; j++) {
        float4 o = sp[j];
        float d = fmaf(o.x, nx, fmaf(o.y, ny, fmaf(o.z, nz, o.w)));
        if (d < d2) {
            if (d < d1) {
                d2 = d1; i2 = i1;
                if (d < d0) { d1 = d0; i1 = i0; d0 = d; i0 = j; }
                else        { d1 = d;  i1 = j; }
            } else { d2 = d; i2 = j; }
        }
    }
    int   ii[3] = {i0, i1, i2};
    float rc[3];
    float s = 0.0f;
#pragma unroll
    for (int k = 0; k < 3; k++) {
        float4 o = sp[ii[k]];
        float dx = o.x - qx, dy = o.y - qy, dz = o.z - qz;
        float dist = sqrtf(fmaf(dx, dx, fmaf(dy, dy, dz * dz)));
        rc[k] = 1.0f / (dist + 1e-8f);
        s += rc[k];
    }
    float inv = 1.0f / s;
    int base = (b * NQ + q) * 3;
#pragma unroll
    for (int k = 0; k < 3; k++) {
        g_knni[base + k] = ii[k];
        g_knnw[base + k] = rc[k] * inv;
    }
}

// ---------------- interp + concat -> agg hi/lo planes ------------------------
__global__ void __launch_bounds__(256) agg_kernel(const float* __restrict__ qp) {
    int warp = blockIdx.x * 8 + (threadIdx.x >> 5);   // 0..NPTS-1
    int lane = threadIdx.x & 31;
    int b  = warp >> 14;
    int qi = warp & (NQ - 1);

    int   ik = 0; float wk = 0.0f;
    if (lane < 3) { ik = g_knni[warp * 3 + lane]; wk = g_knnw[warp * 3 + lane]; }
    int   ia = __shfl_sync(0xffffffffu, ik, 0);
    int   ib = __shfl_sync(0xffffffffu, ik, 1);
    int   ic = __shfl_sync(0xffffffffu, ik, 2);
    float wa = __shfl_sync(0xffffffffu, wk, 0);
    float wb = __shfl_sync(0xffffffffu, wk, 1);
    float wc = __shfl_sync(0xffffffffu, wk, 2);

    const float* fa = g_fall + (size_t)(b * NP + ia) * FDIM;
    const float* fb = g_fall + (size_t)(b * NP + ib) * FDIM;
    const float* fc = g_fall + (size_t)(b * NP + ic) * FDIM;
    __nv_bfloat16* ah = g_aggh + (size_t)warp * AGGP;
    __nv_bfloat16* al = g_aggl + (size_t)warp * AGGP;

    __nv_bfloat16 h, l;
    if (lane < 3) {
        float v = qp[b * 3 * NQ + lane * NQ + qi];
        split_bf16(v, h, l); ah[lane] = h; al[lane] = l;
    }
#pragma unroll
    for (int c = lane; c < FDIM; c += 32) {
        float v = wa * fa[c] + wb * fb[c] + wc * fc[c];
        split_bf16(v, h, l); ah[3 + c] = h; al[3 + c] = l;
    }
#pragma unroll
    for (int c = lane; c < 256; c += 32) {
        float v = __int_as_float(g_gmax[b * 256 + c]);
        split_bf16(v, h, l); ah[451 + c] = h; al[451 + c] = l;
    }
    __nv_bfloat16 z = __float2bfloat16(0.0f);
    for (int c = 707 + lane; c < AGGP; c += 32) { ah[c] = z; al[c] = z; }
}

// ---------------- split-bf16 tensor-core GEMM (mma.sync) ---------------------
// C[m][n] = relu(bias[n] + sum_k A[m][k]*W[n][k]),  A,W given as hi/lo planes.
// BM=128 (grid.y), BN=64 (grid.x), BK=32, 256 thr = 8 warps (4m x 2n),
// warp tile 32x32 (2 m16-tiles x 4 n8-tiles). 3 mma per tile: hh + hl + lh.
// FUSE: apply final 64->1 layer in epilogue (requires gridDim.x == 1).
#define PKB 80                       // smem row pitch bytes (32 bf16 + 16B pad)
#define APL (128 * PKB)              // A plane bytes   (10240)
#define WPL (64 * PKB)               // W plane bytes   (5120)
#define GBUF (2 * APL + 2 * WPL)     // one stage       (30720)

template <bool FUSE>
__global__ void __launch_bounds__(256) tgemm(
    const __nv_bfloat16* __restrict__ Ahi, const __nv_bfloat16* __restrict__ Alo, int lda,
    const __nv_bfloat16* __restrict__ Whi, const __nv_bfloat16* __restrict__ Wlo, int ldw,
    const float* __restrict__ bias, int K,
    float* __restrict__ f32out, int f32ld,
    __nv_bfloat16* __restrict__ phi, __nv_bfloat16* __restrict__ plo, int pld,
    const float* __restrict__ r4, const float* __restrict__ rb4,
    float* __restrict__ finout) {
    extern __shared__ char smem[];
    const int t = threadIdx.x;
    const int lane = t & 31, warp = t >> 5;
    const int wm = warp >> 1, wn = warp & 1;
    const int m0 = blockIdx.y * 128;
    const int n0 = blockIdx.x * 64;

    float acc[2][4][4];
#pragma unroll
    for (int i = 0; i < 2; i++)
#pragma unroll
        for (int j = 0; j < 4; j++)
#pragma unroll
            for (int v = 0; v < 4; v++) acc[i][j][v] = 0.0f;

    const int NC = K / 32;

    auto stage = [&](int buf, int c) {
        char* base = smem + buf * GBUF;
#pragma unroll
        for (int u = 0; u < 4; u++) {                 // A: 1024 cp16
            int e = t + u * 256;
            int pl = e >> 9, rem = e & 511;
            int row = rem >> 2, seg = rem & 3;
            const char* src = (const char*)(pl ? Alo : Ahi)
                + ((size_t)(m0 + row) * lda + c * 32) * 2 + seg * 16;
            cp16(smem_u32(base + pl * APL + row * PKB + seg * 16), src);
        }
#pragma unroll
        for (int u = 0; u < 2; u++) {                 // W: 512 cp16
            int e = t + u * 256;
            int pl = e >> 8, rem = e & 255;
            int row = rem >> 2, seg = rem & 3;
            const char* src = (const char*)(pl ? Wlo : Whi)
                + ((size_t)(n0 + row) * ldw + c * 32) * 2 + seg * 16;
            cp16(smem_u32(base + 2 * APL + pl * WPL + row * PKB + seg * 16), src);
        }
        CP_COMMIT();
    };

    stage(0, 0);
    for (int c = 0; c < NC; c++) {
        if (c + 1 < NC) {
            stage((c + 1) & 1, c + 1);
            asm volatile("cp.async.wait_group 1;" ::: "memory");
        } else {
            asm volatile("cp.async.wait_group 0;" ::: "memory");
        }
        __syncthreads();
        char* base = smem + (c & 1) * GBUF;
#pragma unroll
        for (int kk = 0; kk < 2; kk++) {              // two k16 substeps
            uint32_t afr[2][2][4];
#pragma unroll
            for (int pl = 0; pl < 2; pl++)
#pragma unroll
                for (int mt = 0; mt < 2; mt++) {
                    uint32_t a = smem_u32(base + pl * APL
                        + (wm * 32 + mt * 16 + (lane & 15)) * PKB
                        + (kk * 16 + (lane >> 4) * 8) * 2);
                    ldm_x4(afr[pl][mt], a);
                }
#pragma unroll
            for (int nt = 0; nt < 4; nt++) {
                const char* bp = base + 2 * APL
                    + (wn * 32 + nt * 8 + (lane >> 2)) * PKB
                    + (kk * 16 + (lane & 3) * 2) * 2;
                uint32_t bh[2], bl[2];
                bh[0] = *(const uint32_t*)bp;
                bh[1] = *(const uint32_t*)(bp + 16);
                bl[0] = *(const uint32_t*)(bp + WPL);
                bl[1] = *(const uint32_t*)(bp + WPL + 16);
#pragma unroll
                for (int mt = 0; mt < 2; mt++) {
                    mma16816(acc[mt][nt], afr[0][mt], bh);
                    mma16816(acc[mt][nt], afr[0][mt], bl);
                    mma16816(acc[mt][nt], afr[1][mt], bh);
                }
            }
        }
        __syncthreads();
    }

    // ---------------- epilogue ----------------
    if (FUSE) {
        float part[2][2] = {{0.0f, 0.0f}, {0.0f, 0.0f}};   // [mt][row-half]
#pragma unroll
        for (int mt = 0; mt < 2; mt++)
#pragma unroll
            for (int nt = 0; nt < 4; nt++) {
                int col = n0 + wn * 32 + nt * 8 + (lane & 3) * 2;
                float b0 = bias[col], b1 = bias[col + 1];
                float r0 = r4[col], r1 = r4[col + 1];
                part[mt][0] += fmaxf(acc[mt][nt][0] + b0, 0.0f) * r0
                             + fmaxf(acc[mt][nt][1] + b1, 0.0f) * r1;
                part[mt][1] += fmaxf(acc[mt][nt][2] + b0, 0.0f) * r0
                             + fmaxf(acc[mt][nt][3] + b1, 0.0f) * r1;
            }
        float* sp = (float*)smem;   // [128][2]
#pragma unroll
        for (int mt = 0; mt < 2; mt++)
#pragma unroll
            for (int h = 0; h < 2; h++) {
                float v = part[mt][h];
                v += __shfl_xor_sync(0xffffffffu, v, 1);
                v += __shfl_xor_sync(0xffffffffu, v, 2);
                if ((lane & 3) == 0)
                    sp[(wm * 32 + mt * 16 + h * 8 + (lane >> 2)) * 2 + wn] = v;
            }
        __syncthreads();
        if (t < 128) finout[m0 + t] = sp[t * 2] + sp[t * 2 + 1] + rb4[0];
    } else {
#pragma unroll
        for (int mt = 0; mt < 2; mt++)
#pragma unroll
            for (int nt = 0; nt < 4; nt++) {
                int row0 = m0 + wm * 32 + mt * 16 + (lane >> 2);
                int col = n0 + wn * 32 + nt * 8 + (lane & 3) * 2;
                float b0 = bias[col], b1 = bias[col + 1];
                float v0 = fmaxf(acc[mt][nt][0] + b0, 0.0f);
                float v1 = fmaxf(acc[mt][nt][1] + b1, 0.0f);
                float v2 = fmaxf(acc[mt][nt][2] + b0, 0.0f);
                float v3 = fmaxf(acc[mt][nt][3] + b1, 0.0f);
                if (f32out) {
                    *(float2*)(f32out + (size_t)row0 * f32ld + col) = make_float2(v0, v1);
                    *(float2*)(f32out + (size_t)(row0 + 8) * f32ld + col) = make_float2(v2, v3);
                }
                if (phi) {
                    __nv_bfloat16 h0, l0, h1, l1;
                    split_bf16(v0, h0, l0); split_bf16(v1, h1, l1);
                    uint32_t hw = (uint32_t)*(unsigned short*)&h0
                                | ((uint32_t)*(unsigned short*)&h1 << 16);
                    uint32_t lw = (uint32_t)*(unsigned short*)&l0
                                | ((uint32_t)*(unsigned short*)&l1 << 16);
                    *(uint32_t*)((unsigned short*)phi + (size_t)row0 * pld + col) = hw;
                    *(uint32_t*)((unsigned short*)plo + (size_t)row0 * pld + col) = lw;
                    split_bf16(v2, h0, l0); split_bf16(v3, h1, l1);
                    hw = (uint32_t)*(unsigned short*)&h0
                       | ((uint32_t)*(unsigned short*)&h1 << 16);
                    lw = (uint32_t)*(unsigned short*)&l0
                       | ((uint32_t)*(unsigned short*)&l1 << 16);
                    *(uint32_t*)((unsigned short*)phi + (size_t)(row0 + 8) * pld + col) = hw;
                    *(uint32_t*)((unsigned short*)plo + (size_t)(row0 + 8) * pld + col) = lw;
                }
            }
    }
}

// ---------------- launch -----------------------------------------------------
extern "C" void kernel_launch(void* const* d_in, const int* in_sizes, int n_in,
                              void* d_out, int out_size) {
    const float* op  = (const float*)d_in[0];
    const float* qp  = (const float*)d_in[1];
    const float* w1  = (const float*)d_in[2];
    const float* b1  = (const float*)d_in[3];
    const float* w2  = (const float*)d_in[4];
    const float* b2  = (const float*)d_in[5];
    const float* w3  = (const float*)d_in[6];
    const float* b3  = (const float*)d_in[7];
    const float* r1  = (const float*)d_in[8];
    const float* rb1 = (const float*)d_in[9];
    const float* r2  = (const float*)d_in[10];
    const float* rb2 = (const float*)d_in[11];
    const float* r3  = (const float*)d_in[12];
    const float* rb3 = (const float*)d_in[13];
    const float* r4  = (const float*)d_in[14];
    const float* rb4 = (const float*)d_in[15];
    float* out = (float*)d_out;

    float* p_fall;
    cudaGetSymbolAddress((void**)&p_fall, g_fall);
    __nv_bfloat16 *f1h, *f1l, *f2h, *f2l, *agh, *agl, *h1h, *h1l, *h2h, *h2l;
    __nv_bfloat16 *w2h, *w2l, *w3h, *w3l, *r1h, *r1l, *r2h, *r2l, *r3h, *r3l;
    cudaGetSymbolAddress((void**)&f1h, g_f1h);  cudaGetSymbolAddress((void**)&f1l, g_f1l);
    cudaGetSymbolAddress((void**)&f2h, g_f2h);  cudaGetSymbolAddress((void**)&f2l, g_f2l);
    cudaGetSymbolAddress((void**)&agh, g_aggh); cudaGetSymbolAddress((void**)&agl, g_aggl);
    cudaGetSymbolAddress((void**)&h1h, g_h1h);  cudaGetSymbolAddress((void**)&h1l, g_h1l);
    cudaGetSymbolAddress((void**)&h2h, g_h2h);  cudaGetSymbolAddress((void**)&h2l, g_h2l);
    cudaGetSymbolAddress((void**)&w2h, g_w2h);  cudaGetSymbolAddress((void**)&w2l, g_w2l);
    cudaGetSymbolAddress((void**)&w3h, g_w3h);  cudaGetSymbolAddress((void**)&w3l, g_w3l);
    cudaGetSymbolAddress((void**)&r1h, g_r1h);  cudaGetSymbolAddress((void**)&r1l, g_r1l);
    cudaGetSymbolAddress((void**)&r2h, g_r2h);  cudaGetSymbolAddress((void**)&r2l, g_r2l);
    cudaGetSymbolAddress((void**)&r3h, g_r3h);  cudaGetSymbolAddress((void**)&r3l, g_r3l);

    cudaFuncSetAttribute(knn_kernel, cudaFuncAttributeMaxDynamicSharedMemorySize,
                         NP * (int)sizeof(float4));
    cudaFuncSetAttribute(tgemm<false>, cudaFuncAttributeMaxDynamicSharedMemorySize, 2 * GBUF);
    cudaFuncSetAttribute(tgemm<true>,  cudaFuncAttributeMaxDynamicSharedMemorySize, 2 * GBUF);

    // weight splits (pad K where needed)
    split_w_kernel<<<(128 * 64 + 255) / 256, 256>>>(w2, 128, 64, 64, w2h, w2l);
    split_w_kernel<<<(256 * 128 + 255) / 256, 256>>>(w3, 256, 128, 128, w3h, w3l);
    split_w_kernel<<<(256 * AGGP + 255) / 256, 256>>>(r1, 256, 707, AGGP, r1h, r1l);
    split_w_kernel<<<(128 * 256 + 255) / 256, 256>>>(r2, 128, 256, 256, r2h, r2l);
    split_w_kernel<<<(64 * 128 + 255) / 256, 256>>>(r3, 64, 128, 128, r3h, r3l);

    // feature extractor
    gmax_zero_kernel<<<2, 256>>>();
    mlp1_kernel<<<MPTS / 8, 256>>>(op, w1, b1);
    // mlp2: 64 -> 128 (fp32 into g_fall col 64 + f2 planes)
    tgemm<false><<<dim3(2, MPTS / 128), 256, 2 * GBUF>>>(
        f1h, f1l, 64, w2h, w2l, 64, b2, 64,
        p_fall + 64, FDIM, f2h, f2l, 128, nullptr, nullptr, nullptr);
    // mlp3: 128 -> 256 (fp32 into g_fall col 192)
    tgemm<false><<<dim3(4, MPTS / 128), 256, 2 * GBUF>>>(
        f2h, f2l, 128, w3h, w3l, 128, b3, 128,
        p_fall + 192, FDIM, nullptr, nullptr, 0, nullptr, nullptr, nullptr);
    gmax_kernel<<<MPTS / 128, 256>>>();

    // knn + aggregation
    knn_kernel<<<dim3(NQ / 256, BATCH), 256, NP * sizeof(float4)>>>(op, qp);
    agg_kernel<<<NPTS / 8, 256>>>(qp);

    // regressor
    tgemm<false><<<dim3(4, NPTS / 128), 256, 2 * GBUF>>>(
        agh, agl, AGGP, r1h, r1l, AGGP, rb1, AGGP,
        nullptr, 0, h1h, h1l, 256, nullptr, nullptr, nullptr);
    tgemm<false><<<dim3(2, NPTS / 128), 256, 2 * GBUF>>>(
        h1h, h1l, 256, r2h, r2l, 256, rb2, 256,
        nullptr, 0, h2h, h2l, 128, nullptr, nullptr, nullptr);
    // layer3 (128 -> 64, relu) + fused final 64 -> 1
    tgemm<true><<<dim3(1, NPTS / 128), 256, 2 * GBUF>>>(
        h2h, h2l, 128, r3h, r3l, 128, rb3, 128,
        nullptr, 0, nullptr, nullptr, 0, r4, rb4, out);
}

// round 6
// speedup vs baseline: 2.7903x; 1.0219x over previous
#include <cuda_runtime.h>
#include <cuda_bf16.h>
#include <math_constants.h>
#include <cstdint>

#define BATCH 2
#define NP    4096
#define NQ    16384
#define FDIM  448            // 64 + 128 + 256
#define AGGP  768            // 707 padded to multiple of 32
#define NPTS  (BATCH * NQ)   // 32768 query points
#define MPTS  (BATCH * NP)   // 8192 original points

// ---------------- scratch (device globals; no allocation allowed) -----------
__device__ float g_fall[MPTS * FDIM];          // point-major fp32 (f1|f2|f3)
__device__ int   g_gmax[BATCH * 256];
__device__ int   g_knni[NPTS * 3];
__device__ float g_knnw[NPTS * 3];
__device__ __nv_bfloat16 g_f1h[MPTS * 64],   g_f1l[MPTS * 64];
__device__ __nv_bfloat16 g_f2h[MPTS * 128],  g_f2l[MPTS * 128];
__device__ __nv_bfloat16 g_aggh[(size_t)NPTS * AGGP], g_aggl[(size_t)NPTS * AGGP];
__device__ __nv_bfloat16 g_h1h[(size_t)NPTS * 256],   g_h1l[(size_t)NPTS * 256];
__device__ __nv_bfloat16 g_h2h[(size_t)NPTS * 128],   g_h2l[(size_t)NPTS * 128];
__device__ __nv_bfloat16 g_w2h[128 * 64],   g_w2l[128 * 64];
__device__ __nv_bfloat16 g_w3h[256 * 128],  g_w3l[256 * 128];
__device__ __nv_bfloat16 g_r1h[256 * AGGP], g_r1l[256 * AGGP];   // rotated cols
__device__ __nv_bfloat16 g_r2h[128 * 256],  g_r2l[128 * 256];
__device__ __nv_bfloat16 g_r3h[64 * 128],   g_r3l[64 * 128];

// ---------------- helpers -----------------------------------------------------
__device__ __forceinline__ uint32_t smem_u32(const void* p) {
    uint32_t a;
    asm("{ .reg .u64 t; cvta.to.shared.u64 t, %1; cvt.u32.u64 %0, t; }" : "=r"(a) : "l"(p));
    return a;
}
__device__ __forceinline__ void cp16(uint32_t dst, const void* src) {
    asm volatile("cp.async.cg.shared.global [%0], [%1], 16;" :: "r"(dst), "l"(src));
}
#define CP_COMMIT() asm volatile("cp.async.commit_group;" ::: "memory")

__device__ __forceinline__ void ldm_x4(uint32_t* r, uint32_t addr) {
    asm volatile("ldmatrix.sync.aligned.m8n8.x4.shared.b16 {%0,%1,%2,%3}, [%4];"
                 : "=r"(r[0]), "=r"(r[1]), "=r"(r[2]), "=r"(r[3]) : "r"(addr));
}
__device__ __forceinline__ void mma16816(float* c, const uint32_t* a, const uint32_t* b) {
    asm volatile(
        "mma.sync.aligned.m16n8k16.row.col.f32.bf16.bf16.f32 "
        "{%0,%1,%2,%3}, {%4,%5,%6,%7}, {%8,%9}, {%0,%1,%2,%3};"
        : "+f"(c[0]), "+f"(c[1]), "+f"(c[2]), "+f"(c[3])
        : "r"(a[0]), "r"(a[1]), "r"(a[2]), "r"(a[3]), "r"(b[0]), "r"(b[1]));
}
__device__ __forceinline__ void split_bf16(float v, __nv_bfloat16& h, __nv_bfloat16& l) {
    h = __float2bfloat16(v);
    l = __float2bfloat16(v - __bfloat162float(h));
}
__device__ __forceinline__ uint32_t pck(__nv_bfloat16 a, __nv_bfloat16 b) {
    return (uint32_t)*(unsigned short*)&a | ((uint32_t)*(unsigned short*)&b << 16);
}

// ---------------- mlp1: 3 -> 64 (fp32 to g_fall + hi/lo planes) --------------
__global__ void __launch_bounds__(256) mlp1_kernel(const float* __restrict__ op,
                                                   const float* __restrict__ w1,
                                                   const float* __restrict__ b1) {
    __shared__ float sw[192];
    __shared__ float sb[64];
    int t = threadIdx.x;
    if (t < 192) sw[t] = w1[t];
    if (t < 64)  sb[t] = b1[t];
    __syncthreads();
    int pfl  = blockIdx.x * 8 + (t >> 5);
    int lane = t & 31;
    int b  = pfl >> 12;
    int pt = pfl & (NP - 1);
    float x = op[b * 3 * NP + 0 * NP + pt];
    float y = op[b * 3 * NP + 1 * NP + pt];
    float z = op[b * 3 * NP + 2 * NP + pt];
    float* dst = g_fall + (size_t)pfl * FDIM;
#pragma unroll
    for (int u = 0; u < 2; u++) {
        int c = lane + u * 32;
        float v = fmaf(sw[c*3+0], x, fmaf(sw[c*3+1], y, fmaf(sw[c*3+2], z, sb[c])));
        v = fmaxf(v, 0.0f);
        dst[c] = v;
        __nv_bfloat16 h, l; split_bf16(v, h, l);
        g_f1h[pfl * 64 + c] = h;
        g_f1l[pfl * 64 + c] = l;
    }
}

// ---------------- global max over f3 -----------------------------------------
__global__ void gmax_zero_kernel() {
    int t = threadIdx.x + blockIdx.x * blockDim.x;
    if (t < BATCH * 256) g_gmax[t] = 0;
}
__global__ void __launch_bounds__(256) gmax_kernel() {
    int c  = threadIdx.x;
    int p0 = blockIdx.x * 128;
    int b  = p0 >> 12;
    float m = 0.0f;
    const float* src = g_fall + (size_t)p0 * FDIM + 192 + c;
#pragma unroll 4
    for (int p = 0; p < 128; p++) m = fmaxf(m, src[(size_t)p * FDIM]);
    atomicMax(&g_gmax[b * 256 + c], __float_as_int(m));
}

// ---------------- single fused weight split (+pad, r1 rotated) ---------------
// segments: w2 8192 | w3 32768 | r1 196608 | r2 32768 | r3 8192 = 278528 elems
__global__ void __launch_bounds__(256) split_all_kernel(
    const float* __restrict__ w2, const float* __restrict__ w3,
    const float* __restrict__ r1, const float* __restrict__ r2,
    const float* __restrict__ r3) {
    int i = blockIdx.x * 256 + threadIdx.x;
    if (i >= 278528) return;
    const float* src; __nv_bfloat16 *hi, *lo;
    int off, kpad, kin; bool rot = false;
    if (i < 8192)        { src = w2; hi = g_w2h; lo = g_w2l; off = i;          kpad = 64;  kin = 64;  }
    else if (i < 40960)  { src = w3; hi = g_w3h; lo = g_w3l; off = i - 8192;   kpad = 128; kin = 128; }
    else if (i < 237568) { src = r1; hi = g_r1h; lo = g_r1l; off = i - 40960;  kpad = AGGP; kin = 707; rot = true; }
    else if (i < 270336) { src = r2; hi = g_r2h; lo = g_r2l; off = i - 237568; kpad = 256; kin = 256; }
    else                 { src = r3; hi = g_r3h; lo = g_r3l; off = i - 270336; kpad = 128; kin = 128; }
    int r = off / kpad, k = off - r * kpad;
    float v = 0.0f;
    if (k < kin) {
        int ks = rot ? ((k + 3 >= 707) ? k + 3 - 707 : k + 3) : k;
        v = src[r * kin + ks];
    }
    __nv_bfloat16 h, l; split_bf16(v, h, l);
    hi[off] = h; lo[off] = l;
}

// ---------------- KNN (top-3) ------------------------------------------------
__global__ void __launch_bounds__(256) knn_kernel(const float* __restrict__ op,
                                                  const float* __restrict__ qp) {
    extern __shared__ float4 sp[];        // NP * 16B = 64 KB
    int b = blockIdx.y;
    int tid = threadIdx.x;
    for (int i = tid; i < NP; i += 256) {
        float x = op[b * 3 * NP + 0 * NP + i];
        float y = op[b * 3 * NP + 1 * NP + i];
        float z = op[b * 3 * NP + 2 * NP + i];
        sp[i] = make_float4(x, y, z, fmaf(x, x, fmaf(y, y, z * z)));
    }
    __syncthreads();

    int q = blockIdx.x * 256 + tid;
    float qx = qp[b * 3 * NQ + 0 * NQ + q];
    float qy = qp[b * 3 * NQ + 1 * NQ + q];
    float qz = qp[b * 3 * NQ + 2 * NQ + q];
    float nx = -2.0f * qx, ny = -2.0f * qy, nz = -2.0f * qz;

    float d0 = CUDART_INF_F, d1 = CUDART_INF_F, d2 = CUDART_INF_F;
    int i0 = 0, i1 = 0, i2 = 0;
#pragma unroll 8
    for (int j = 0; j < NP; j++) {
        float4 o = sp[j];
        float d = fmaf(o.x, nx, fmaf(o.y, ny, fmaf(o.z, nz, o.w)));
        if (d < d2) {
            if (d < d1) {
                d2 = d1; i2 = i1;
                if (d < d0) { d1 = d0; i1 = i0; d0 = d; i0 = j; }
                else        { d1 = d;  i1 = j; }
            } else { d2 = d; i2 = j; }
        }
    }
    int   ii[3] = {i0, i1, i2};
    float rc[3];
    float s = 0.0f;
#pragma unroll
    for (int k = 0; k < 3; k++) {
        float4 o = sp[ii[k]];
        float dx = o.x - qx, dy = o.y - qy, dz = o.z - qz;
        float dist = sqrtf(fmaf(dx, dx, fmaf(dy, dy, dz * dz)));
        rc[k] = 1.0f / (dist + 1e-8f);
        s += rc[k];
    }
    float inv = 1.0f / s;
    int base = (b * NQ + q) * 3;
#pragma unroll
    for (int k = 0; k < 3; k++) {
        g_knni[base + k] = ii[k];
        g_knnw[base + k] = rc[k] * inv;
    }
}

// ---------------- interp + concat -> agg hi/lo planes (rotated layout) -------
// agg cols: [0:448) interp | [448:704) global | [704:707) query | [707:768) 0
__global__ void __launch_bounds__(256) agg_kernel(const float* __restrict__ qp) {
    int warp = blockIdx.x * 8 + (threadIdx.x >> 5);   // 0..NPTS-1
    int lane = threadIdx.x & 31;
    int b  = warp >> 14;
    int qi = warp & (NQ - 1);

    int   ik = 0; float wk = 0.0f;
    if (lane < 3) { ik = g_knni[warp * 3 + lane]; wk = g_knnw[warp * 3 + lane]; }
    int   ia = __shfl_sync(0xffffffffu, ik, 0);
    int   ib = __shfl_sync(0xffffffffu, ik, 1);
    int   ic = __shfl_sync(0xffffffffu, ik, 2);
    float wa = __shfl_sync(0xffffffffu, wk, 0);
    float wb = __shfl_sync(0xffffffffu, wk, 1);
    float wc = __shfl_sync(0xffffffffu, wk, 2);

    const float4* fa4 = (const float4*)(g_fall + (size_t)(b * NP + ia) * FDIM);
    const float4* fb4 = (const float4*)(g_fall + (size_t)(b * NP + ib) * FDIM);
    const float4* fc4 = (const float4*)(g_fall + (size_t)(b * NP + ic) * FDIM);
    __nv_bfloat16* ah = g_aggh + (size_t)warp * AGGP;
    __nv_bfloat16* al = g_aggl + (size_t)warp * AGGP;

    __nv_bfloat16 h0, l0, h1, l1, h2, l2, h3, l3;
    // interp: 112 float4 = 448 channels
    for (int c4 = lane; c4 < 112; c4 += 32) {
        float4 A = fa4[c4], B = fb4[c4], C = fc4[c4];
        float v0 = wa * A.x + wb * B.x + wc * C.x;
        float v1 = wa * A.y + wb * B.y + wc * C.y;
        float v2 = wa * A.z + wb * B.z + wc * C.z;
        float v3 = wa * A.w + wb * B.w + wc * C.w;
        split_bf16(v0, h0, l0); split_bf16(v1, h1, l1);
        split_bf16(v2, h2, l2); split_bf16(v3, h3, l3);
        ((uint2*)ah)[c4] = make_uint2(pck(h0, h1), pck(h2, h3));
        ((uint2*)al)[c4] = make_uint2(pck(l0, l1), pck(l2, l3));
    }
    // global feats: 64 groups of 4
    for (int c4 = lane; c4 < 64; c4 += 32) {
        float v0 = __int_as_float(g_gmax[b * 256 + c4 * 4 + 0]);
        float v1 = __int_as_float(g_gmax[b * 256 + c4 * 4 + 1]);
        float v2 = __int_as_float(g_gmax[b * 256 + c4 * 4 + 2]);
        float v3 = __int_as_float(g_gmax[b * 256 + c4 * 4 + 3]);
        split_bf16(v0, h0, l0); split_bf16(v1, h1, l1);
        split_bf16(v2, h2, l2); split_bf16(v3, h3, l3);
        ((uint2*)(ah + 448))[c4] = make_uint2(pck(h0, h1), pck(h2, h3));
        ((uint2*)(al + 448))[c4] = make_uint2(pck(l0, l1), pck(l2, l3));
    }
    if (lane < 3) {
        float v = qp[b * 3 * NQ + lane * NQ + qi];
        split_bf16(v, h0, l0); ah[704 + lane] = h0; al[704 + lane] = l0;
    }
    __nv_bfloat16 z = __float2bfloat16(0.0f);
    for (int c = 707 + lane; c < AGGP; c += 32) { ah[c] = z; al[c] = z; }
}

// ---------------- wide split-bf16 tensor GEMM: full N per CTA ----------------
// BM=128 (grid.x), BN=N (128 or 256), BK=32, 512 thr = 16 warps (4m x 4n).
#define PKB 80                       // smem row pitch bytes (32 bf16 + 16B pad)
#define APL (128 * PKB)              // A plane bytes (10240)

template <int BN>
__global__ void __launch_bounds__(512) tgemm_wide(
    const __nv_bfloat16* __restrict__ Ahi, const __nv_bfloat16* __restrict__ Alo, int lda,
    const __nv_bfloat16* __restrict__ Whi, const __nv_bfloat16* __restrict__ Wlo,
    const float* __restrict__ bias, int K,
    float* __restrict__ f32out, int f32ld,
    __nv_bfloat16* __restrict__ phi, __nv_bfloat16* __restrict__ plo, int pld) {
    extern __shared__ char smem[];
    constexpr int WPL = BN * PKB;                 // W plane bytes
    constexpr int SS  = 2 * APL + 2 * WPL;        // one stage
    constexpr int NT8 = BN / 32;                  // n8 tiles per warp
    const int t = threadIdx.x;
    const int lane = t & 31, warp = t >> 5;
    const int wm = warp >> 2, wn = warp & 3;
    const int m0 = blockIdx.x * 128;
    const int ldw = K;                            // weights stored K-contig

    float acc[2][NT8][4];
#pragma unroll
    for (int i = 0; i < 2; i++)
#pragma unroll
        for (int j = 0; j < NT8; j++)
#pragma unroll
            for (int v = 0; v < 4; v++) acc[i][j][v] = 0.0f;

    const int NC = K / 32;

    auto stage = [&](int buf, int c) {
        char* base = smem + buf * SS;
#pragma unroll
        for (int u = 0; u < 2; u++) {                 // A: 1024 cp16
            int e = t + u * 512;
            int pl = e >> 9, rem = e & 511;
            int row = rem >> 2, seg = rem & 3;
            const char* src = (const char*)(pl ? Alo : Ahi)
                + ((size_t)(m0 + row) * lda + c * 32) * 2 + seg * 16;
            cp16(smem_u32(base + pl * APL + row * PKB + seg * 16), src);
        }
#pragma unroll
        for (int u = 0; u < BN / 64; u++) {           // W: BN*8 cp16
            int e = t + u * 512;
            int pl = e / (BN * 4), rem = e % (BN * 4);
            int row = rem >> 2, seg = rem & 3;
            const char* src = (const char*)(pl ? Wlo : Whi)
                + ((size_t)row * ldw + c * 32) * 2 + seg * 16;
            cp16(smem_u32(base + 2 * APL + pl * WPL + row * PKB + seg * 16), src);
        }
        CP_COMMIT();
    };

    stage(0, 0);
    for (int c = 0; c < NC; c++) {
        if (c + 1 < NC) {
            stage((c + 1) & 1, c + 1);
            asm volatile("cp.async.wait_group 1;" ::: "memory");
        } else {
            asm volatile("cp.async.wait_group 0;" ::: "memory");
        }
        __syncthreads();
        char* base = smem + (c & 1) * SS;
#pragma unroll
        for (int kk = 0; kk < 2; kk++) {
            uint32_t afr[2][2][4];
#pragma unroll
            for (int pl = 0; pl < 2; pl++)
#pragma unroll
                for (int mt = 0; mt < 2; mt++) {
                    uint32_t a = smem_u32(base + pl * APL
                        + (wm * 32 + mt * 16 + (lane & 15)) * PKB
                        + (kk * 16 + (lane >> 4) * 8) * 2);
                    ldm_x4(afr[pl][mt], a);
                }
#pragma unroll
            for (int nt = 0; nt < NT8; nt++) {
                const char* bp = base + 2 * APL
                    + (wn * (BN / 4) + nt * 8 + (lane >> 2)) * PKB
                    + (kk * 16 + (lane & 3) * 2) * 2;
                uint32_t bh[2], bl[2];
                bh[0] = *(const uint32_t*)bp;
                bh[1] = *(const uint32_t*)(bp + 16);
                bl[0] = *(const uint32_t*)(bp + WPL);
                bl[1] = *(const uint32_t*)(bp + WPL + 16);
#pragma unroll
                for (int mt = 0; mt < 2; mt++) {
                    mma16816(acc[mt][nt], afr[0][mt], bh);
                    mma16816(acc[mt][nt], afr[0][mt], bl);
                    mma16816(acc[mt][nt], afr[1][mt], bh);
                }
            }
        }
        __syncthreads();
    }

    // epilogue: bias + relu, write fp32 and/or hi/lo planes
#pragma unroll
    for (int mt = 0; mt < 2; mt++)
#pragma unroll
        for (int nt = 0; nt < NT8; nt++) {
            int row0 = m0 + wm * 32 + mt * 16 + (lane >> 2);
            int col = wn * (BN / 4) + nt * 8 + (lane & 3) * 2;
            float b0 = bias[col], b1 = bias[col + 1];
            float v0 = fmaxf(acc[mt][nt][0] + b0, 0.0f);
            float v1 = fmaxf(acc[mt][nt][1] + b1, 0.0f);
            float v2 = fmaxf(acc[mt][nt][2] + b0, 0.0f);
            float v3 = fmaxf(acc[mt][nt][3] + b1, 0.0f);
            if (f32out) {
                *(float2*)(f32out + (size_t)row0 * f32ld + col) = make_float2(v0, v1);
                *(float2*)(f32out + (size_t)(row0 + 8) * f32ld + col) = make_float2(v2, v3);
            }
            if (phi) {
                __nv_bfloat16 h0, l0, h1, l1;
                split_bf16(v0, h0, l0); split_bf16(v1, h1, l1);
                *(uint32_t*)((unsigned short*)phi + (size_t)row0 * pld + col) = pck(h0, h1);
                *(uint32_t*)((unsigned short*)plo + (size_t)row0 * pld + col) = pck(l0, l1);
                split_bf16(v2, h0, l0); split_bf16(v3, h1, l1);
                *(uint32_t*)((unsigned short*)phi + (size_t)(row0 + 8) * pld + col) = pck(h0, h1);
                *(uint32_t*)((unsigned short*)plo + (size_t)(row0 + 8) * pld + col) = pck(l0, l1);
            }
        }
}

// ---------------- narrow GEMM with fused final 64->1 (unchanged, validated) --
#define WPLN (64 * PKB)
#define GBUF (2 * APL + 2 * WPLN)

__global__ void __launch_bounds__(256) tgemm_fin(
    const __nv_bfloat16* __restrict__ Ahi, const __nv_bfloat16* __restrict__ Alo, int lda,
    const __nv_bfloat16* __restrict__ Whi, const __nv_bfloat16* __restrict__ Wlo, int ldw,
    const float* __restrict__ bias, int K,
    const float* __restrict__ r4, const float* __restrict__ rb4,
    float* __restrict__ finout) {
    extern __shared__ char smem[];
    const int t = threadIdx.x;
    const int lane = t & 31, warp = t >> 5;
    const int wm = warp >> 1, wn = warp & 1;
    const int m0 = blockIdx.y * 128;

    float acc[2][4][4];
#pragma unroll
    for (int i = 0; i < 2; i++)
#pragma unroll
        for (int j = 0; j < 4; j++)
#pragma unroll
            for (int v = 0; v < 4; v++) acc[i][j][v] = 0.0f;

    const int NC = K / 32;

    auto stage = [&](int buf, int c) {
        char* base = smem + buf * GBUF;
#pragma unroll
        for (int u = 0; u < 4; u++) {
            int e = t + u * 256;
            int pl = e >> 9, rem = e & 511;
            int row = rem >> 2, seg = rem & 3;
            const char* src = (const char*)(pl ? Alo : Ahi)
                + ((size_t)(m0 + row) * lda + c * 32) * 2 + seg * 16;
            cp16(smem_u32(base + pl * APL + row * PKB + seg * 16), src);
        }
#pragma unroll
        for (int u = 0; u < 2; u++) {
            int e = t + u * 256;
            int pl = e >> 8, rem = e & 255;
            int row = rem >> 2, seg = rem & 3;
            const char* src = (const char*)(pl ? Wlo : Whi)
                + ((size_t)row * ldw + c * 32) * 2 + seg * 16;
            cp16(smem_u32(base + 2 * APL + pl * WPLN + row * PKB + seg * 16), src);
        }
        CP_COMMIT();
    };

    stage(0, 0);
    for (int c = 0; c < NC; c++) {
        if (c + 1 < NC) {
            stage((c + 1) & 1, c + 1);
            asm volatile("cp.async.wait_group 1;" ::: "memory");
        } else {
            asm volatile("cp.async.wait_group 0;" ::: "memory");
        }
        __syncthreads();
        char* base = smem + (c & 1) * GBUF;
#pragma unroll
        for (int kk = 0; kk < 2; kk++) {
            uint32_t afr[2][2][4];
#pragma unroll
            for (int pl = 0; pl < 2; pl++)
#pragma unroll
                for (int mt = 0; mt < 2; mt++) {
                    uint32_t a = smem_u32(base + pl * APL
                        + (wm * 32 + mt * 16 + (lane & 15)) * PKB
                        + (kk * 16 + (lane >> 4) * 8) * 2);
                    ldm_x4(afr[pl][mt], a);
                }
#pragma unroll
            for (int nt = 0; nt < 4; nt++) {
                const char* bp = base + 2 * APL
                    + (wn * 32 + nt * 8 + (lane >> 2)) * PKB
                    + (kk * 16 + (lane & 3) * 2) * 2;
                uint32_t bh[2], bl[2];
                bh[0] = *(const uint32_t*)bp;
                bh[1] = *(const uint32_t*)(bp + 16);
                bl[0] = *(const uint32_t*)(bp + WPLN);
                bl[1] = *(const uint32_t*)(bp + WPLN + 16);
#pragma unroll
                for (int mt = 0; mt < 2; mt++) {
                    mma16816(acc[mt][nt], afr[0][mt], bh);
                    mma16816(acc[mt][nt], afr[0][mt], bl);
                    mma16816(acc[mt][nt], afr[1][mt], bh);
                }
            }
        }
        __syncthreads();
    }

    float part[2][2] = {{0.0f, 0.0f}, {0.0f, 0.0f}};
#pragma unroll
    for (int mt = 0; mt < 2; mt++)
#pragma unroll
        for (int nt = 0; nt < 4; nt++) {
            int col = wn * 32 + nt * 8 + (lane & 3) * 2;
            float b0 = bias[col], b1 = bias[col + 1];
            float r0 = r4[col], r1 = r4[col + 1];
            part[mt][0] += fmaxf(acc[mt][nt][0] + b0, 0.0f) * r0
                         + fmaxf(acc[mt][nt][1] + b1, 0.0f) * r1;
            part[mt][1] += fmaxf(acc[mt][nt][2] + b0, 0.0f) * r0
                         + fmaxf(acc[mt][nt][3] + b1, 0.0f) * r1;
        }
    float* sp = (float*)smem;
#pragma unroll
    for (int mt = 0; mt < 2; mt++)
#pragma unroll
        for (int h = 0; h < 2; h++) {
            float v = part[mt][h];
            v += __shfl_xor_sync(0xffffffffu, v, 1);
            v += __shfl_xor_sync(0xffffffffu, v, 2);
            if ((lane & 3) == 0)
                sp[(wm * 32 + mt * 16 + h * 8 + (lane >> 2)) * 2 + wn] = v;
        }
    __syncthreads();
    if (t < 128) finout[m0 + t] = sp[t * 2] + sp[t * 2 + 1] + rb4[0];
}

// ---------------- launch -----------------------------------------------------
extern "C" void kernel_launch(void* const* d_in, const int* in_sizes, int n_in,
                              void* d_out, int out_size) {
    const float* op  = (const float*)d_in[0];
    const float* qp  = (const float*)d_in[1];
    const float* w1  = (const float*)d_in[2];
    const float* b1  = (const float*)d_in[3];
    const float* w2  = (const float*)d_in[4];
    const float* b2  = (const float*)d_in[5];
    const float* w3  = (const float*)d_in[6];
    const float* b3  = (const float*)d_in[7];
    const float* r1  = (const float*)d_in[8];
    const float* rb1 = (const float*)d_in[9];
    const float* r2  = (const float*)d_in[10];
    const float* rb2 = (const float*)d_in[11];
    const float* r3  = (const float*)d_in[12];
    const float* rb3 = (const float*)d_in[13];
    const float* r4  = (const float*)d_in[14];
    const float* rb4 = (const float*)d_in[15];
    float* out = (float*)d_out;

    float* p_fall;
    cudaGetSymbolAddress((void**)&p_fall, g_fall);
    __nv_bfloat16 *f1h, *f1l, *f2h, *f2l, *agh, *agl, *h1h, *h1l, *h2h, *h2l;
    __nv_bfloat16 *w2h, *w2l, *w3h, *w3l, *r1h, *r1l, *r2h, *r2l, *r3h, *r3l;
    cudaGetSymbolAddress((void**)&f1h, g_f1h);  cudaGetSymbolAddress((void**)&f1l, g_f1l);
    cudaGetSymbolAddress((void**)&f2h, g_f2h);  cudaGetSymbolAddress((void**)&f2l, g_f2l);
    cudaGetSymbolAddress((void**)&agh, g_aggh); cudaGetSymbolAddress((void**)&agl, g_aggl);
    cudaGetSymbolAddress((void**)&h1h, g_h1h);  cudaGetSymbolAddress((void**)&h1l, g_h1l);
    cudaGetSymbolAddress((void**)&h2h, g_h2h);  cudaGetSymbolAddress((void**)&h2l, g_h2l);
    cudaGetSymbolAddress((void**)&w2h, g_w2h);  cudaGetSymbolAddress((void**)&w2l, g_w2l);
    cudaGetSymbolAddress((void**)&w3h, g_w3h);  cudaGetSymbolAddress((void**)&w3l, g_w3l);
    cudaGetSymbolAddress((void**)&r1h, g_r1h);  cudaGetSymbolAddress((void**)&r1l, g_r1l);
    cudaGetSymbolAddress((void**)&r2h, g_r2h);  cudaGetSymbolAddress((void**)&r2l, g_r2l);
    cudaGetSymbolAddress((void**)&r3h, g_r3h);  cudaGetSymbolAddress((void**)&r3l, g_r3l);

    constexpr int SM256 = 2 * (2 * APL + 2 * 256 * PKB);   // 122880
    constexpr int SM128 = 2 * (2 * APL + 2 * 128 * PKB);   // 81920
    cudaFuncSetAttribute(knn_kernel, cudaFuncAttributeMaxDynamicSharedMemorySize,
                         NP * (int)sizeof(float4));
    cudaFuncSetAttribute(tgemm_wide<256>, cudaFuncAttributeMaxDynamicSharedMemorySize, SM256);
    cudaFuncSetAttribute(tgemm_wide<128>, cudaFuncAttributeMaxDynamicSharedMemorySize, SM128);
    cudaFuncSetAttribute(tgemm_fin, cudaFuncAttributeMaxDynamicSharedMemorySize, 2 * GBUF);

    // 1: weight splits (single launch; r1 rotated)
    split_all_kernel<<<1088, 256>>>(w2, w3, r1, r2, r3);
    // 2-3: feature extractor front
    gmax_zero_kernel<<<2, 256>>>();
    mlp1_kernel<<<MPTS / 8, 256>>>(op, w1, b1);
    // 4: mlp2 64->128
    tgemm_wide<128><<<MPTS / 128, 512, SM128>>>(
        f1h, f1l, 64, w2h, w2l, b2, 64,
        p_fall + 64, FDIM, f2h, f2l, 128);
    // 5: mlp3 128->256
    tgemm_wide<256><<<MPTS / 128, 512, SM256>>>(
        f2h, f2l, 128, w3h, w3l, b3, 128,
        p_fall + 192, FDIM, nullptr, nullptr, 0);
    // 6-8: gmax, knn, agg
    gmax_kernel<<<MPTS / 128, 256>>>();
    knn_kernel<<<dim3(NQ / 256, BATCH), 256, NP * sizeof(float4)>>>(op, qp);
    agg_kernel<<<NPTS / 8, 256>>>(qp);
    // 9: gemm1 768->256
    tgemm_wide<256><<<NPTS / 128, 512, SM256>>>(
        agh, agl, AGGP, r1h, r1l, rb1, AGGP,
        nullptr, 0, h1h, h1l, 256);
    // 10: gemm2 256->128
    tgemm_wide<128><<<NPTS / 128, 512, SM128>>>(
        h1h, h1l, 256, r2h, r2l, rb2, 256,
        nullptr, 0, h2h, h2l, 128);
    // 11: gemm3 128->64 + fused final 64->1
    tgemm_fin<<<dim3(1, NPTS / 128), 256, 2 * GBUF>>>(
        h2h, h2l, 128, r3h, r3l, 128, rb3, 128, r4, rb4, out);
}

// round 7
// speedup vs baseline: 2.9518x; 1.0579x over previous
#include <cuda_runtime.h>
#include <cuda_bf16.h>
#include <math_constants.h>
#include <cstdint>

#define BATCH 2
#define NP    4096
#define NQ    16384
#define FDIM  448            // 64 + 128 + 256
#define AGGP  768            // 707 padded to multiple of 32
#define NPTS  (BATCH * NQ)   // 32768 query points
#define MPTS  (BATCH * NP)   // 8192 original points

// ---------------- scratch (device globals; no allocation allowed) -----------
__device__ float g_fall[MPTS * FDIM];          // point-major fp32 (f1|f2|f3)
__device__ int   g_gmax[BATCH * 256];
__device__ int   g_knni[NPTS * 3];
__device__ float g_knnw[NPTS * 3];
__device__ __nv_bfloat16 g_f1h[MPTS * 64],   g_f1l[MPTS * 64];
__device__ __nv_bfloat16 g_f2h[MPTS * 128],  g_f2l[MPTS * 128];
__device__ __nv_bfloat16 g_h1h[(size_t)NPTS * 256],   g_h1l[(size_t)NPTS * 256];
__device__ __nv_bfloat16 g_h2h[(size_t)NPTS * 128],   g_h2l[(size_t)NPTS * 128];
__device__ __nv_bfloat16 g_w2h[128 * 64],   g_w2l[128 * 64];
__device__ __nv_bfloat16 g_w3h[256 * 128],  g_w3l[256 * 128];
__device__ __nv_bfloat16 g_r1h[256 * AGGP], g_r1l[256 * AGGP];   // rotated cols
__device__ __nv_bfloat16 g_r2h[128 * 256],  g_r2l[128 * 256];
__device__ __nv_bfloat16 g_r3h[64 * 128],   g_r3l[64 * 128];

// ---------------- helpers -----------------------------------------------------
__device__ __forceinline__ uint32_t smem_u32(const void* p) {
    uint32_t a;
    asm("{ .reg .u64 t; cvta.to.shared.u64 t, %1; cvt.u32.u64 %0, t; }" : "=r"(a) : "l"(p));
    return a;
}
__device__ __forceinline__ void cp16(uint32_t dst, const void* src) {
    asm volatile("cp.async.cg.shared.global [%0], [%1], 16;" :: "r"(dst), "l"(src));
}
#define CP_COMMIT() asm volatile("cp.async.commit_group;" ::: "memory")

__device__ __forceinline__ void ldm_x4(uint32_t* r, uint32_t addr) {
    asm volatile("ldmatrix.sync.aligned.m8n8.x4.shared.b16 {%0,%1,%2,%3}, [%4];"
                 : "=r"(r[0]), "=r"(r[1]), "=r"(r[2]), "=r"(r[3]) : "r"(addr));
}
__device__ __forceinline__ void mma16816(float* c, const uint32_t* a, const uint32_t* b) {
    asm volatile(
        "mma.sync.aligned.m16n8k16.row.col.f32.bf16.bf16.f32 "
        "{%0,%1,%2,%3}, {%4,%5,%6,%7}, {%8,%9}, {%0,%1,%2,%3};"
        : "+f"(c[0]), "+f"(c[1]), "+f"(c[2]), "+f"(c[3])
        : "r"(a[0]), "r"(a[1]), "r"(a[2]), "r"(a[3]), "r"(b[0]), "r"(b[1]));
}
__device__ __forceinline__ void split_bf16(float v, __nv_bfloat16& h, __nv_bfloat16& l) {
    h = __float2bfloat16(v);
    l = __float2bfloat16(v - __bfloat162float(h));
}
__device__ __forceinline__ uint32_t pck(__nv_bfloat16 a, __nv_bfloat16 b) {
    return (uint32_t)*(unsigned short*)&a | ((uint32_t)*(unsigned short*)&b << 16);
}

// ---------------- mlp1: 3 -> 64 (fp32 to g_fall + hi/lo planes) --------------
__global__ void __launch_bounds__(256) mlp1_kernel(const float* __restrict__ op,
                                                   const float* __restrict__ w1,
                                                   const float* __restrict__ b1) {
    __shared__ float sw[192];
    __shared__ float sb[64];
    int t = threadIdx.x;
    if (t < 192) sw[t] = w1[t];
    if (t < 64)  sb[t] = b1[t];
    __syncthreads();
    int pfl  = blockIdx.x * 8 + (t >> 5);
    int lane = t & 31;
    int b  = pfl >> 12;
    int pt = pfl & (NP - 1);
    float x = op[b * 3 * NP + 0 * NP + pt];
    float y = op[b * 3 * NP + 1 * NP + pt];
    float z = op[b * 3 * NP + 2 * NP + pt];
    float* dst = g_fall + (size_t)pfl * FDIM;
#pragma unroll
    for (int u = 0; u < 2; u++) {
        int c = lane + u * 32;
        float v = fmaf(sw[c*3+0], x, fmaf(sw[c*3+1], y, fmaf(sw[c*3+2], z, sb[c])));
        v = fmaxf(v, 0.0f);
        dst[c] = v;
        __nv_bfloat16 h, l; split_bf16(v, h, l);
        g_f1h[pfl * 64 + c] = h;
        g_f1l[pfl * 64 + c] = l;
    }
}

__global__ void gmax_zero_kernel() {
    int t = threadIdx.x + blockIdx.x * blockDim.x;
    if (t < BATCH * 256) g_gmax[t] = 0;
}

// ---------------- single fused weight split (+pad, r1 rotated) ---------------
__global__ void __launch_bounds__(256) split_all_kernel(
    const float* __restrict__ w2, const float* __restrict__ w3,
    const float* __restrict__ r1, const float* __restrict__ r2,
    const float* __restrict__ r3) {
    int i = blockIdx.x * 256 + threadIdx.x;
    if (i >= 278528) return;
    const float* src; __nv_bfloat16 *hi, *lo;
    int off, kpad, kin; bool rot = false;
    if (i < 8192)        { src = w2; hi = g_w2h; lo = g_w2l; off = i;          kpad = 64;  kin = 64;  }
    else if (i < 40960)  { src = w3; hi = g_w3h; lo = g_w3l; off = i - 8192;   kpad = 128; kin = 128; }
    else if (i < 237568) { src = r1; hi = g_r1h; lo = g_r1l; off = i - 40960;  kpad = AGGP; kin = 707; rot = true; }
    else if (i < 270336) { src = r2; hi = g_r2h; lo = g_r2l; off = i - 237568; kpad = 256; kin = 256; }
    else                 { src = r3; hi = g_r3h; lo = g_r3l; off = i - 270336; kpad = 128; kin = 128; }
    int r = off / kpad, k = off - r * kpad;
    float v = 0.0f;
    if (k < kin) {
        int ks = rot ? ((k + 3 >= 707) ? k + 3 - 707 : k + 3) : k;
        v = src[r * kin + ks];
    }
    __nv_bfloat16 h, l; split_bf16(v, h, l);
    hi[off] = h; lo[off] = l;
}

// ---------------- KNN (top-3) ------------------------------------------------
__global__ void __launch_bounds__(256) knn_kernel(const float* __restrict__ op,
                                                  const float* __restrict__ qp) {
    extern __shared__ float4 sp[];        // NP * 16B = 64 KB
    int b = blockIdx.y;
    int tid = threadIdx.x;
    for (int i = tid; i < NP; i += 256) {
        float x = op[b * 3 * NP + 0 * NP + i];
        float y = op[b * 3 * NP + 1 * NP + i];
        float z = op[b * 3 * NP + 2 * NP + i];
        sp[i] = make_float4(x, y, z, fmaf(x, x, fmaf(y, y, z * z)));
    }
    __syncthreads();

    int q = blockIdx.x * 256 + tid;
    float qx = qp[b * 3 * NQ + 0 * NQ + q];
    float qy = qp[b * 3 * NQ + 1 * NQ + q];
    float qz = qp[b * 3 * NQ + 2 * NQ + q];
    float nx = -2.0f * qx, ny = -2.0f * qy, nz = -2.0f * qz;

    float d0 = CUDART_INF_F, d1 = CUDART_INF_F, d2 = CUDART_INF_F;
    int i0 = 0, i1 = 0, i2 = 0;
#pragma unroll 8
    for (int j = 0; j < NP; j++) {
        float4 o = sp[j];
        float d = fmaf(o.x, nx, fmaf(o.y, ny, fmaf(o.z, nz, o.w)));
        if (d < d2) {
            if (d < d1) {
                d2 = d1; i2 = i1;
                if (d < d0) { d1 = d0; i1 = i0; d0 = d; i0 = j; }
                else        { d1 = d;  i1 = j; }
            } else { d2 = d; i2 = j; }
        }
    }
    int   ii[3] = {i0, i1, i2};
    float rc[3];
    float s = 0.0f;
#pragma unroll
    for (int k = 0; k < 3; k++) {
        float4 o = sp[ii[k]];
        float dx = o.x - qx, dy = o.y - qy, dz = o.z - qz;
        float dist = sqrtf(fmaf(dx, dx, fmaf(dy, dy, dz * dz)));
        rc[k] = 1.0f / (dist + 1e-8f);
        s += rc[k];
    }
    float inv = 1.0f / s;
    int base = (b * NQ + q) * 3;
#pragma unroll
    for (int k = 0; k < 3; k++) {
        g_knni[base + k] = ii[k];
        g_knnw[base + k] = rc[k] * inv;
    }
}

// ---------------- wide split-bf16 tensor GEMM: full N per CTA ----------------
// BM=128 (grid.x), BN=N (128 or 256), BK=32, 512 thr = 16 warps (4m x 4n).
// GMAX: fold per-column global max (atomicMax) into the epilogue (for mlp3).
#define PKB 80                       // smem row pitch bytes (32 bf16 + 16B pad)
#define APL (128 * PKB)              // A plane bytes (10240)

template <int BN, bool GMAX>
__global__ void __launch_bounds__(512) tgemm_wide(
    const __nv_bfloat16* __restrict__ Ahi, const __nv_bfloat16* __restrict__ Alo, int lda,
    const __nv_bfloat16* __restrict__ Whi, const __nv_bfloat16* __restrict__ Wlo,
    const float* __restrict__ bias, int K,
    float* __restrict__ f32out, int f32ld,
    __nv_bfloat16* __restrict__ phi, __nv_bfloat16* __restrict__ plo, int pld) {
    extern __shared__ char smem[];
    constexpr int WPL = BN * PKB;                 // W plane bytes
    constexpr int SS  = 2 * APL + 2 * WPL;        // one stage
    constexpr int NT8 = BN / 32;                  // n8 tiles per warp
    const int t = threadIdx.x;
    const int lane = t & 31, warp = t >> 5;
    const int wm = warp >> 2, wn = warp & 3;
    const int m0 = blockIdx.x * 128;
    const int ldw = K;

    float acc[2][NT8][4];
#pragma unroll
    for (int i = 0; i < 2; i++)
#pragma unroll
        for (int j = 0; j < NT8; j++)
#pragma unroll
            for (int v = 0; v < 4; v++) acc[i][j][v] = 0.0f;

    const int NC = K / 32;

    auto stage = [&](int buf, int c) {
        char* base = smem + buf * SS;
#pragma unroll
        for (int u = 0; u < 2; u++) {                 // A: 1024 cp16
            int e = t + u * 512;
            int pl = e >> 9, rem = e & 511;
            int row = rem >> 2, seg = rem & 3;
            const char* src = (const char*)(pl ? Alo : Ahi)
                + ((size_t)(m0 + row) * lda + c * 32) * 2 + seg * 16;
            cp16(smem_u32(base + pl * APL + row * PKB + seg * 16), src);
        }
#pragma unroll
        for (int u = 0; u < BN / 64; u++) {           // W: BN*8 cp16
            int e = t + u * 512;
            int pl = e / (BN * 4), rem = e % (BN * 4);
            int row = rem >> 2, seg = rem & 3;
            const char* src = (const char*)(pl ? Wlo : Whi)
                + ((size_t)row * ldw + c * 32) * 2 + seg * 16;
            cp16(smem_u32(base + 2 * APL + pl * WPL + row * PKB + seg * 16), src);
        }
        CP_COMMIT();
    };

    stage(0, 0);
    for (int c = 0; c < NC; c++) {
        if (c + 1 < NC) {
            stage((c + 1) & 1, c + 1);
            asm volatile("cp.async.wait_group 1;" ::: "memory");
        } else {
            asm volatile("cp.async.wait_group 0;" ::: "memory");
        }
        __syncthreads();
        char* base = smem + (c & 1) * SS;
#pragma unroll
        for (int kk = 0; kk < 2; kk++) {
            uint32_t afr[2][2][4];
#pragma unroll
            for (int pl = 0; pl < 2; pl++)
#pragma unroll
                for (int mt = 0; mt < 2; mt++) {
                    uint32_t a = smem_u32(base + pl * APL
                        + (wm * 32 + mt * 16 + (lane & 15)) * PKB
                        + (kk * 16 + (lane >> 4) * 8) * 2);
                    ldm_x4(afr[pl][mt], a);
                }
#pragma unroll
            for (int nt = 0; nt < NT8; nt++) {
                const char* bp = base + 2 * APL
                    + (wn * (BN / 4) + nt * 8 + (lane >> 2)) * PKB
                    + (kk * 16 + (lane & 3) * 2) * 2;
                uint32_t bh[2], bl[2];
                bh[0] = *(const uint32_t*)bp;
                bh[1] = *(const uint32_t*)(bp + 16);
                bl[0] = *(const uint32_t*)(bp + WPL);
                bl[1] = *(const uint32_t*)(bp + WPL + 16);
#pragma unroll
                for (int mt = 0; mt < 2; mt++) {
                    mma16816(acc[mt][nt], afr[0][mt], bh);
                    mma16816(acc[mt][nt], afr[0][mt], bl);
                    mma16816(acc[mt][nt], afr[1][mt], bh);
                }
            }
        }
        __syncthreads();
    }

    // epilogue: bias + relu, write fp32 and/or hi/lo planes
#pragma unroll
    for (int mt = 0; mt < 2; mt++)
#pragma unroll
        for (int nt = 0; nt < NT8; nt++) {
            int row0 = m0 + wm * 32 + mt * 16 + (lane >> 2);
            int col = wn * (BN / 4) + nt * 8 + (lane & 3) * 2;
            float b0 = bias[col], b1 = bias[col + 1];
            float v0 = fmaxf(acc[mt][nt][0] + b0, 0.0f);
            float v1 = fmaxf(acc[mt][nt][1] + b1, 0.0f);
            float v2 = fmaxf(acc[mt][nt][2] + b0, 0.0f);
            float v3 = fmaxf(acc[mt][nt][3] + b1, 0.0f);
            if (f32out) {
                *(float2*)(f32out + (size_t)row0 * f32ld + col) = make_float2(v0, v1);
                *(float2*)(f32out + (size_t)(row0 + 8) * f32ld + col) = make_float2(v2, v3);
            }
            if (phi) {
                __nv_bfloat16 h0, l0, h1, l1;
                split_bf16(v0, h0, l0); split_bf16(v1, h1, l1);
                *(uint32_t*)((unsigned short*)phi + (size_t)row0 * pld + col) = pck(h0, h1);
                *(uint32_t*)((unsigned short*)plo + (size_t)row0 * pld + col) = pck(l0, l1);
                split_bf16(v2, h0, l0); split_bf16(v3, h1, l1);
                *(uint32_t*)((unsigned short*)phi + (size_t)(row0 + 8) * pld + col) = pck(h0, h1);
                *(uint32_t*)((unsigned short*)plo + (size_t)(row0 + 8) * pld + col) = pck(l0, l1);
            }
        }

    if (GMAX) {
        int b = m0 >> 12;   // NP = 4096 rows per batch
#pragma unroll
        for (int nt = 0; nt < NT8; nt++) {
            int col = wn * (BN / 4) + nt * 8 + (lane & 3) * 2;
            float b0 = bias[col], b1 = bias[col + 1];
            float mA = fmaxf(fmaxf(acc[0][nt][0], acc[0][nt][2]),
                             fmaxf(acc[1][nt][0], acc[1][nt][2])) + b0;
            float mB = fmaxf(fmaxf(acc[0][nt][1], acc[0][nt][3]),
                             fmaxf(acc[1][nt][1], acc[1][nt][3])) + b1;
            mA = fmaxf(mA, 0.0f); mB = fmaxf(mB, 0.0f);
#pragma unroll
            for (int o = 4; o < 32; o <<= 1) {
                mA = fmaxf(mA, __shfl_xor_sync(0xffffffffu, mA, o));
                mB = fmaxf(mB, __shfl_xor_sync(0xffffffffu, mB, o));
            }
            if ((lane >> 2) == 0) {
                atomicMax(&g_gmax[b * 256 + col],     __float_as_int(mA));
                atomicMax(&g_gmax[b * 256 + col + 1], __float_as_int(mB));
            }
        }
    }
}

// ---------------- gemm1 with FUSED interpolation staging ---------------------
// A[q][k] built on the fly: k<448 interp from fall via knn, 448-703 gmax,
// 704-706 query coords, rest 0 (matches rotated r1).  BN=256, K=768.
__global__ void __launch_bounds__(512) tgemm_g1(
    const float* __restrict__ fall, const float* __restrict__ qp,
    const __nv_bfloat16* __restrict__ Whi, const __nv_bfloat16* __restrict__ Wlo,
    const float* __restrict__ bias,
    __nv_bfloat16* __restrict__ phi, __nv_bfloat16* __restrict__ plo) {
    constexpr int BN = 256, K = AGGP, NC = K / 32, NT8 = BN / 32;
    constexpr int WPL = BN * PKB;
    constexpr int SS  = 2 * APL + 2 * WPL;
    extern __shared__ char smem[];
    int*   si  = (int*)(smem + 2 * SS);            // [128*3]
    float* swt = (float*)(smem + 2 * SS + 1536);   // [128*3]
    float* gms = (float*)(smem + 2 * SS + 3072);   // [256]
    const int t = threadIdx.x;
    const int lane = t & 31, warp = t >> 5;
    const int wm = warp >> 2, wn = warp & 3;
    const int m0 = blockIdx.x * 128;
    const int b  = m0 >> 14;                       // NQ = 16384

    if (t < 128) {
#pragma unroll
        for (int j = 0; j < 3; j++) {
            si[t * 3 + j]  = g_knni[(m0 + t) * 3 + j];
            swt[t * 3 + j] = g_knnw[(m0 + t) * 3 + j];
        }
    } else if (t >= 256) {
        gms[t - 256] = __int_as_float(g_gmax[b * 256 + t - 256]);
    }
    __syncthreads();

    float acc[2][NT8][4];
#pragma unroll
    for (int i = 0; i < 2; i++)
#pragma unroll
        for (int j = 0; j < NT8; j++)
#pragma unroll
            for (int v = 0; v < 4; v++) acc[i][j][v] = 0.0f;

    auto stageW = [&](int buf, int c) {
        char* base = smem + buf * SS;
#pragma unroll
        for (int u = 0; u < 4; u++) {
            int e = t + u * 512;
            int pl = e >> 10, rem = e & 1023;
            int row = rem >> 2, seg = rem & 3;
            const char* src = (const char*)(pl ? Wlo : Whi)
                + ((size_t)row * K + c * 32) * 2 + seg * 16;
            cp16(smem_u32(base + 2 * APL + pl * WPL + row * PKB + seg * 16), src);
        }
        CP_COMMIT();
    };

    auto stageA = [&](char* base, int c) {
        const int ch0 = c * 32;
#pragma unroll
        for (int u = 0; u < 2; u++) {
            int e = t + u * 512;
            int row = e >> 3, c4 = e & 7;
            int ch = ch0 + c4 * 4;
            float v0, v1, v2, v3;
            if (ch < 448) {
                const float* fr = fall + (size_t)(b * NP) * FDIM + ch;
                float4 A = *(const float4*)(fr + (size_t)si[row * 3 + 0] * FDIM);
                float4 B = *(const float4*)(fr + (size_t)si[row * 3 + 1] * FDIM);
                float4 C = *(const float4*)(fr + (size_t)si[row * 3 + 2] * FDIM);
                float wa = swt[row * 3 + 0], wb = swt[row * 3 + 1], wc = swt[row * 3 + 2];
                v0 = wa * A.x + wb * B.x + wc * C.x;
                v1 = wa * A.y + wb * B.y + wc * C.y;
                v2 = wa * A.z + wb * B.z + wc * C.z;
                v3 = wa * A.w + wb * B.w + wc * C.w;
            } else if (ch < 704) {
                v0 = gms[ch - 448]; v1 = gms[ch - 447];
                v2 = gms[ch - 446]; v3 = gms[ch - 445];
            } else if (ch == 704) {
                int qi = (m0 + row) & (NQ - 1);
                v0 = qp[b * 3 * NQ + 0 * NQ + qi];
                v1 = qp[b * 3 * NQ + 1 * NQ + qi];
                v2 = qp[b * 3 * NQ + 2 * NQ + qi];
                v3 = 0.0f;
            } else {
                v0 = v1 = v2 = v3 = 0.0f;
            }
            __nv_bfloat16 h0, l0, h1, l1, h2, l2, h3, l3;
            split_bf16(v0, h0, l0); split_bf16(v1, h1, l1);
            split_bf16(v2, h2, l2); split_bf16(v3, h3, l3);
            int off = row * PKB + (c4 >> 1) * 16 + (c4 & 1) * 8;
            *(uint2*)(base + off)       = make_uint2(pck(h0, h1), pck(h2, h3));
            *(uint2*)(base + APL + off) = make_uint2(pck(l0, l1), pck(l2, l3));
        }
    };

    stageW(0, 0);
    for (int c = 0; c < NC; c++) {
        char* base = smem + (c & 1) * SS;
        stageA(base, c);
        if (c + 1 < NC) {
            stageW((c + 1) & 1, c + 1);
            asm volatile("cp.async.wait_group 1;" ::: "memory");
        } else {
            asm volatile("cp.async.wait_group 0;" ::: "memory");
        }
        __syncthreads();
#pragma unroll
        for (int kk = 0; kk < 2; kk++) {
            uint32_t afr[2][2][4];
#pragma unroll
            for (int pl = 0; pl < 2; pl++)
#pragma unroll
                for (int mt = 0; mt < 2; mt++) {
                    uint32_t a = smem_u32(base + pl * APL
                        + (wm * 32 + mt * 16 + (lane & 15)) * PKB
                        + (kk * 16 + (lane >> 4) * 8) * 2);
                    ldm_x4(afr[pl][mt], a);
                }
#pragma unroll
            for (int nt = 0; nt < NT8; nt++) {
                const char* bp = base + 2 * APL
                    + (wn * (BN / 4) + nt * 8 + (lane >> 2)) * PKB
                    + (kk * 16 + (lane & 3) * 2) * 2;
                uint32_t bh[2], bl[2];
                bh[0] = *(const uint32_t*)bp;
                bh[1] = *(const uint32_t*)(bp + 16);
                bl[0] = *(const uint32_t*)(bp + WPL);
                bl[1] = *(const uint32_t*)(bp + WPL + 16);
#pragma unroll
                for (int mt = 0; mt < 2; mt++) {
                    mma16816(acc[mt][nt], afr[0][mt], bh);
                    mma16816(acc[mt][nt], afr[0][mt], bl);
                    mma16816(acc[mt][nt], afr[1][mt], bh);
                }
            }
        }
        __syncthreads();
    }

#pragma unroll
    for (int mt = 0; mt < 2; mt++)
#pragma unroll
        for (int nt = 0; nt < NT8; nt++) {
            int row0 = m0 + wm * 32 + mt * 16 + (lane >> 2);
            int col = wn * (BN / 4) + nt * 8 + (lane & 3) * 2;
            float b0 = bias[col], b1 = bias[col + 1];
            float v0 = fmaxf(acc[mt][nt][0] + b0, 0.0f);
            float v1 = fmaxf(acc[mt][nt][1] + b1, 0.0f);
            float v2 = fmaxf(acc[mt][nt][2] + b0, 0.0f);
            float v3 = fmaxf(acc[mt][nt][3] + b1, 0.0f);
            __nv_bfloat16 h0, l0, h1, l1;
            split_bf16(v0, h0, l0); split_bf16(v1, h1, l1);
            *(uint32_t*)((unsigned short*)phi + (size_t)row0 * 256 + col) = pck(h0, h1);
            *(uint32_t*)((unsigned short*)plo + (size_t)row0 * 256 + col) = pck(l0, l1);
            split_bf16(v2, h0, l0); split_bf16(v3, h1, l1);
            *(uint32_t*)((unsigned short*)phi + (size_t)(row0 + 8) * 256 + col) = pck(h0, h1);
            *(uint32_t*)((unsigned short*)plo + (size_t)(row0 + 8) * 256 + col) = pck(l0, l1);
        }
}

// ---------------- narrow GEMM with fused final 64->1 (validated) -------------
#define WPLN (64 * PKB)
#define GBUF (2 * APL + 2 * WPLN)

__global__ void __launch_bounds__(256) tgemm_fin(
    const __nv_bfloat16* __restrict__ Ahi, const __nv_bfloat16* __restrict__ Alo, int lda,
    const __nv_bfloat16* __restrict__ Whi, const __nv_bfloat16* __restrict__ Wlo, int ldw,
    const float* __restrict__ bias, int K,
    const float* __restrict__ r4, const float* __restrict__ rb4,
    float* __restrict__ finout) {
    extern __shared__ char smem[];
    const int t = threadIdx.x;
    const int lane = t & 31, warp = t >> 5;
    const int wm = warp >> 1, wn = warp & 1;
    const int m0 = blockIdx.y * 128;

    float acc[2][4][4];
#pragma unroll
    for (int i = 0; i < 2; i++)
#pragma unroll
        for (int j = 0; j < 4; j++)
#pragma unroll
            for (int v = 0; v < 4; v++) acc[i][j][v] = 0.0f;

    const int NC = K / 32;

    auto stage = [&](int buf, int c) {
        char* base = smem + buf * GBUF;
#pragma unroll
        for (int u = 0; u < 4; u++) {
            int e = t + u * 256;
            int pl = e >> 9, rem = e & 511;
            int row = rem >> 2, seg = rem & 3;
            const char* src = (const char*)(pl ? Alo : Ahi)
                + ((size_t)(m0 + row) * lda + c * 32) * 2 + seg * 16;
            cp16(smem_u32(base + pl * APL + row * PKB + seg * 16), src);
        }
#pragma unroll
        for (int u = 0; u < 2; u++) {
            int e = t + u * 256;
            int pl = e >> 8, rem = e & 255;
            int row = rem >> 2, seg = rem & 3;
            const char* src = (const char*)(pl ? Wlo : Whi)
                + ((size_t)row * ldw + c * 32) * 2 + seg * 16;
            cp16(smem_u32(base + 2 * APL + pl * WPLN + row * PKB + seg * 16), src);
        }
        CP_COMMIT();
    };

    stage(0, 0);
    for (int c = 0; c < NC; c++) {
        if (c + 1 < NC) {
            stage((c + 1) & 1, c + 1);
            asm volatile("cp.async.wait_group 1;" ::: "memory");
        } else {
            asm volatile("cp.async.wait_group 0;" ::: "memory");
        }
        __syncthreads();
        char* base = smem + (c & 1) * GBUF;
#pragma unroll
        for (int kk = 0; kk < 2; kk++) {
            uint32_t afr[2][2][4];
#pragma unroll
            for (int pl = 0; pl < 2; pl++)
#pragma unroll
                for (int mt = 0; mt < 2; mt++) {
                    uint32_t a = smem_u32(base + pl * APL
                        + (wm * 32 + mt * 16 + (lane & 15)) * PKB
                        + (kk * 16 + (lane >> 4) * 8) * 2);
                    ldm_x4(afr[pl][mt], a);
                }
#pragma unroll
            for (int nt = 0; nt < 4; nt++) {
                const char* bp = base + 2 * APL
                    + (wn * 32 + nt * 8 + (lane >> 2)) * PKB
                    + (kk * 16 + (lane & 3) * 2) * 2;
                uint32_t bh[2], bl[2];
                bh[0] = *(const uint32_t*)bp;
                bh[1] = *(const uint32_t*)(bp + 16);
                bl[0] = *(const uint32_t*)(bp + WPLN);
                bl[1] = *(const uint32_t*)(bp + WPLN + 16);
#pragma unroll
                for (int mt = 0; mt < 2; mt++) {
                    mma16816(acc[mt][nt], afr[0][mt], bh);
                    mma16816(acc[mt][nt], afr[0][mt], bl);
                    mma16816(acc[mt][nt], afr[1][mt], bh);
                }
            }
        }
        __syncthreads();
    }

    float part[2][2] = {{0.0f, 0.0f}, {0.0f, 0.0f}};
#pragma unroll
    for (int mt = 0; mt < 2; mt++)
#pragma unroll
        for (int nt = 0; nt < 4; nt++) {
            int col = wn * 32 + nt * 8 + (lane & 3) * 2;
            float b0 = bias[col], b1 = bias[col + 1];
            float r0 = r4[col], r1 = r4[col + 1];
            part[mt][0] += fmaxf(acc[mt][nt][0] + b0, 0.0f) * r0
                         + fmaxf(acc[mt][nt][1] + b1, 0.0f) * r1;
            part[mt][1] += fmaxf(acc[mt][nt][2] + b0, 0.0f) * r0
                         + fmaxf(acc[mt][nt][3] + b1, 0.0f) * r1;
        }
    float* sp = (float*)smem;
#pragma unroll
    for (int mt = 0; mt < 2; mt++)
#pragma unroll
        for (int h = 0; h < 2; h++) {
            float v = part[mt][h];
            v += __shfl_xor_sync(0xffffffffu, v, 1);
            v += __shfl_xor_sync(0xffffffffu, v, 2);
            if ((lane & 3) == 0)
                sp[(wm * 32 + mt * 16 + h * 8 + (lane >> 2)) * 2 + wn] = v;
        }
    __syncthreads();
    if (t < 128) finout[m0 + t] = sp[t * 2] + sp[t * 2 + 1] + rb4[0];
}

// ---------------- launch -----------------------------------------------------
extern "C" void kernel_launch(void* const* d_in, const int* in_sizes, int n_in,
                              void* d_out, int out_size) {
    const float* op  = (const float*)d_in[0];
    const float* qp  = (const float*)d_in[1];
    const float* w1  = (const float*)d_in[2];
    const float* b1  = (const float*)d_in[3];
    const float* w2  = (const float*)d_in[4];
    const float* b2  = (const float*)d_in[5];
    const float* w3  = (const float*)d_in[6];
    const float* b3  = (const float*)d_in[7];
    const float* r1  = (const float*)d_in[8];
    const float* rb1 = (const float*)d_in[9];
    const float* r2  = (const float*)d_in[10];
    const float* rb2 = (const float*)d_in[11];
    const float* r3  = (const float*)d_in[12];
    const float* rb3 = (const float*)d_in[13];
    const float* r4  = (const float*)d_in[14];
    const float* rb4 = (const float*)d_in[15];
    float* out = (float*)d_out;

    float* p_fall;
    cudaGetSymbolAddress((void**)&p_fall, g_fall);
    __nv_bfloat16 *f1h, *f1l, *f2h, *f2l, *h1h, *h1l, *h2h, *h2l;
    __nv_bfloat16 *w2h, *w2l, *w3h, *w3l, *r1h, *r1l, *r2h, *r2l, *r3h, *r3l;
    cudaGetSymbolAddress((void**)&f1h, g_f1h);  cudaGetSymbolAddress((void**)&f1l, g_f1l);
    cudaGetSymbolAddress((void**)&f2h, g_f2h);  cudaGetSymbolAddress((void**)&f2l, g_f2l);
    cudaGetSymbolAddress((void**)&h1h, g_h1h);  cudaGetSymbolAddress((void**)&h1l, g_h1l);
    cudaGetSymbolAddress((void**)&h2h, g_h2h);  cudaGetSymbolAddress((void**)&h2l, g_h2l);
    cudaGetSymbolAddress((void**)&w2h, g_w2h);  cudaGetSymbolAddress((void**)&w2l, g_w2l);
    cudaGetSymbolAddress((void**)&w3h, g_w3h);  cudaGetSymbolAddress((void**)&w3l, g_w3l);
    cudaGetSymbolAddress((void**)&r1h, g_r1h);  cudaGetSymbolAddress((void**)&r1l, g_r1l);
    cudaGetSymbolAddress((void**)&r2h, g_r2h);  cudaGetSymbolAddress((void**)&r2l, g_r2l);
    cudaGetSymbolAddress((void**)&r3h, g_r3h);  cudaGetSymbolAddress((void**)&r3l, g_r3l);

    constexpr int SM256 = 2 * (2 * APL + 2 * 256 * PKB);   // 122880
    constexpr int SM128 = 2 * (2 * APL + 2 * 128 * PKB);   // 81920
    constexpr int SMG1  = SM256 + 4096;
    cudaFuncSetAttribute(knn_kernel, cudaFuncAttributeMaxDynamicSharedMemorySize,
                         NP * (int)sizeof(float4));
    cudaFuncSetAttribute(tgemm_wide<256, true>,  cudaFuncAttributeMaxDynamicSharedMemorySize, SM256);
    cudaFuncSetAttribute(tgemm_wide<128, false>, cudaFuncAttributeMaxDynamicSharedMemorySize, SM128);
    cudaFuncSetAttribute(tgemm_g1, cudaFuncAttributeMaxDynamicSharedMemorySize, SMG1);
    cudaFuncSetAttribute(tgemm_fin, cudaFuncAttributeMaxDynamicSharedMemorySize, 2 * GBUF);

    split_all_kernel<<<1088, 256>>>(w2, w3, r1, r2, r3);
    gmax_zero_kernel<<<2, 256>>>();
    mlp1_kernel<<<MPTS / 8, 256>>>(op, w1, b1);
    // mlp2 64->128
    tgemm_wide<128, false><<<MPTS / 128, 512, SM128>>>(
        f1h, f1l, 64, w2h, w2l, b2, 64,
        p_fall + 64, FDIM, f2h, f2l, 128);
    // mlp3 128->256 + fused gmax
    tgemm_wide<256, true><<<MPTS / 128, 512, SM256>>>(
        f2h, f2l, 128, w3h, w3l, b3, 128,
        p_fall + 192, FDIM, nullptr, nullptr, 0);
    // knn
    knn_kernel<<<dim3(NQ / 256, BATCH), 256, NP * sizeof(float4)>>>(op, qp);
    // gemm1 768->256 with fused interpolation staging
    tgemm_g1<<<NPTS / 128, 512, SMG1>>>(p_fall, qp, r1h, r1l, rb1, h1h, h1l);
    // gemm2 256->128
    tgemm_wide<128, false><<<NPTS / 128, 512, SM128>>>(
        h1h, h1l, 256, r2h, r2l, rb2, 256,
        nullptr, 0, h2h, h2l, 128);
    // gemm3 128->64 + fused final 64->1
    tgemm_fin<<<dim3(1, NPTS / 128), 256, 2 * GBUF>>>(
        h2h, h2l, 128, r3h, r3l, 128, rb3, 128, r4, rb4, out);
}

// round 8
// speedup vs baseline: 3.7614x; 1.2742x over previous
#include <cuda_runtime.h>
#include <cuda_bf16.h>
#include <math_constants.h>
#include <cstdint>

#define BATCH 2
#define NP    4096
#define NPH   2048           // half of NP (knn split)
#define NQ    16384
#define FDIM  448            // 64 + 128 + 256
#define AGK   480            // gemm1 K: 448 interp + 3 query + 29 pad
#define NPTS  (BATCH * NQ)   // 32768 query points
#define MPTS  (BATCH * NP)   // 8192 original points

// ---------------- scratch (device globals; no allocation allowed) -----------
__device__ float g_fall[MPTS * FDIM];          // point-major fp32 (f1|f2|f3)
__device__ int   g_gmax[BATCH * 256];
__device__ float g_b1[BATCH * 256];            // gemm1 bias incl. global feats
__device__ int   g_knni[NPTS * 3];
__device__ float g_knnw[NPTS * 3];
__device__ float g_kcd[NPTS * 6];              // knn candidates (2 halves x 3)
__device__ int   g_kci[NPTS * 6];
__device__ __nv_bfloat16 g_f1h[MPTS * 64],   g_f1l[MPTS * 64];
__device__ __nv_bfloat16 g_f2h[MPTS * 128],  g_f2l[MPTS * 128];
__device__ __nv_bfloat16 g_h1h[(size_t)NPTS * 256],   g_h1l[(size_t)NPTS * 256];
__device__ __nv_bfloat16 g_h2h[(size_t)NPTS * 128],   g_h2l[(size_t)NPTS * 128];
__device__ __nv_bfloat16 g_w2h[128 * 64],   g_w2l[128 * 64];
__device__ __nv_bfloat16 g_w3h[256 * 128],  g_w3l[256 * 128];
__device__ __nv_bfloat16 g_r1h[256 * AGK],  g_r1l[256 * AGK];   // remapped cols
__device__ __nv_bfloat16 g_r2h[128 * 256],  g_r2l[128 * 256];
__device__ __nv_bfloat16 g_r3h[64 * 128],   g_r3l[64 * 128];

// ---------------- helpers -----------------------------------------------------
__device__ __forceinline__ uint32_t smem_u32(const void* p) {
    uint32_t a;
    asm("{ .reg .u64 t; cvta.to.shared.u64 t, %1; cvt.u32.u64 %0, t; }" : "=r"(a) : "l"(p));
    return a;
}
__device__ __forceinline__ void cp16(uint32_t dst, const void* src) {
    asm volatile("cp.async.cg.shared.global [%0], [%1], 16;" :: "r"(dst), "l"(src));
}
#define CP_COMMIT() asm volatile("cp.async.commit_group;" ::: "memory")

__device__ __forceinline__ void ldm_x4(uint32_t* r, uint32_t addr) {
    asm volatile("ldmatrix.sync.aligned.m8n8.x4.shared.b16 {%0,%1,%2,%3}, [%4];"
                 : "=r"(r[0]), "=r"(r[1]), "=r"(r[2]), "=r"(r[3]) : "r"(addr));
}
__device__ __forceinline__ void mma16816(float* c, const uint32_t* a, const uint32_t* b) {
    asm volatile(
        "mma.sync.aligned.m16n8k16.row.col.f32.bf16.bf16.f32 "
        "{%0,%1,%2,%3}, {%4,%5,%6,%7}, {%8,%9}, {%0,%1,%2,%3};"
        : "+f"(c[0]), "+f"(c[1]), "+f"(c[2]), "+f"(c[3])
        : "r"(a[0]), "r"(a[1]), "r"(a[2]), "r"(a[3]), "r"(b[0]), "r"(b[1]));
}
__device__ __forceinline__ void split_bf16(float v, __nv_bfloat16& h, __nv_bfloat16& l) {
    h = __float2bfloat16(v);
    l = __float2bfloat16(v - __bfloat162float(h));
}
__device__ __forceinline__ uint32_t pck(__nv_bfloat16 a, __nv_bfloat16 b) {
    return (uint32_t)*(unsigned short*)&a | ((uint32_t)*(unsigned short*)&b << 16);
}

// ---------------- mlp1: 3 -> 64 (fp32 to g_fall + hi/lo planes) --------------
__global__ void __launch_bounds__(256) mlp1_kernel(const float* __restrict__ op,
                                                   const float* __restrict__ w1,
                                                   const float* __restrict__ b1) {
    __shared__ float sw[192];
    __shared__ float sb[64];
    int t = threadIdx.x;
    if (t < 192) sw[t] = w1[t];
    if (t < 64)  sb[t] = b1[t];
    __syncthreads();
    int pfl  = blockIdx.x * 8 + (t >> 5);
    int lane = t & 31;
    int b  = pfl >> 12;
    int pt = pfl & (NP - 1);
    float x = op[b * 3 * NP + 0 * NP + pt];
    float y = op[b * 3 * NP + 1 * NP + pt];
    float z = op[b * 3 * NP + 2 * NP + pt];
    float* dst = g_fall + (size_t)pfl * FDIM;
#pragma unroll
    for (int u = 0; u < 2; u++) {
        int c = lane + u * 32;
        float v = fmaf(sw[c*3+0], x, fmaf(sw[c*3+1], y, fmaf(sw[c*3+2], z, sb[c])));
        v = fmaxf(v, 0.0f);
        dst[c] = v;
        __nv_bfloat16 h, l; split_bf16(v, h, l);
        g_f1h[pfl * 64 + c] = h;
        g_f1l[pfl * 64 + c] = l;
    }
}

__global__ void gmax_zero_kernel() {
    int t = threadIdx.x + blockIdx.x * blockDim.x;
    if (t < BATCH * 256) g_gmax[t] = 0;
}

// ---------------- gemm1 bias: rb1 + global-feature contribution (fp32) -------
__global__ void __launch_bounds__(256) gbias_kernel(const float* __restrict__ r1,
                                                    const float* __restrict__ rb1) {
    int b = blockIdx.x, n = threadIdx.x;
    const float* wr = r1 + n * 707 + 451;
    float acc = rb1[n];
#pragma unroll 8
    for (int j = 0; j < 256; j++)
        acc = fmaf(wr[j], __int_as_float(g_gmax[b * 256 + j]), acc);
    g_b1[b * 256 + n] = acc;
}

// ---------------- single fused weight split (+pad, r1 remapped) --------------
// segments: w2 8192 | w3 32768 | r1 122880 | r2 32768 | r3 8192 = 204800
__global__ void __launch_bounds__(256) split_all_kernel(
    const float* __restrict__ w2, const float* __restrict__ w3,
    const float* __restrict__ r1, const float* __restrict__ r2,
    const float* __restrict__ r3) {
    int i = blockIdx.x * 256 + threadIdx.x;
    if (i >= 204800) return;
    float v = 0.0f;
    __nv_bfloat16 *hi, *lo; int off;
    if (i < 8192) {
        off = i; hi = g_w2h; lo = g_w2l;
        v = w2[off];
    } else if (i < 40960) {
        off = i - 8192; hi = g_w3h; lo = g_w3l;
        v = w3[off];
    } else if (i < 163840) {
        off = i - 40960; hi = g_r1h; lo = g_r1l;
        int r = off / AGK, k = off - r * AGK;
        if (k < 448)      v = r1[r * 707 + 3 + k];     // interp channels
        else if (k < 451) v = r1[r * 707 + (k - 448)]; // query coords
    } else if (i < 196608) {
        off = i - 163840; hi = g_r2h; lo = g_r2l;
        v = r2[off];
    } else {
        off = i - 196608; hi = g_r3h; lo = g_r3l;
        v = r3[off];
    }
    __nv_bfloat16 h, l; split_bf16(v, h, l);
    hi[off] = h; lo[off] = l;
}

// ---------------- KNN part 1: top-3 within one half of the points ------------
__global__ void __launch_bounds__(256) knn_part_kernel(const float* __restrict__ op,
                                                       const float* __restrict__ qp) {
    __shared__ float4 sp[NPH];            // 32 KB
    int b = blockIdx.y, half = blockIdx.z;
    int tid = threadIdx.x;
    int jbase = half * NPH;
    for (int i = tid; i < NPH; i += 256) {
        float x = op[b * 3 * NP + 0 * NP + jbase + i];
        float y = op[b * 3 * NP + 1 * NP + jbase + i];
        float z = op[b * 3 * NP + 2 * NP + jbase + i];
        sp[i] = make_float4(x, y, z, fmaf(x, x, fmaf(y, y, z * z)));
    }
    __syncthreads();

    int q = blockIdx.x * 256 + tid;
    float qx = qp[b * 3 * NQ + 0 * NQ + q];
    float qy = qp[b * 3 * NQ + 1 * NQ + q];
    float qz = qp[b * 3 * NQ + 2 * NQ + q];
    float nx = -2.0f * qx, ny = -2.0f * qy, nz = -2.0f * qz;

    float d0 = CUDART_INF_F, d1 = CUDART_INF_F, d2 = CUDART_INF_F;
    int i0 = 0, i1 = 0, i2 = 0;
#pragma unroll 8
    for (int j = 0; j < NPH; j++) {
        float4 o = sp[j];
        float d = fmaf(o.x, nx, fmaf(o.y, ny, fmaf(o.z, nz, o.w)));
        if (d < d2) {
            if (d < d1) {
                d2 = d1; i2 = i1;
                if (d < d0) { d1 = d0; i1 = i0; d0 = d; i0 = j; }
                else        { d1 = d;  i1 = j; }
            } else { d2 = d; i2 = j; }
        }
    }
    int base = ((b * NQ + q) * 2 + half) * 3;
    g_kcd[base + 0] = d0; g_kci[base + 0] = jbase + i0;
    g_kcd[base + 1] = d1; g_kci[base + 1] = jbase + i1;
    g_kcd[base + 2] = d2; g_kci[base + 2] = jbase + i2;
}

// ---------------- KNN part 2: merge halves, compute weights ------------------
__global__ void __launch_bounds__(256) knn_merge_kernel(const float* __restrict__ op,
                                                        const float* __restrict__ qp) {
    int i = blockIdx.x * 256 + threadIdx.x;   // 0..NPTS-1
    int b = i >> 14, q = i & (NQ - 1);
    float d0 = CUDART_INF_F, d1 = CUDART_INF_F, d2 = CUDART_INF_F;
    int i0 = 0, i1 = 0, i2 = 0;
#pragma unroll
    for (int c = 0; c < 6; c++) {
        float d = g_kcd[i * 6 + c];
        int   j = g_kci[i * 6 + c];
        if (d < d2) {
            if (d < d1) {
                d2 = d1; i2 = i1;
                if (d < d0) { d1 = d0; i1 = i0; d0 = d; i0 = j; }
                else        { d1 = d;  i1 = j; }
            } else { d2 = d; i2 = j; }
        }
    }
    float qx = qp[b * 3 * NQ + 0 * NQ + q];
    float qy = qp[b * 3 * NQ + 1 * NQ + q];
    float qz = qp[b * 3 * NQ + 2 * NQ + q];
    int   ii[3] = {i0, i1, i2};
    float rc[3];
    float s = 0.0f;
#pragma unroll
    for (int k = 0; k < 3; k++) {
        float dx = op[b * 3 * NP + 0 * NP + ii[k]] - qx;
        float dy = op[b * 3 * NP + 1 * NP + ii[k]] - qy;
        float dz = op[b * 3 * NP + 2 * NP + ii[k]] - qz;
        float dist = sqrtf(fmaf(dx, dx, fmaf(dy, dy, dz * dz)));
        rc[k] = 1.0f / (dist + 1e-8f);
        s += rc[k];
    }
    float inv = 1.0f / s;
#pragma unroll
    for (int k = 0; k < 3; k++) {
        g_knni[i * 3 + k] = ii[k];
        g_knnw[i * 3 + k] = rc[k] * inv;
    }
}

// ---------------- wide split-bf16 tensor GEMM: full N per CTA ----------------
#define PKB 80                       // smem row pitch bytes (32 bf16 + 16B pad)
#define APL (128 * PKB)              // A plane bytes (10240)

template <int BN, bool GMAX>
__global__ void __launch_bounds__(512) tgemm_wide(
    const __nv_bfloat16* __restrict__ Ahi, const __nv_bfloat16* __restrict__ Alo, int lda,
    const __nv_bfloat16* __restrict__ Whi, const __nv_bfloat16* __restrict__ Wlo,
    const float* __restrict__ bias, int K,
    float* __restrict__ f32out, int f32ld,
    __nv_bfloat16* __restrict__ phi, __nv_bfloat16* __restrict__ plo, int pld) {
    extern __shared__ char smem[];
    constexpr int WPL = BN * PKB;
    constexpr int SS  = 2 * APL + 2 * WPL;
    constexpr int NT8 = BN / 32;
    const int t = threadIdx.x;
    const int lane = t & 31, warp = t >> 5;
    const int wm = warp >> 2, wn = warp & 3;
    const int m0 = blockIdx.x * 128;
    const int ldw = K;

    float acc[2][NT8][4];
#pragma unroll
    for (int i = 0; i < 2; i++)
#pragma unroll
        for (int j = 0; j < NT8; j++)
#pragma unroll
            for (int v = 0; v < 4; v++) acc[i][j][v] = 0.0f;

    const int NC = K / 32;

    auto stage = [&](int buf, int c) {
        char* base = smem + buf * SS;
#pragma unroll
        for (int u = 0; u < 2; u++) {
            int e = t + u * 512;
            int pl = e >> 9, rem = e & 511;
            int row = rem >> 2, seg = rem & 3;
            const char* src = (const char*)(pl ? Alo : Ahi)
                + ((size_t)(m0 + row) * lda + c * 32) * 2 + seg * 16;
            cp16(smem_u32(base + pl * APL + row * PKB + seg * 16), src);
        }
#pragma unroll
        for (int u = 0; u < BN / 64; u++) {
            int e = t + u * 512;
            int pl = e / (BN * 4), rem = e % (BN * 4);
            int row = rem >> 2, seg = rem & 3;
            const char* src = (const char*)(pl ? Wlo : Whi)
                + ((size_t)row * ldw + c * 32) * 2 + seg * 16;
            cp16(smem_u32(base + 2 * APL + pl * WPL + row * PKB + seg * 16), src);
        }
        CP_COMMIT();
    };

    stage(0, 0);
    for (int c = 0; c < NC; c++) {
        if (c + 1 < NC) {
            stage((c + 1) & 1, c + 1);
            asm volatile("cp.async.wait_group 1;" ::: "memory");
        } else {
            asm volatile("cp.async.wait_group 0;" ::: "memory");
        }
        __syncthreads();
        char* base = smem + (c & 1) * SS;
#pragma unroll
        for (int kk = 0; kk < 2; kk++) {
            uint32_t afr[2][2][4];
#pragma unroll
            for (int pl = 0; pl < 2; pl++)
#pragma unroll
                for (int mt = 0; mt < 2; mt++) {
                    uint32_t a = smem_u32(base + pl * APL
                        + (wm * 32 + mt * 16 + (lane & 15)) * PKB
                        + (kk * 16 + (lane >> 4) * 8) * 2);
                    ldm_x4(afr[pl][mt], a);
                }
#pragma unroll
            for (int nt = 0; nt < NT8; nt++) {
                const char* bp = base + 2 * APL
                    + (wn * (BN / 4) + nt * 8 + (lane >> 2)) * PKB
                    + (kk * 16 + (lane & 3) * 2) * 2;
                uint32_t bh[2], bl[2];
                bh[0] = *(const uint32_t*)bp;
                bh[1] = *(const uint32_t*)(bp + 16);
                bl[0] = *(const uint32_t*)(bp + WPL);
                bl[1] = *(const uint32_t*)(bp + WPL + 16);
#pragma unroll
                for (int mt = 0; mt < 2; mt++) {
                    mma16816(acc[mt][nt], afr[0][mt], bh);
                    mma16816(acc[mt][nt], afr[0][mt], bl);
                    mma16816(acc[mt][nt], afr[1][mt], bh);
                }
            }
        }
        __syncthreads();
    }

#pragma unroll
    for (int mt = 0; mt < 2; mt++)
#pragma unroll
        for (int nt = 0; nt < NT8; nt++) {
            int row0 = m0 + wm * 32 + mt * 16 + (lane >> 2);
            int col = wn * (BN / 4) + nt * 8 + (lane & 3) * 2;
            float b0 = bias[col], b1 = bias[col + 1];
            float v0 = fmaxf(acc[mt][nt][0] + b0, 0.0f);
            float v1 = fmaxf(acc[mt][nt][1] + b1, 0.0f);
            float v2 = fmaxf(acc[mt][nt][2] + b0, 0.0f);
            float v3 = fmaxf(acc[mt][nt][3] + b1, 0.0f);
            if (f32out) {
                *(float2*)(f32out + (size_t)row0 * f32ld + col) = make_float2(v0, v1);
                *(float2*)(f32out + (size_t)(row0 + 8) * f32ld + col) = make_float2(v2, v3);
            }
            if (phi) {
                __nv_bfloat16 h0, l0, h1, l1;
                split_bf16(v0, h0, l0); split_bf16(v1, h1, l1);
                *(uint32_t*)((unsigned short*)phi + (size_t)row0 * pld + col) = pck(h0, h1);
                *(uint32_t*)((unsigned short*)plo + (size_t)row0 * pld + col) = pck(l0, l1);
                split_bf16(v2, h0, l0); split_bf16(v3, h1, l1);
                *(uint32_t*)((unsigned short*)phi + (size_t)(row0 + 8) * pld + col) = pck(h0, h1);
                *(uint32_t*)((unsigned short*)plo + (size_t)(row0 + 8) * pld + col) = pck(l0, l1);
            }
        }

    if (GMAX) {
        int b = m0 >> 12;
#pragma unroll
        for (int nt = 0; nt < NT8; nt++) {
            int col = wn * (BN / 4) + nt * 8 + (lane & 3) * 2;
            float b0 = bias[col], b1 = bias[col + 1];
            float mA = fmaxf(fmaxf(acc[0][nt][0], acc[0][nt][2]),
                             fmaxf(acc[1][nt][0], acc[1][nt][2])) + b0;
            float mB = fmaxf(fmaxf(acc[0][nt][1], acc[0][nt][3]),
                             fmaxf(acc[1][nt][1], acc[1][nt][3])) + b1;
            mA = fmaxf(mA, 0.0f); mB = fmaxf(mB, 0.0f);
#pragma unroll
            for (int o = 4; o < 32; o <<= 1) {
                mA = fmaxf(mA, __shfl_xor_sync(0xffffffffu, mA, o));
                mB = fmaxf(mB, __shfl_xor_sync(0xffffffffu, mB, o));
            }
            if ((lane >> 2) == 0) {
                atomicMax(&g_gmax[b * 256 + col],     __float_as_int(mA));
                atomicMax(&g_gmax[b * 256 + col + 1], __float_as_int(mB));
            }
        }
    }
}

// ---------------- gemm1: fused interpolation staging, K=480 ------------------
// A cols: [0:448) interp | 448..450 query | rest 0.  Bias = g_b1 (incl global).
__global__ void __launch_bounds__(512) tgemm_g1(
    const float* __restrict__ fall, const float* __restrict__ qp,
    const __nv_bfloat16* __restrict__ Whi, const __nv_bfloat16* __restrict__ Wlo,
    __nv_bfloat16* __restrict__ phi, __nv_bfloat16* __restrict__ plo) {
    constexpr int BN = 256, K = AGK, NC = K / 32, NT8 = BN / 32;
    constexpr int WPL = BN * PKB;
    constexpr int SS  = 2 * APL + 2 * WPL;
    extern __shared__ char smem[];
    int*   si  = (int*)(smem + 2 * SS);            // [128*3]
    float* swt = (float*)(smem + 2 * SS + 1536);   // [128*3]
    const int t = threadIdx.x;
    const int lane = t & 31, warp = t >> 5;
    const int wm = warp >> 2, wn = warp & 3;
    const int m0 = blockIdx.x * 128;
    const int b  = m0 >> 14;

    if (t < 128) {
#pragma unroll
        for (int j = 0; j < 3; j++) {
            si[t * 3 + j]  = g_knni[(m0 + t) * 3 + j];
            swt[t * 3 + j] = g_knnw[(m0 + t) * 3 + j];
        }
    }
    __syncthreads();

    float acc[2][NT8][4];
#pragma unroll
    for (int i = 0; i < 2; i++)
#pragma unroll
        for (int j = 0; j < NT8; j++)
#pragma unroll
            for (int v = 0; v < 4; v++) acc[i][j][v] = 0.0f;

    auto stageW = [&](int buf, int c) {
        char* base = smem + buf * SS;
#pragma unroll
        for (int u = 0; u < 4; u++) {
            int e = t + u * 512;
            int pl = e >> 10, rem = e & 1023;
            int row = rem >> 2, seg = rem & 3;
            const char* src = (const char*)(pl ? Wlo : Whi)
                + ((size_t)row * K + c * 32) * 2 + seg * 16;
            cp16(smem_u32(base + 2 * APL + pl * WPL + row * PKB + seg * 16), src);
        }
        CP_COMMIT();
    };

    auto stageA = [&](char* base, int c) {
        const int ch0 = c * 32;
#pragma unroll
        for (int u = 0; u < 2; u++) {
            int e = t + u * 512;
            int row = e >> 3, c4 = e & 7;
            int ch = ch0 + c4 * 4;
            float v0, v1, v2, v3;
            if (ch < 448) {
                const float* fr = fall + (size_t)(b * NP) * FDIM + ch;
                float4 A = *(const float4*)(fr + (size_t)si[row * 3 + 0] * FDIM);
                float4 B = *(const float4*)(fr + (size_t)si[row * 3 + 1] * FDIM);
                float4 C = *(const float4*)(fr + (size_t)si[row * 3 + 2] * FDIM);
                float wa = swt[row * 3 + 0], wb = swt[row * 3 + 1], wc = swt[row * 3 + 2];
                v0 = wa * A.x + wb * B.x + wc * C.x;
                v1 = wa * A.y + wb * B.y + wc * C.y;
                v2 = wa * A.z + wb * B.z + wc * C.z;
                v3 = wa * A.w + wb * B.w + wc * C.w;
            } else if (ch == 448) {
                int qi = (m0 + row) & (NQ - 1);
                v0 = qp[b * 3 * NQ + 0 * NQ + qi];
                v1 = qp[b * 3 * NQ + 1 * NQ + qi];
                v2 = qp[b * 3 * NQ + 2 * NQ + qi];
                v3 = 0.0f;
            } else {
                v0 = v1 = v2 = v3 = 0.0f;
            }
            __nv_bfloat16 h0, l0, h1, l1, h2, l2, h3, l3;
            split_bf16(v0, h0, l0); split_bf16(v1, h1, l1);
            split_bf16(v2, h2, l2); split_bf16(v3, h3, l3);
            int off = row * PKB + (c4 >> 1) * 16 + (c4 & 1) * 8;
            *(uint2*)(base + off)       = make_uint2(pck(h0, h1), pck(h2, h3));
            *(uint2*)(base + APL + off) = make_uint2(pck(l0, l1), pck(l2, l3));
        }
    };

    stageW(0, 0);
    for (int c = 0; c < NC; c++) {
        char* base = smem + (c & 1) * SS;
        stageA(base, c);
        if (c + 1 < NC) {
            stageW((c + 1) & 1, c + 1);
            asm volatile("cp.async.wait_group 1;" ::: "memory");
        } else {
            asm volatile("cp.async.wait_group 0;" ::: "memory");
        }
        __syncthreads();
#pragma unroll
        for (int kk = 0; kk < 2; kk++) {
            uint32_t afr[2][2][4];
#pragma unroll
            for (int pl = 0; pl < 2; pl++)
#pragma unroll
                for (int mt = 0; mt < 2; mt++) {
                    uint32_t a = smem_u32(base + pl * APL
                        + (wm * 32 + mt * 16 + (lane & 15)) * PKB
                        + (kk * 16 + (lane >> 4) * 8) * 2);
                    ldm_x4(afr[pl][mt], a);
                }
#pragma unroll
            for (int nt = 0; nt < NT8; nt++) {
                const char* bp = base + 2 * APL
                    + (wn * (BN / 4) + nt * 8 + (lane >> 2)) * PKB
                    + (kk * 16 + (lane & 3) * 2) * 2;
                uint32_t bh[2], bl[2];
                bh[0] = *(const uint32_t*)bp;
                bh[1] = *(const uint32_t*)(bp + 16);
                bl[0] = *(const uint32_t*)(bp + WPL);
                bl[1] = *(const uint32_t*)(bp + WPL + 16);
#pragma unroll
                for (int mt = 0; mt < 2; mt++) {
                    mma16816(acc[mt][nt], afr[0][mt], bh);
                    mma16816(acc[mt][nt], afr[0][mt], bl);
                    mma16816(acc[mt][nt], afr[1][mt], bh);
                }
            }
        }
        __syncthreads();
    }

    const float* bias = g_b1 + b * 256;
#pragma unroll
    for (int mt = 0; mt < 2; mt++)
#pragma unroll
        for (int nt = 0; nt < NT8; nt++) {
            int row0 = m0 + wm * 32 + mt * 16 + (lane >> 2);
            int col = wn * (BN / 4) + nt * 8 + (lane & 3) * 2;
            float b0 = bias[col], b1 = bias[col + 1];
            float v0 = fmaxf(acc[mt][nt][0] + b0, 0.0f);
            float v1 = fmaxf(acc[mt][nt][1] + b1, 0.0f);
            float v2 = fmaxf(acc[mt][nt][2] + b0, 0.0f);
            float v3 = fmaxf(acc[mt][nt][3] + b1, 0.0f);
            __nv_bfloat16 h0, l0, h1, l1;
            split_bf16(v0, h0, l0); split_bf16(v1, h1, l1);
            *(uint32_t*)((unsigned short*)phi + (size_t)row0 * 256 + col) = pck(h0, h1);
            *(uint32_t*)((unsigned short*)plo + (size_t)row0 * 256 + col) = pck(l0, l1);
            split_bf16(v2, h0, l0); split_bf16(v3, h1, l1);
            *(uint32_t*)((unsigned short*)phi + (size_t)(row0 + 8) * 256 + col) = pck(h0, h1);
            *(uint32_t*)((unsigned short*)plo + (size_t)(row0 + 8) * 256 + col) = pck(l0, l1);
        }
}

// ---------------- narrow GEMM with fused final 64->1 (validated) -------------
#define WPLN (64 * PKB)
#define GBUF (2 * APL + 2 * WPLN)

__global__ void __launch_bounds__(256) tgemm_fin(
    const __nv_bfloat16* __restrict__ Ahi, const __nv_bfloat16* __restrict__ Alo, int lda,
    const __nv_bfloat16* __restrict__ Whi, const __nv_bfloat16* __restrict__ Wlo, int ldw,
    const float* __restrict__ bias, int K,
    const float* __restrict__ r4, const float* __restrict__ rb4,
    float* __restrict__ finout) {
    extern __shared__ char smem[];
    const int t = threadIdx.x;
    const int lane = t & 31, warp = t >> 5;
    const int wm = warp >> 1, wn = warp & 1;
    const int m0 = blockIdx.y * 128;

    float acc[2][4][4];
#pragma unroll
    for (int i = 0; i < 2; i++)
#pragma unroll
        for (int j = 0; j < 4; j++)
#pragma unroll
            for (int v = 0; v < 4; v++) acc[i][j][v] = 0.0f;

    const int NC = K / 32;

    auto stage = [&](int buf, int c) {
        char* base = smem + buf * GBUF;
#pragma unroll
        for (int u = 0; u < 4; u++) {
            int e = t + u * 256;
            int pl = e >> 9, rem = e & 511;
            int row = rem >> 2, seg = rem & 3;
            const char* src = (const char*)(pl ? Alo : Ahi)
                + ((size_t)(m0 + row) * lda + c * 32) * 2 + seg * 16;
            cp16(smem_u32(base + pl * APL + row * PKB + seg * 16), src);
        }
#pragma unroll
        for (int u = 0; u < 2; u++) {
            int e = t + u * 256;
            int pl = e >> 8, rem = e & 255;
            int row = rem >> 2, seg = rem & 3;
            const char* src = (const char*)(pl ? Wlo : Whi)
                + ((size_t)row * ldw + c * 32) * 2 + seg * 16;
            cp16(smem_u32(base + 2 * APL + pl * WPLN + row * PKB + seg * 16), src);
        }
        CP_COMMIT();
    };

    stage(0, 0);
    for (int c = 0; c < NC; c++) {
        if (c + 1 < NC) {
            stage((c + 1) & 1, c + 1);
            asm volatile("cp.async.wait_group 1;" ::: "memory");
        } else {
            asm volatile("cp.async.wait_group 0;" ::: "memory");
        }
        __syncthreads();
        char* base = smem + (c & 1) * GBUF;
#pragma unroll
        for (int kk = 0; kk < 2; kk++) {
            uint32_t afr[2][2][4];
#pragma unroll
            for (int pl = 0; pl < 2; pl++)
#pragma unroll
                for (int mt = 0; mt < 2; mt++) {
                    uint32_t a = smem_u32(base + pl * APL
                        + (wm * 32 + mt * 16 + (lane & 15)) * PKB
                        + (kk * 16 + (lane >> 4) * 8) * 2);
                    ldm_x4(afr[pl][mt], a);
                }
#pragma unroll
            for (int nt = 0; nt < 4; nt++) {
                const char* bp = base + 2 * APL
                    + (wn * 32 + nt * 8 + (lane >> 2)) * PKB
                    + (kk * 16 + (lane & 3) * 2) * 2;
                uint32_t bh[2], bl[2];
                bh[0] = *(const uint32_t*)bp;
                bh[1] = *(const uint32_t*)(bp + 16);
                bl[0] = *(const uint32_t*)(bp + WPLN);
                bl[1] = *(const uint32_t*)(bp + WPLN + 16);
#pragma unroll
                for (int mt = 0; mt < 2; mt++) {
                    mma16816(acc[mt][nt], afr[0][mt], bh);
                    mma16816(acc[mt][nt], afr[0][mt], bl);
                    mma16816(acc[mt][nt], afr[1][mt], bh);
                }
            }
        }
        __syncthreads();
    }

    float part[2][2] = {{0.0f, 0.0f}, {0.0f, 0.0f}};
#pragma unroll
    for (int mt = 0; mt < 2; mt++)
#pragma unroll
        for (int nt = 0; nt < 4; nt++) {
            int col = wn * 32 + nt * 8 + (lane & 3) * 2;
            float b0 = bias[col], b1 = bias[col + 1];
            float r0 = r4[col], r1 = r4[col + 1];
            part[mt][0] += fmaxf(acc[mt][nt][0] + b0, 0.0f) * r0
                         + fmaxf(acc[mt][nt][1] + b1, 0.0f) * r1;
            part[mt][1] += fmaxf(acc[mt][nt][2] + b0, 0.0f) * r0
                         + fmaxf(acc[mt][nt][3] + b1, 0.0f) * r1;
        }
    float* sp = (float*)smem;
#pragma unroll
    for (int mt = 0; mt < 2; mt++)
#pragma unroll
        for (int h = 0; h < 2; h++) {
            float v = part[mt][h];
            v += __shfl_xor_sync(0xffffffffu, v, 1);
            v += __shfl_xor_sync(0xffffffffu, v, 2);
            if ((lane & 3) == 0)
                sp[(wm * 32 + mt * 16 + h * 8 + (lane >> 2)) * 2 + wn] = v;
        }
    __syncthreads();
    if (t < 128) finout[m0 + t] = sp[t * 2] + sp[t * 2 + 1] + rb4[0];
}

// ---------------- launch -----------------------------------------------------
extern "C" void kernel_launch(void* const* d_in, const int* in_sizes, int n_in,
                              void* d_out, int out_size) {
    const float* op  = (const float*)d_in[0];
    const float* qp  = (const float*)d_in[1];
    const float* w1  = (const float*)d_in[2];
    const float* b1  = (const float*)d_in[3];
    const float* w2  = (const float*)d_in[4];
    const float* b2  = (const float*)d_in[5];
    const float* w3  = (const float*)d_in[6];
    const float* b3  = (const float*)d_in[7];
    const float* r1  = (const float*)d_in[8];
    const float* rb1 = (const float*)d_in[9];
    const float* r2  = (const float*)d_in[10];
    const float* rb2 = (const float*)d_in[11];
    const float* r3  = (const float*)d_in[12];
    const float* rb3 = (const float*)d_in[13];
    const float* r4  = (const float*)d_in[14];
    const float* rb4 = (const float*)d_in[15];
    float* out = (float*)d_out;

    float* p_fall;
    cudaGetSymbolAddress((void**)&p_fall, g_fall);
    __nv_bfloat16 *f1h, *f1l, *f2h, *f2l, *h1h, *h1l, *h2h, *h2l;
    __nv_bfloat16 *w2h, *w2l, *w3h, *w3l, *r1h, *r1l, *r2h, *r2l, *r3h, *r3l;
    cudaGetSymbolAddress((void**)&f1h, g_f1h);  cudaGetSymbolAddress((void**)&f1l, g_f1l);
    cudaGetSymbolAddress((void**)&f2h, g_f2h);  cudaGetSymbolAddress((void**)&f2l, g_f2l);
    cudaGetSymbolAddress((void**)&h1h, g_h1h);  cudaGetSymbolAddress((void**)&h1l, g_h1l);
    cudaGetSymbolAddress((void**)&h2h, g_h2h);  cudaGetSymbolAddress((void**)&h2l, g_h2l);
    cudaGetSymbolAddress((void**)&w2h, g_w2h);  cudaGetSymbolAddress((void**)&w2l, g_w2l);
    cudaGetSymbolAddress((void**)&w3h, g_w3h);  cudaGetSymbolAddress((void**)&w3l, g_w3l);
    cudaGetSymbolAddress((void**)&r1h, g_r1h);  cudaGetSymbolAddress((void**)&r1l, g_r1l);
    cudaGetSymbolAddress((void**)&r2h, g_r2h);  cudaGetSymbolAddress((void**)&r2l, g_r2l);
    cudaGetSymbolAddress((void**)&r3h, g_r3h);  cudaGetSymbolAddress((void**)&r3l, g_r3l);

    constexpr int SM256 = 2 * (2 * APL + 2 * 256 * PKB);   // 122880
    constexpr int SM128 = 2 * (2 * APL + 2 * 128 * PKB);   // 81920
    constexpr int SMG1  = SM256 + 3072;
    cudaFuncSetAttribute(tgemm_wide<256, true>,  cudaFuncAttributeMaxDynamicSharedMemorySize, SM256);
    cudaFuncSetAttribute(tgemm_wide<128, false>, cudaFuncAttributeMaxDynamicSharedMemorySize, SM128);
    cudaFuncSetAttribute(tgemm_g1, cudaFuncAttributeMaxDynamicSharedMemorySize, SMG1);
    cudaFuncSetAttribute(tgemm_fin, cudaFuncAttributeMaxDynamicSharedMemorySize, 2 * GBUF);

    split_all_kernel<<<800, 256>>>(w2, w3, r1, r2, r3);
    gmax_zero_kernel<<<2, 256>>>();
    mlp1_kernel<<<MPTS / 8, 256>>>(op, w1, b1);
    // mlp2 64->128
    tgemm_wide<128, false><<<MPTS / 128, 512, SM128>>>(
        f1h, f1l, 64, w2h, w2l, b2, 64,
        p_fall + 64, FDIM, f2h, f2l, 128);
    // mlp3 128->256 + fused gmax
    tgemm_wide<256, true><<<MPTS / 128, 512, SM256>>>(
        f2h, f2l, 128, w3h, w3l, b3, 128,
        p_fall + 192, FDIM, nullptr, nullptr, 0);
    // gemm1 bias (rb1 + global-feature fold, fp32 exact)
    gbias_kernel<<<BATCH, 256>>>(r1, rb1);
    // knn: split halves + merge
    knn_part_kernel<<<dim3(NQ / 256, BATCH, 2), 256>>>(op, qp);
    knn_merge_kernel<<<NPTS / 256, 256>>>(op, qp);
    // gemm1 480->256 with fused interpolation staging
    tgemm_g1<<<NPTS / 128, 512, SMG1>>>(p_fall, qp, r1h, r1l, h1h, h1l);
    // gemm2 256->128
    tgemm_wide<128, false><<<NPTS / 128, 512, SM128>>>(
        h1h, h1l, 256, r2h, r2l, rb2, 256,
        nullptr, 0, h2h, h2l, 128);
    // gemm3 128->64 + fused final 64->1
    tgemm_fin<<<dim3(1, NPTS / 128), 256, 2 * GBUF>>>(
        h2h, h2l, 128, r3h, r3l, 128, rb3, 128, r4, rb4, out);
}

// round 9
// speedup vs baseline: 3.9105x; 1.0396x over previous
#include <cuda_runtime.h>
#include <cuda_bf16.h>
#include <math_constants.h>
#include <cstdint>

#define BATCH 2
#define NP    4096
#define NPH   2048           // half of NP (knn split)
#define NQ    16384
#define FDIM  448            // 64 + 128 + 256
#define AGK   480            // gemm1 K: 448 interp + 3 query + 29 pad
#define NPTS  (BATCH * NQ)   // 32768 query points
#define MPTS  (BATCH * NP)   // 8192 original points

// ---------------- scratch (device globals; no allocation allowed) -----------
__device__ float g_fall[MPTS * FDIM];          // point-major fp32 (f1|f2|f3)
__device__ int   g_gmax[BATCH * 256];
__device__ float g_b1[BATCH * 256];            // gemm1 bias incl. global feats
__device__ int   g_knni[NPTS * 3];
__device__ float g_knnw[NPTS * 3];
__device__ float g_kcd[NPTS * 6];              // knn candidates (2 halves x 3)
__device__ int   g_kci[NPTS * 6];
__device__ __nv_bfloat16 g_f1h[MPTS * 64],   g_f1l[MPTS * 64];
__device__ __nv_bfloat16 g_f2h[MPTS * 128],  g_f2l[MPTS * 128];
__device__ __nv_bfloat16 g_h1h[(size_t)NPTS * 256],   g_h1l[(size_t)NPTS * 256];
__device__ __nv_bfloat16 g_w2h[128 * 64],   g_w2l[128 * 64];
__device__ __nv_bfloat16 g_w3h[256 * 128],  g_w3l[256 * 128];
__device__ __nv_bfloat16 g_r1h[256 * AGK],  g_r1l[256 * AGK];   // remapped cols
__device__ __nv_bfloat16 g_r2h[128 * 256],  g_r2l[128 * 256];
__device__ __nv_bfloat16 g_r3h[64 * 128],   g_r3l[64 * 128];

// ---------------- helpers -----------------------------------------------------
__device__ __forceinline__ uint32_t smem_u32(const void* p) {
    uint32_t a;
    asm("{ .reg .u64 t; cvta.to.shared.u64 t, %1; cvt.u32.u64 %0, t; }" : "=r"(a) : "l"(p));
    return a;
}
__device__ __forceinline__ void cp16(uint32_t dst, const void* src) {
    asm volatile("cp.async.cg.shared.global [%0], [%1], 16;" :: "r"(dst), "l"(src));
}
#define CP_COMMIT() asm volatile("cp.async.commit_group;" ::: "memory")

__device__ __forceinline__ void ldm_x4(uint32_t* r, uint32_t addr) {
    asm volatile("ldmatrix.sync.aligned.m8n8.x4.shared.b16 {%0,%1,%2,%3}, [%4];"
                 : "=r"(r[0]), "=r"(r[1]), "=r"(r[2]), "=r"(r[3]) : "r"(addr));
}
__device__ __forceinline__ void mma16816(float* c, const uint32_t* a, const uint32_t* b) {
    asm volatile(
        "mma.sync.aligned.m16n8k16.row.col.f32.bf16.bf16.f32 "
        "{%0,%1,%2,%3}, {%4,%5,%6,%7}, {%8,%9}, {%0,%1,%2,%3};"
        : "+f"(c[0]), "+f"(c[1]), "+f"(c[2]), "+f"(c[3])
        : "r"(a[0]), "r"(a[1]), "r"(a[2]), "r"(a[3]), "r"(b[0]), "r"(b[1]));
}
__device__ __forceinline__ void split_bf16(float v, __nv_bfloat16& h, __nv_bfloat16& l) {
    h = __float2bfloat16(v);
    l = __float2bfloat16(v - __bfloat162float(h));
}
__device__ __forceinline__ uint32_t pck(__nv_bfloat16 a, __nv_bfloat16 b) {
    return (uint32_t)*(unsigned short*)&a | ((uint32_t)*(unsigned short*)&b << 16);
}

// ---------------- mlp1: 3 -> 64 (fp32 to g_fall + hi/lo planes) --------------
__global__ void __launch_bounds__(256) mlp1_kernel(const float* __restrict__ op,
                                                   const float* __restrict__ w1,
                                                   const float* __restrict__ b1) {
    __shared__ float sw[192];
    __shared__ float sb[64];
    int t = threadIdx.x;
    if (t < 192) sw[t] = w1[t];
    if (t < 64)  sb[t] = b1[t];
    __syncthreads();
    int pfl  = blockIdx.x * 8 + (t >> 5);
    int lane = t & 31;
    int b  = pfl >> 12;
    int pt = pfl & (NP - 1);
    float x = op[b * 3 * NP + 0 * NP + pt];
    float y = op[b * 3 * NP + 1 * NP + pt];
    float z = op[b * 3 * NP + 2 * NP + pt];
    float* dst = g_fall + (size_t)pfl * FDIM;
#pragma unroll
    for (int u = 0; u < 2; u++) {
        int c = lane + u * 32;
        float v = fmaf(sw[c*3+0], x, fmaf(sw[c*3+1], y, fmaf(sw[c*3+2], z, sb[c])));
        v = fmaxf(v, 0.0f);
        dst[c] = v;
        __nv_bfloat16 h, l; split_bf16(v, h, l);
        g_f1h[pfl * 64 + c] = h;
        g_f1l[pfl * 64 + c] = l;
    }
}

__global__ void gmax_zero_kernel() {
    int t = threadIdx.x + blockIdx.x * blockDim.x;
    if (t < BATCH * 256) g_gmax[t] = 0;
}

// ---------------- gemm1 bias: rb1 + global-feature contribution (fp32) -------
__global__ void __launch_bounds__(256) gbias_kernel(const float* __restrict__ r1,
                                                    const float* __restrict__ rb1) {
    int b = blockIdx.x, n = threadIdx.x;
    const float* wr = r1 + n * 707 + 451;
    float acc = rb1[n];
#pragma unroll 8
    for (int j = 0; j < 256; j++)
        acc = fmaf(wr[j], __int_as_float(g_gmax[b * 256 + j]), acc);
    g_b1[b * 256 + n] = acc;
}

// ---------------- single fused weight split (+pad, r1 remapped) --------------
__global__ void __launch_bounds__(256) split_all_kernel(
    const float* __restrict__ w2, const float* __restrict__ w3,
    const float* __restrict__ r1, const float* __restrict__ r2,
    const float* __restrict__ r3) {
    int i = blockIdx.x * 256 + threadIdx.x;
    if (i >= 204800) return;
    float v = 0.0f;
    __nv_bfloat16 *hi, *lo; int off;
    if (i < 8192) {
        off = i; hi = g_w2h; lo = g_w2l;
        v = w2[off];
    } else if (i < 40960) {
        off = i - 8192; hi = g_w3h; lo = g_w3l;
        v = w3[off];
    } else if (i < 163840) {
        off = i - 40960; hi = g_r1h; lo = g_r1l;
        int r = off / AGK, k = off - r * AGK;
        if (k < 448)      v = r1[r * 707 + 3 + k];     // interp channels
        else if (k < 451) v = r1[r * 707 + (k - 448)]; // query coords
    } else if (i < 196608) {
        off = i - 163840; hi = g_r2h; lo = g_r2l;
        v = r2[off];
    } else {
        off = i - 196608; hi = g_r3h; lo = g_r3l;
        v = r3[off];
    }
    __nv_bfloat16 h, l; split_bf16(v, h, l);
    hi[off] = h; lo[off] = l;
}

// ---------------- KNN part 1: top-3 within one half of the points ------------
__global__ void __launch_bounds__(256) knn_part_kernel(const float* __restrict__ op,
                                                       const float* __restrict__ qp) {
    __shared__ float4 sp[NPH];            // 32 KB
    int b = blockIdx.y, half = blockIdx.z;
    int tid = threadIdx.x;
    int jbase = half * NPH;
    for (int i = tid; i < NPH; i += 256) {
        float x = op[b * 3 * NP + 0 * NP + jbase + i];
        float y = op[b * 3 * NP + 1 * NP + jbase + i];
        float z = op[b * 3 * NP + 2 * NP + jbase + i];
        sp[i] = make_float4(x, y, z, fmaf(x, x, fmaf(y, y, z * z)));
    }
    __syncthreads();

    int q = blockIdx.x * 256 + tid;
    float qx = qp[b * 3 * NQ + 0 * NQ + q];
    float qy = qp[b * 3 * NQ + 1 * NQ + q];
    float qz = qp[b * 3 * NQ + 2 * NQ + q];
    float nx = -2.0f * qx, ny = -2.0f * qy, nz = -2.0f * qz;

    float d0 = CUDART_INF_F, d1 = CUDART_INF_F, d2 = CUDART_INF_F;
    int i0 = 0, i1 = 0, i2 = 0;
#pragma unroll 8
    for (int j = 0; j < NPH; j++) {
        float4 o = sp[j];
        float d = fmaf(o.x, nx, fmaf(o.y, ny, fmaf(o.z, nz, o.w)));
        if (d < d2) {
            if (d < d1) {
                d2 = d1; i2 = i1;
                if (d < d0) { d1 = d0; i1 = i0; d0 = d; i0 = j; }
                else        { d1 = d;  i1 = j; }
            } else { d2 = d; i2 = j; }
        }
    }
    int base = ((b * NQ + q) * 2 + half) * 3;
    g_kcd[base + 0] = d0; g_kci[base + 0] = jbase + i0;
    g_kcd[base + 1] = d1; g_kci[base + 1] = jbase + i1;
    g_kcd[base + 2] = d2; g_kci[base + 2] = jbase + i2;
}

// ---------------- KNN part 2: merge halves, compute weights ------------------
__global__ void __launch_bounds__(256) knn_merge_kernel(const float* __restrict__ op,
                                                        const float* __restrict__ qp) {
    int i = blockIdx.x * 256 + threadIdx.x;   // 0..NPTS-1
    int b = i >> 14, q = i & (NQ - 1);
    float d0 = CUDART_INF_F, d1 = CUDART_INF_F, d2 = CUDART_INF_F;
    int i0 = 0, i1 = 0, i2 = 0;
#pragma unroll
    for (int c = 0; c < 6; c++) {
        float d = g_kcd[i * 6 + c];
        int   j = g_kci[i * 6 + c];
        if (d < d2) {
            if (d < d1) {
                d2 = d1; i2 = i1;
                if (d < d0) { d1 = d0; i1 = i0; d0 = d; i0 = j; }
                else        { d1 = d;  i1 = j; }
            } else { d2 = d; i2 = j; }
        }
    }
    float qx = qp[b * 3 * NQ + 0 * NQ + q];
    float qy = qp[b * 3 * NQ + 1 * NQ + q];
    float qz = qp[b * 3 * NQ + 2 * NQ + q];
    int   ii[3] = {i0, i1, i2};
    float rc[3];
    float s = 0.0f;
#pragma unroll
    for (int k = 0; k < 3; k++) {
        float dx = op[b * 3 * NP + 0 * NP + ii[k]] - qx;
        float dy = op[b * 3 * NP + 1 * NP + ii[k]] - qy;
        float dz = op[b * 3 * NP + 2 * NP + ii[k]] - qz;
        float dist = sqrtf(fmaf(dx, dx, fmaf(dy, dy, dz * dz)));
        rc[k] = 1.0f / (dist + 1e-8f);
        s += rc[k];
    }
    float inv = 1.0f / s;
#pragma unroll
    for (int k = 0; k < 3; k++) {
        g_knni[i * 3 + k] = ii[k];
        g_knnw[i * 3 + k] = rc[k] * inv;
    }
}

// ---------------- wide split-bf16 tensor GEMM: full N per CTA ----------------
#define PKB 80                       // smem row pitch bytes (32 bf16 + 16B pad)
#define APL (128 * PKB)              // A plane bytes (10240)

template <int BN, bool GMAX>
__global__ void __launch_bounds__(512) tgemm_wide(
    const __nv_bfloat16* __restrict__ Ahi, const __nv_bfloat16* __restrict__ Alo, int lda,
    const __nv_bfloat16* __restrict__ Whi, const __nv_bfloat16* __restrict__ Wlo,
    const float* __restrict__ bias, int K,
    float* __restrict__ f32out, int f32ld,
    __nv_bfloat16* __restrict__ phi, __nv_bfloat16* __restrict__ plo, int pld) {
    extern __shared__ char smem[];
    constexpr int WPL = BN * PKB;
    constexpr int SS  = 2 * APL + 2 * WPL;
    constexpr int NT8 = BN / 32;
    const int t = threadIdx.x;
    const int lane = t & 31, warp = t >> 5;
    const int wm = warp >> 2, wn = warp & 3;
    const int m0 = blockIdx.x * 128;
    const int ldw = K;

    float acc[2][NT8][4];
#pragma unroll
    for (int i = 0; i < 2; i++)
#pragma unroll
        for (int j = 0; j < NT8; j++)
#pragma unroll
            for (int v = 0; v < 4; v++) acc[i][j][v] = 0.0f;

    const int NC = K / 32;

    auto stage = [&](int buf, int c) {
        char* base = smem + buf * SS;
#pragma unroll
        for (int u = 0; u < 2; u++) {
            int e = t + u * 512;
            int pl = e >> 9, rem = e & 511;
            int row = rem >> 2, seg = rem & 3;
            const char* src = (const char*)(pl ? Alo : Ahi)
                + ((size_t)(m0 + row) * lda + c * 32) * 2 + seg * 16;
            cp16(smem_u32(base + pl * APL + row * PKB + seg * 16), src);
        }
#pragma unroll
        for (int u = 0; u < BN / 64; u++) {
            int e = t + u * 512;
            int pl = e / (BN * 4), rem = e % (BN * 4);
            int row = rem >> 2, seg = rem & 3;
            const char* src = (const char*)(pl ? Wlo : Whi)
                + ((size_t)row * ldw + c * 32) * 2 + seg * 16;
            cp16(smem_u32(base + 2 * APL + pl * WPL + row * PKB + seg * 16), src);
        }
        CP_COMMIT();
    };

    stage(0, 0);
    for (int c = 0; c < NC; c++) {
        if (c + 1 < NC) {
            stage((c + 1) & 1, c + 1);
            asm volatile("cp.async.wait_group 1;" ::: "memory");
        } else {
            asm volatile("cp.async.wait_group 0;" ::: "memory");
        }
        __syncthreads();
        char* base = smem + (c & 1) * SS;
#pragma unroll
        for (int kk = 0; kk < 2; kk++) {
            uint32_t afr[2][2][4];
#pragma unroll
            for (int pl = 0; pl < 2; pl++)
#pragma unroll
                for (int mt = 0; mt < 2; mt++) {
                    uint32_t a = smem_u32(base + pl * APL
                        + (wm * 32 + mt * 16 + (lane & 15)) * PKB
                        + (kk * 16 + (lane >> 4) * 8) * 2);
                    ldm_x4(afr[pl][mt], a);
                }
#pragma unroll
            for (int nt = 0; nt < NT8; nt++) {
                const char* bp = base + 2 * APL
                    + (wn * (BN / 4) + nt * 8 + (lane >> 2)) * PKB
                    + (kk * 16 + (lane & 3) * 2) * 2;
                uint32_t bh[2], bl[2];
                bh[0] = *(const uint32_t*)bp;
                bh[1] = *(const uint32_t*)(bp + 16);
                bl[0] = *(const uint32_t*)(bp + WPL);
                bl[1] = *(const uint32_t*)(bp + WPL + 16);
#pragma unroll
                for (int mt = 0; mt < 2; mt++) {
                    mma16816(acc[mt][nt], afr[0][mt], bh);
                    mma16816(acc[mt][nt], afr[0][mt], bl);
                    mma16816(acc[mt][nt], afr[1][mt], bh);
                }
            }
        }
        __syncthreads();
    }

#pragma unroll
    for (int mt = 0; mt < 2; mt++)
#pragma unroll
        for (int nt = 0; nt < NT8; nt++) {
            int row0 = m0 + wm * 32 + mt * 16 + (lane >> 2);
            int col = wn * (BN / 4) + nt * 8 + (lane & 3) * 2;
            float b0 = bias[col], b1 = bias[col + 1];
            float v0 = fmaxf(acc[mt][nt][0] + b0, 0.0f);
            float v1 = fmaxf(acc[mt][nt][1] + b1, 0.0f);
            float v2 = fmaxf(acc[mt][nt][2] + b0, 0.0f);
            float v3 = fmaxf(acc[mt][nt][3] + b1, 0.0f);
            if (f32out) {
                *(float2*)(f32out + (size_t)row0 * f32ld + col) = make_float2(v0, v1);
                *(float2*)(f32out + (size_t)(row0 + 8) * f32ld + col) = make_float2(v2, v3);
            }
            if (phi) {
                __nv_bfloat16 h0, l0, h1, l1;
                split_bf16(v0, h0, l0); split_bf16(v1, h1, l1);
                *(uint32_t*)((unsigned short*)phi + (size_t)row0 * pld + col) = pck(h0, h1);
                *(uint32_t*)((unsigned short*)plo + (size_t)row0 * pld + col) = pck(l0, l1);
                split_bf16(v2, h0, l0); split_bf16(v3, h1, l1);
                *(uint32_t*)((unsigned short*)phi + (size_t)(row0 + 8) * pld + col) = pck(h0, h1);
                *(uint32_t*)((unsigned short*)plo + (size_t)(row0 + 8) * pld + col) = pck(l0, l1);
            }
        }

    if (GMAX) {
        int b = m0 >> 12;
#pragma unroll
        for (int nt = 0; nt < NT8; nt++) {
            int col = wn * (BN / 4) + nt * 8 + (lane & 3) * 2;
            float b0 = bias[col], b1 = bias[col + 1];
            float mA = fmaxf(fmaxf(acc[0][nt][0], acc[0][nt][2]),
                             fmaxf(acc[1][nt][0], acc[1][nt][2])) + b0;
            float mB = fmaxf(fmaxf(acc[0][nt][1], acc[0][nt][3]),
                             fmaxf(acc[1][nt][1], acc[1][nt][3])) + b1;
            mA = fmaxf(mA, 0.0f); mB = fmaxf(mB, 0.0f);
#pragma unroll
            for (int o = 4; o < 32; o <<= 1) {
                mA = fmaxf(mA, __shfl_xor_sync(0xffffffffu, mA, o));
                mB = fmaxf(mB, __shfl_xor_sync(0xffffffffu, mB, o));
            }
            if ((lane >> 2) == 0) {
                atomicMax(&g_gmax[b * 256 + col],     __float_as_int(mA));
                atomicMax(&g_gmax[b * 256 + col + 1], __float_as_int(mB));
            }
        }
    }
}

// ---------------- gemm1: fused interpolation staging, K=480 ------------------
__global__ void __launch_bounds__(512) tgemm_g1(
    const float* __restrict__ fall, const float* __restrict__ qp,
    const __nv_bfloat16* __restrict__ Whi, const __nv_bfloat16* __restrict__ Wlo,
    __nv_bfloat16* __restrict__ phi, __nv_bfloat16* __restrict__ plo) {
    constexpr int BN = 256, K = AGK, NC = K / 32, NT8 = BN / 32;
    constexpr int WPL = BN * PKB;
    constexpr int SS  = 2 * APL + 2 * WPL;
    extern __shared__ char smem[];
    int*   si  = (int*)(smem + 2 * SS);            // [128*3]
    float* swt = (float*)(smem + 2 * SS + 1536);   // [128*3]
    const int t = threadIdx.x;
    const int lane = t & 31, warp = t >> 5;
    const int wm = warp >> 2, wn = warp & 3;
    const int m0 = blockIdx.x * 128;
    const int b  = m0 >> 14;

    if (t < 128) {
#pragma unroll
        for (int j = 0; j < 3; j++) {
            si[t * 3 + j]  = g_knni[(m0 + t) * 3 + j];
            swt[t * 3 + j] = g_knnw[(m0 + t) * 3 + j];
        }
    }
    __syncthreads();

    float acc[2][NT8][4];
#pragma unroll
    for (int i = 0; i < 2; i++)
#pragma unroll
        for (int j = 0; j < NT8; j++)
#pragma unroll
            for (int v = 0; v < 4; v++) acc[i][j][v] = 0.0f;

    auto stageW = [&](int buf, int c) {
        char* base = smem + buf * SS;
#pragma unroll
        for (int u = 0; u < 4; u++) {
            int e = t + u * 512;
            int pl = e >> 10, rem = e & 1023;
            int row = rem >> 2, seg = rem & 3;
            const char* src = (const char*)(pl ? Wlo : Whi)
                + ((size_t)row * K + c * 32) * 2 + seg * 16;
            cp16(smem_u32(base + 2 * APL + pl * WPL + row * PKB + seg * 16), src);
        }
        CP_COMMIT();
    };

    auto stageA = [&](char* base, int c) {
        const int ch0 = c * 32;
#pragma unroll
        for (int u = 0; u < 2; u++) {
            int e = t + u * 512;
            int row = e >> 3, c4 = e & 7;
            int ch = ch0 + c4 * 4;
            float v0, v1, v2, v3;
            if (ch < 448) {
                const float* fr = fall + (size_t)(b * NP) * FDIM + ch;
                float4 A = *(const float4*)(fr + (size_t)si[row * 3 + 0] * FDIM);
                float4 B = *(const float4*)(fr + (size_t)si[row * 3 + 1] * FDIM);
                float4 C = *(const float4*)(fr + (size_t)si[row * 3 + 2] * FDIM);
                float wa = swt[row * 3 + 0], wb = swt[row * 3 + 1], wc = swt[row * 3 + 2];
                v0 = wa * A.x + wb * B.x + wc * C.x;
                v1 = wa * A.y + wb * B.y + wc * C.y;
                v2 = wa * A.z + wb * B.z + wc * C.z;
                v3 = wa * A.w + wb * B.w + wc * C.w;
            } else if (ch == 448) {
                int qi = (m0 + row) & (NQ - 1);
                v0 = qp[b * 3 * NQ + 0 * NQ + qi];
                v1 = qp[b * 3 * NQ + 1 * NQ + qi];
                v2 = qp[b * 3 * NQ + 2 * NQ + qi];
                v3 = 0.0f;
            } else {
                v0 = v1 = v2 = v3 = 0.0f;
            }
            __nv_bfloat16 h0, l0, h1, l1, h2, l2, h3, l3;
            split_bf16(v0, h0, l0); split_bf16(v1, h1, l1);
            split_bf16(v2, h2, l2); split_bf16(v3, h3, l3);
            int off = row * PKB + (c4 >> 1) * 16 + (c4 & 1) * 8;
            *(uint2*)(base + off)       = make_uint2(pck(h0, h1), pck(h2, h3));
            *(uint2*)(base + APL + off) = make_uint2(pck(l0, l1), pck(l2, l3));
        }
    };

    stageW(0, 0);
    for (int c = 0; c < NC; c++) {
        char* base = smem + (c & 1) * SS;
        stageA(base, c);
        if (c + 1 < NC) {
            stageW((c + 1) & 1, c + 1);
            asm volatile("cp.async.wait_group 1;" ::: "memory");
        } else {
            asm volatile("cp.async.wait_group 0;" ::: "memory");
        }
        __syncthreads();
#pragma unroll
        for (int kk = 0; kk < 2; kk++) {
            uint32_t afr[2][2][4];
#pragma unroll
            for (int pl = 0; pl < 2; pl++)
#pragma unroll
                for (int mt = 0; mt < 2; mt++) {
                    uint32_t a = smem_u32(base + pl * APL
                        + (wm * 32 + mt * 16 + (lane & 15)) * PKB
                        + (kk * 16 + (lane >> 4) * 8) * 2);
                    ldm_x4(afr[pl][mt], a);
                }
#pragma unroll
            for (int nt = 0; nt < NT8; nt++) {
                const char* bp = base + 2 * APL
                    + (wn * (BN / 4) + nt * 8 + (lane >> 2)) * PKB
                    + (kk * 16 + (lane & 3) * 2) * 2;
                uint32_t bh[2], bl[2];
                bh[0] = *(const uint32_t*)bp;
                bh[1] = *(const uint32_t*)(bp + 16);
                bl[0] = *(const uint32_t*)(bp + WPL);
                bl[1] = *(const uint32_t*)(bp + WPL + 16);
#pragma unroll
                for (int mt = 0; mt < 2; mt++) {
                    mma16816(acc[mt][nt], afr[0][mt], bh);
                    mma16816(acc[mt][nt], afr[0][mt], bl);
                    mma16816(acc[mt][nt], afr[1][mt], bh);
                }
            }
        }
        __syncthreads();
    }

    const float* bias = g_b1 + b * 256;
#pragma unroll
    for (int mt = 0; mt < 2; mt++)
#pragma unroll
        for (int nt = 0; nt < NT8; nt++) {
            int row0 = m0 + wm * 32 + mt * 16 + (lane >> 2);
            int col = wn * (BN / 4) + nt * 8 + (lane & 3) * 2;
            float b0 = bias[col], b1 = bias[col + 1];
            float v0 = fmaxf(acc[mt][nt][0] + b0, 0.0f);
            float v1 = fmaxf(acc[mt][nt][1] + b1, 0.0f);
            float v2 = fmaxf(acc[mt][nt][2] + b0, 0.0f);
            float v3 = fmaxf(acc[mt][nt][3] + b1, 0.0f);
            __nv_bfloat16 h0, l0, h1, l1;
            split_bf16(v0, h0, l0); split_bf16(v1, h1, l1);
            *(uint32_t*)((unsigned short*)phi + (size_t)row0 * 256 + col) = pck(h0, h1);
            *(uint32_t*)((unsigned short*)plo + (size_t)row0 * 256 + col) = pck(l0, l1);
            split_bf16(v2, h0, l0); split_bf16(v3, h1, l1);
            *(uint32_t*)((unsigned short*)phi + (size_t)(row0 + 8) * 256 + col) = pck(h0, h1);
            *(uint32_t*)((unsigned short*)plo + (size_t)(row0 + 8) * 256 + col) = pck(l0, l1);
        }
}

// ---------------- fused tail: (256->128 relu)(128->64 relu)(64->1) -----------
// Phase 1: gemm2 mainloop identical to tgemm_wide<128>.
// Phase 2: h2 -> smem (chunked fragment layout, reusing pipeline buffers).
// Phase 3: gemm3 from smem against preloaded r3 tile.  Phase 4: dot r4 -> out.
#define SS128   (2 * APL + 2 * 128 * PKB)   // 40960, one gemm2 stage
#define H2CHK   (2 * APL)                   // h2 chunk: hi+lo planes, 20480
#define W3BASE  (2 * SS128)                 // 81920
#define W3CHK   (2 * 64 * PKB)              // 10240 per chunk (hi+lo)
#define SMTAIL  (W3BASE + 4 * W3CHK)        // 122880

__global__ void __launch_bounds__(512) tgemm_tail(
    const __nv_bfloat16* __restrict__ Ahi, const __nv_bfloat16* __restrict__ Alo,
    const __nv_bfloat16* __restrict__ Whi, const __nv_bfloat16* __restrict__ Wlo,
    const __nv_bfloat16* __restrict__ W3hi, const __nv_bfloat16* __restrict__ W3lo,
    const float* __restrict__ rb2, const float* __restrict__ rb3,
    const float* __restrict__ r4, const float* __restrict__ rb4,
    float* __restrict__ out) {
    constexpr int K = 256, NC = K / 32;
    constexpr int WPL = 128 * PKB;
    extern __shared__ char smem[];
    const int t = threadIdx.x;
    const int lane = t & 31, warp = t >> 5;
    const int wm = warp >> 2, wn = warp & 3;
    const int m0 = blockIdx.x * 128;

    float acc[2][4][4];
#pragma unroll
    for (int i = 0; i < 2; i++)
#pragma unroll
        for (int j = 0; j < 4; j++)
#pragma unroll
            for (int v = 0; v < 4; v++) acc[i][j][v] = 0.0f;

    // preload r3 tile (4 K-chunks, hi/lo), joins first cp.async group
    {
        char* w3b = smem + W3BASE;
#pragma unroll
        for (int u = 0; u < 4; u++) {
            int e = t + u * 512;             // 0..2047
            int pl = e >> 10, rem = e & 1023;
            int ck = rem >> 8, r2m = rem & 255;
            int row = r2m >> 2, seg = r2m & 3;
            const char* src = (const char*)(pl ? W3lo : W3hi)
                + ((size_t)row * 128 + ck * 32) * 2 + seg * 16;
            cp16(smem_u32(w3b + ck * W3CHK + pl * (64 * PKB) + row * PKB + seg * 16), src);
        }
    }

    auto stage = [&](int buf, int c) {
        char* base = smem + buf * SS128;
#pragma unroll
        for (int u = 0; u < 2; u++) {
            int e = t + u * 512;
            int pl = e >> 9, rem = e & 511;
            int row = rem >> 2, seg = rem & 3;
            const char* src = (const char*)(pl ? Alo : Ahi)
                + ((size_t)(m0 + row) * K + c * 32) * 2 + seg * 16;
            cp16(smem_u32(base + pl * APL + row * PKB + seg * 16), src);
        }
#pragma unroll
        for (int u = 0; u < 2; u++) {
            int e = t + u * 512;
            int pl = e >> 9, rem = e & 511;
            int row = rem >> 2, seg = rem & 3;
            const char* src = (const char*)(pl ? Wlo : Whi)
                + ((size_t)row * K + c * 32) * 2 + seg * 16;
            cp16(smem_u32(base + 2 * APL + pl * WPL + row * PKB + seg * 16), src);
        }
        CP_COMMIT();
    };

    stage(0, 0);
    for (int c = 0; c < NC; c++) {
        if (c + 1 < NC) {
            stage((c + 1) & 1, c + 1);
            asm volatile("cp.async.wait_group 1;" ::: "memory");
        } else {
            asm volatile("cp.async.wait_group 0;" ::: "memory");
        }
        __syncthreads();
        char* base = smem + (c & 1) * SS128;
#pragma unroll
        for (int kk = 0; kk < 2; kk++) {
            uint32_t afr[2][2][4];
#pragma unroll
            for (int pl = 0; pl < 2; pl++)
#pragma unroll
                for (int mt = 0; mt < 2; mt++) {
                    uint32_t a = smem_u32(base + pl * APL
                        + (wm * 32 + mt * 16 + (lane & 15)) * PKB
                        + (kk * 16 + (lane >> 4) * 8) * 2);
                    ldm_x4(afr[pl][mt], a);
                }
#pragma unroll
            for (int nt = 0; nt < 4; nt++) {
                const char* bp = base + 2 * APL
                    + (wn * 32 + nt * 8 + (lane >> 2)) * PKB
                    + (kk * 16 + (lane & 3) * 2) * 2;
                uint32_t bh[2], bl[2];
                bh[0] = *(const uint32_t*)bp;
                bh[1] = *(const uint32_t*)(bp + 16);
                bl[0] = *(const uint32_t*)(bp + WPL);
                bl[1] = *(const uint32_t*)(bp + WPL + 16);
#pragma unroll
                for (int mt = 0; mt < 2; mt++) {
                    mma16816(acc[mt][nt], afr[0][mt], bh);
                    mma16816(acc[mt][nt], afr[0][mt], bl);
                    mma16816(acc[mt][nt], afr[1][mt], bh);
                }
            }
        }
        __syncthreads();
    }

    // phase 2: h2 = relu(acc+rb2) -> smem chunks (reuse pipeline buffers)
    // col in [0,128): chunk = col>>5 == wn; byte offset = row*PKB + (col&31)*2
#pragma unroll
    for (int mt = 0; mt < 2; mt++)
#pragma unroll
        for (int nt = 0; nt < 4; nt++) {
            int rowl = wm * 32 + mt * 16 + (lane >> 2);
            int col = wn * 32 + nt * 8 + (lane & 3) * 2;
            float b0 = rb2[col], b1 = rb2[col + 1];
            float v0 = fmaxf(acc[mt][nt][0] + b0, 0.0f);
            float v1 = fmaxf(acc[mt][nt][1] + b1, 0.0f);
            float v2 = fmaxf(acc[mt][nt][2] + b0, 0.0f);
            float v3 = fmaxf(acc[mt][nt][3] + b1, 0.0f);
            char* ckb = smem + wn * H2CHK;
            int ci = (col & 31) * 2;
            __nv_bfloat16 h0, l0, h1, l1;
            split_bf16(v0, h0, l0); split_bf16(v1, h1, l1);
            *(uint32_t*)(ckb + rowl * PKB + ci)       = pck(h0, h1);
            *(uint32_t*)(ckb + APL + rowl * PKB + ci) = pck(l0, l1);
            split_bf16(v2, h0, l0); split_bf16(v3, h1, l1);
            *(uint32_t*)(ckb + (rowl + 8) * PKB + ci)       = pck(h0, h1);
            *(uint32_t*)(ckb + APL + (rowl + 8) * PKB + ci) = pck(l0, l1);
        }
    __syncthreads();

    // phase 3: gemm3 (K=128, N=64) from smem
    float acc3[2][2][4];
#pragma unroll
    for (int i = 0; i < 2; i++)
#pragma unroll
        for (int j = 0; j < 2; j++)
#pragma unroll
            for (int v = 0; v < 4; v++) acc3[i][j][v] = 0.0f;

    for (int c = 0; c < 4; c++) {
        char* abase = smem + c * H2CHK;
        char* bbase = smem + W3BASE + c * W3CHK;
#pragma unroll
        for (int kk = 0; kk < 2; kk++) {
            uint32_t afr[2][2][4];
#pragma unroll
            for (int pl = 0; pl < 2; pl++)
#pragma unroll
                for (int mt = 0; mt < 2; mt++) {
                    uint32_t a = smem_u32(abase + pl * APL
                        + (wm * 32 + mt * 16 + (lane & 15)) * PKB
                        + (kk * 16 + (lane >> 4) * 8) * 2);
                    ldm_x4(afr[pl][mt], a);
                }
#pragma unroll
            for (int nt = 0; nt < 2; nt++) {
                const char* bp = bbase
                    + (wn * 16 + nt * 8 + (lane >> 2)) * PKB
                    + (kk * 16 + (lane & 3) * 2) * 2;
                uint32_t bh[2], bl[2];
                bh[0] = *(const uint32_t*)bp;
                bh[1] = *(const uint32_t*)(bp + 16);
                bl[0] = *(const uint32_t*)(bp + 64 * PKB);
                bl[1] = *(const uint32_t*)(bp + 64 * PKB + 16);
#pragma unroll
                for (int mt = 0; mt < 2; mt++) {
                    mma16816(acc3[mt][nt], afr[0][mt], bh);
                    mma16816(acc3[mt][nt], afr[0][mt], bl);
                    mma16816(acc3[mt][nt], afr[1][mt], bh);
                }
            }
        }
    }
    __syncthreads();   // h2 reads done before sp reuse

    // phase 4: relu(.+rb3) dot r4, reduce, + rb4
    float part[2][2] = {{0.0f, 0.0f}, {0.0f, 0.0f}};
#pragma unroll
    for (int mt = 0; mt < 2; mt++)
#pragma unroll
        for (int nt = 0; nt < 2; nt++) {
            int col = wn * 16 + nt * 8 + (lane & 3) * 2;
            float b0 = rb3[col], b1 = rb3[col + 1];
            float r0 = r4[col], r1 = r4[col + 1];
            part[mt][0] += fmaxf(acc3[mt][nt][0] + b0, 0.0f) * r0
                         + fmaxf(acc3[mt][nt][1] + b1, 0.0f) * r1;
            part[mt][1] += fmaxf(acc3[mt][nt][2] + b0, 0.0f) * r0
                         + fmaxf(acc3[mt][nt][3] + b1, 0.0f) * r1;
        }
    float* sp = (float*)smem;   // [128][4]
#pragma unroll
    for (int mt = 0; mt < 2; mt++)
#pragma unroll
        for (int h = 0; h < 2; h++) {
            float v = part[mt][h];
            v += __shfl_xor_sync(0xffffffffu, v, 1);
            v += __shfl_xor_sync(0xffffffffu, v, 2);
            if ((lane & 3) == 0)
                sp[(wm * 32 + mt * 16 + h * 8 + (lane >> 2)) * 4 + wn] = v;
        }
    __syncthreads();
    if (t < 128)
        out[m0 + t] = sp[t * 4] + sp[t * 4 + 1] + sp[t * 4 + 2] + sp[t * 4 + 3] + rb4[0];
}

// ---------------- launch -----------------------------------------------------
extern "C" void kernel_launch(void* const* d_in, const int* in_sizes, int n_in,
                              void* d_out, int out_size) {
    const float* op  = (const float*)d_in[0];
    const float* qp  = (const float*)d_in[1];
    const float* w1  = (const float*)d_in[2];
    const float* b1  = (const float*)d_in[3];
    const float* w2  = (const float*)d_in[4];
    const float* b2  = (const float*)d_in[5];
    const float* w3  = (const float*)d_in[6];
    const float* b3  = (const float*)d_in[7];
    const float* r1  = (const float*)d_in[8];
    const float* rb1 = (const float*)d_in[9];
    const float* r2  = (const float*)d_in[10];
    const float* rb2 = (const float*)d_in[11];
    const float* r3  = (const float*)d_in[12];
    const float* rb3 = (const float*)d_in[13];
    const float* r4  = (const float*)d_in[14];
    const float* rb4 = (const float*)d_in[15];
    float* out = (float*)d_out;

    float* p_fall;
    cudaGetSymbolAddress((void**)&p_fall, g_fall);
    __nv_bfloat16 *f1h, *f1l, *f2h, *f2l, *h1h, *h1l;
    __nv_bfloat16 *w2h, *w2l, *w3h, *w3l, *r1h, *r1l, *r2h, *r2l, *r3h, *r3l;
    cudaGetSymbolAddress((void**)&f1h, g_f1h);  cudaGetSymbolAddress((void**)&f1l, g_f1l);
    cudaGetSymbolAddress((void**)&f2h, g_f2h);  cudaGetSymbolAddress((void**)&f2l, g_f2l);
    cudaGetSymbolAddress((void**)&h1h, g_h1h);  cudaGetSymbolAddress((void**)&h1l, g_h1l);
    cudaGetSymbolAddress((void**)&w2h, g_w2h);  cudaGetSymbolAddress((void**)&w2l, g_w2l);
    cudaGetSymbolAddress((void**)&w3h, g_w3h);  cudaGetSymbolAddress((void**)&w3l, g_w3l);
    cudaGetSymbolAddress((void**)&r1h, g_r1h);  cudaGetSymbolAddress((void**)&r1l, g_r1l);
    cudaGetSymbolAddress((void**)&r2h, g_r2h);  cudaGetSymbolAddress((void**)&r2l, g_r2l);
    cudaGetSymbolAddress((void**)&r3h, g_r3h);  cudaGetSymbolAddress((void**)&r3l, g_r3l);

    constexpr int SM256 = 2 * (2 * APL + 2 * 256 * PKB);   // 122880
    constexpr int SM128 = 2 * (2 * APL + 2 * 128 * PKB);   // 81920
    constexpr int SMG1  = SM256 + 3072;
    cudaFuncSetAttribute(tgemm_wide<256, true>,  cudaFuncAttributeMaxDynamicSharedMemorySize, SM256);
    cudaFuncSetAttribute(tgemm_wide<128, false>, cudaFuncAttributeMaxDynamicSharedMemorySize, SM128);
    cudaFuncSetAttribute(tgemm_g1,   cudaFuncAttributeMaxDynamicSharedMemorySize, SMG1);
    cudaFuncSetAttribute(tgemm_tail, cudaFuncAttributeMaxDynamicSharedMemorySize, SMTAIL);

    split_all_kernel<<<800, 256>>>(w2, w3, r1, r2, r3);
    gmax_zero_kernel<<<2, 256>>>();
    mlp1_kernel<<<MPTS / 8, 256>>>(op, w1, b1);
    // mlp2 64->128
    tgemm_wide<128, false><<<MPTS / 128, 512, SM128>>>(
        f1h, f1l, 64, w2h, w2l, b2, 64,
        p_fall + 64, FDIM, f2h, f2l, 128);
    // mlp3 128->256 + fused gmax
    tgemm_wide<256, true><<<MPTS / 128, 512, SM256>>>(
        f2h, f2l, 128, w3h, w3l, b3, 128,
        p_fall + 192, FDIM, nullptr, nullptr, 0);
    // gemm1 bias (rb1 + global-feature fold, fp32 exact)
    gbias_kernel<<<BATCH, 256>>>(r1, rb1);
    // knn: split halves + merge
    knn_part_kernel<<<dim3(NQ / 256, BATCH, 2), 256>>>(op, qp);
    knn_merge_kernel<<<NPTS / 256, 256>>>(op, qp);
    // gemm1 480->256 with fused interpolation staging
    tgemm_g1<<<NPTS / 128, 512, SMG1>>>(p_fall, qp, r1h, r1l, h1h, h1l);
    // fused tail: 256->128->64->1
    tgemm_tail<<<NPTS / 128, 512, SMTAIL>>>(
        h1h, h1l, r2h, r2l, r3h, r3l, rb2, rb3, r4, rb4, out);
}

// round 10
// speedup vs baseline: 4.0610x; 1.0385x over previous
#include <cuda_runtime.h>
#include <cuda_bf16.h>
#include <math_constants.h>
#include <cstdint>

#define BATCH 2
#define NP    4096
#define NPH   2048           // half of NP (knn split)
#define NQ    16384
#define FDIM  448            // 64 + 128 + 256
#define AGK   480            // gemm1 K: 448 interp + 3 query + 29 pad
#define NPTS  (BATCH * NQ)   // 32768 query points
#define MPTS  (BATCH * NP)   // 8192 original points

// ---------------- scratch (device globals; no allocation allowed) -----------
__device__ float g_fall[MPTS * FDIM];          // point-major fp32 (f1|f2|f3)
__device__ int   g_gmax[BATCH * 256];
__device__ float g_b1[BATCH * 256];            // gemm1 bias incl. global feats
__device__ int   g_knni[NPTS * 3];
__device__ float g_knnw[NPTS * 3];
__device__ float g_kcd[NPTS * 6];              // knn candidates (2 halves x 3)
__device__ int   g_kci[NPTS * 6];
__device__ __nv_bfloat16 g_f1h[MPTS * 64],   g_f1l[MPTS * 64];
__device__ __nv_bfloat16 g_f2h[MPTS * 128],  g_f2l[MPTS * 128];
__device__ __nv_bfloat16 g_w2h[128 * 64],   g_w2l[128 * 64];
__device__ __nv_bfloat16 g_w3h[256 * 128],  g_w3l[256 * 128];
__device__ __nv_bfloat16 g_r1h[256 * AGK],  g_r1l[256 * AGK];   // remapped cols
__device__ __nv_bfloat16 g_r2h[128 * 256],  g_r2l[128 * 256];
__device__ __nv_bfloat16 g_r3h[64 * 128],   g_r3l[64 * 128];

// ---------------- helpers -----------------------------------------------------
__device__ __forceinline__ uint32_t smem_u32(const void* p) {
    uint32_t a;
    asm("{ .reg .u64 t; cvta.to.shared.u64 t, %1; cvt.u32.u64 %0, t; }" : "=r"(a) : "l"(p));
    return a;
}
__device__ __forceinline__ void cp16(uint32_t dst, const void* src) {
    asm volatile("cp.async.cg.shared.global [%0], [%1], 16;" :: "r"(dst), "l"(src));
}
#define CP_COMMIT() asm volatile("cp.async.commit_group;" ::: "memory")

__device__ __forceinline__ void ldm_x4(uint32_t* r, uint32_t addr) {
    asm volatile("ldmatrix.sync.aligned.m8n8.x4.shared.b16 {%0,%1,%2,%3}, [%4];"
                 : "=r"(r[0]), "=r"(r[1]), "=r"(r[2]), "=r"(r[3]) : "r"(addr));
}
__device__ __forceinline__ void mma16816(float* c, const uint32_t* a, const uint32_t* b) {
    asm volatile(
        "mma.sync.aligned.m16n8k16.row.col.f32.bf16.bf16.f32 "
        "{%0,%1,%2,%3}, {%4,%5,%6,%7}, {%8,%9}, {%0,%1,%2,%3};"
        : "+f"(c[0]), "+f"(c[1]), "+f"(c[2]), "+f"(c[3])
        : "r"(a[0]), "r"(a[1]), "r"(a[2]), "r"(a[3]), "r"(b[0]), "r"(b[1]));
}
__device__ __forceinline__ void split_bf16(float v, __nv_bfloat16& h, __nv_bfloat16& l) {
    h = __float2bfloat16(v);
    l = __float2bfloat16(v - __bfloat162float(h));
}
__device__ __forceinline__ uint32_t pck(__nv_bfloat16 a, __nv_bfloat16 b) {
    return (uint32_t)*(unsigned short*)&a | ((uint32_t)*(unsigned short*)&b << 16);
}

// ---------------- mlp1: 3 -> 64 (fp32 to g_fall + hi/lo planes) --------------
__global__ void __launch_bounds__(256) mlp1_kernel(const float* __restrict__ op,
                                                   const float* __restrict__ w1,
                                                   const float* __restrict__ b1) {
    __shared__ float sw[192];
    __shared__ float sb[64];
    int t = threadIdx.x;
    if (t < 192) sw[t] = w1[t];
    if (t < 64)  sb[t] = b1[t];
    __syncthreads();
    int pfl  = blockIdx.x * 8 + (t >> 5);
    int lane = t & 31;
    int b  = pfl >> 12;
    int pt = pfl & (NP - 1);
    float x = op[b * 3 * NP + 0 * NP + pt];
    float y = op[b * 3 * NP + 1 * NP + pt];
    float z = op[b * 3 * NP + 2 * NP + pt];
    float* dst = g_fall + (size_t)pfl * FDIM;
#pragma unroll
    for (int u = 0; u < 2; u++) {
        int c = lane + u * 32;
        float v = fmaf(sw[c*3+0], x, fmaf(sw[c*3+1], y, fmaf(sw[c*3+2], z, sb[c])));
        v = fmaxf(v, 0.0f);
        dst[c] = v;
        __nv_bfloat16 h, l; split_bf16(v, h, l);
        g_f1h[pfl * 64 + c] = h;
        g_f1l[pfl * 64 + c] = l;
    }
}

__global__ void gmax_zero_kernel() {
    int t = threadIdx.x + blockIdx.x * blockDim.x;
    if (t < BATCH * 256) g_gmax[t] = 0;
}

// ---------------- gemm1 bias: rb1 + global-feature contribution (fp32) -------
__global__ void __launch_bounds__(256) gbias_kernel(const float* __restrict__ r1,
                                                    const float* __restrict__ rb1) {
    int b = blockIdx.x, n = threadIdx.x;
    const float* wr = r1 + n * 707 + 451;
    float acc = rb1[n];
#pragma unroll 8
    for (int j = 0; j < 256; j++)
        acc = fmaf(wr[j], __int_as_float(g_gmax[b * 256 + j]), acc);
    g_b1[b * 256 + n] = acc;
}

// ---------------- single fused weight split (+pad, r1 remapped) --------------
__global__ void __launch_bounds__(256) split_all_kernel(
    const float* __restrict__ w2, const float* __restrict__ w3,
    const float* __restrict__ r1, const float* __restrict__ r2,
    const float* __restrict__ r3) {
    int i = blockIdx.x * 256 + threadIdx.x;
    if (i >= 204800) return;
    float v = 0.0f;
    __nv_bfloat16 *hi, *lo; int off;
    if (i < 8192) {
        off = i; hi = g_w2h; lo = g_w2l;
        v = w2[off];
    } else if (i < 40960) {
        off = i - 8192; hi = g_w3h; lo = g_w3l;
        v = w3[off];
    } else if (i < 163840) {
        off = i - 40960; hi = g_r1h; lo = g_r1l;
        int r = off / AGK, k = off - r * AGK;
        if (k < 448)      v = r1[r * 707 + 3 + k];     // interp channels
        else if (k < 451) v = r1[r * 707 + (k - 448)]; // query coords
    } else if (i < 196608) {
        off = i - 163840; hi = g_r2h; lo = g_r2l;
        v = r2[off];
    } else {
        off = i - 196608; hi = g_r3h; lo = g_r3l;
        v = r3[off];
    }
    __nv_bfloat16 h, l; split_bf16(v, h, l);
    hi[off] = h; lo[off] = l;
}

// ---------------- KNN part 1: top-3 within one half of the points ------------
__global__ void __launch_bounds__(256) knn_part_kernel(const float* __restrict__ op,
                                                       const float* __restrict__ qp) {
    __shared__ float4 sp[NPH];            // 32 KB
    int b = blockIdx.y, half = blockIdx.z;
    int tid = threadIdx.x;
    int jbase = half * NPH;
    for (int i = tid; i < NPH; i += 256) {
        float x = op[b * 3 * NP + 0 * NP + jbase + i];
        float y = op[b * 3 * NP + 1 * NP + jbase + i];
        float z = op[b * 3 * NP + 2 * NP + jbase + i];
        sp[i] = make_float4(x, y, z, fmaf(x, x, fmaf(y, y, z * z)));
    }
    __syncthreads();

    int q = blockIdx.x * 256 + tid;
    float qx = qp[b * 3 * NQ + 0 * NQ + q];
    float qy = qp[b * 3 * NQ + 1 * NQ + q];
    float qz = qp[b * 3 * NQ + 2 * NQ + q];
    float nx = -2.0f * qx, ny = -2.0f * qy, nz = -2.0f * qz;

    float d0 = CUDART_INF_F, d1 = CUDART_INF_F, d2 = CUDART_INF_F;
    int i0 = 0, i1 = 0, i2 = 0;
#pragma unroll 8
    for (int j = 0; j < NPH; j++) {
        float4 o = sp[j];
        float d = fmaf(o.x, nx, fmaf(o.y, ny, fmaf(o.z, nz, o.w)));
        if (d < d2) {
            if (d < d1) {
                d2 = d1; i2 = i1;
                if (d < d0) { d1 = d0; i1 = i0; d0 = d; i0 = j; }
                else        { d1 = d;  i1 = j; }
            } else { d2 = d; i2 = j; }
        }
    }
    int base = ((b * NQ + q) * 2 + half) * 3;
    g_kcd[base + 0] = d0; g_kci[base + 0] = jbase + i0;
    g_kcd[base + 1] = d1; g_kci[base + 1] = jbase + i1;
    g_kcd[base + 2] = d2; g_kci[base + 2] = jbase + i2;
}

// ---------------- KNN part 2: merge halves, compute weights ------------------
__global__ void __launch_bounds__(256) knn_merge_kernel(const float* __restrict__ op,
                                                        const float* __restrict__ qp) {
    int i = blockIdx.x * 256 + threadIdx.x;   // 0..NPTS-1
    int b = i >> 14, q = i & (NQ - 1);
    float d0 = CUDART_INF_F, d1 = CUDART_INF_F, d2 = CUDART_INF_F;
    int i0 = 0, i1 = 0, i2 = 0;
#pragma unroll
    for (int c = 0; c < 6; c++) {
        float d = g_kcd[i * 6 + c];
        int   j = g_kci[i * 6 + c];
        if (d < d2) {
            if (d < d1) {
                d2 = d1; i2 = i1;
                if (d < d0) { d1 = d0; i1 = i0; d0 = d; i0 = j; }
                else        { d1 = d;  i1 = j; }
            } else { d2 = d; i2 = j; }
        }
    }
    float qx = qp[b * 3 * NQ + 0 * NQ + q];
    float qy = qp[b * 3 * NQ + 1 * NQ + q];
    float qz = qp[b * 3 * NQ + 2 * NQ + q];
    int   ii[3] = {i0, i1, i2};
    float rc[3];
    float s = 0.0f;
#pragma unroll
    for (int k = 0; k < 3; k++) {
        float dx = op[b * 3 * NP + 0 * NP + ii[k]] - qx;
        float dy = op[b * 3 * NP + 1 * NP + ii[k]] - qy;
        float dz = op[b * 3 * NP + 2 * NP + ii[k]] - qz;
        float dist = sqrtf(fmaf(dx, dx, fmaf(dy, dy, dz * dz)));
        rc[k] = 1.0f / (dist + 1e-8f);
        s += rc[k];
    }
    float inv = 1.0f / s;
#pragma unroll
    for (int k = 0; k < 3; k++) {
        g_knni[i * 3 + k] = ii[k];
        g_knnw[i * 3 + k] = rc[k] * inv;
    }
}

// ---------------- wide split-bf16 tensor GEMM (mlp2 / mlp3) ------------------
#define PKB 80                       // smem row pitch bytes (32 bf16 + 16B pad)
#define APL (128 * PKB)              // A plane bytes (10240)

template <int BN, bool GMAX>
__global__ void __launch_bounds__(512) tgemm_wide(
    const __nv_bfloat16* __restrict__ Ahi, const __nv_bfloat16* __restrict__ Alo, int lda,
    const __nv_bfloat16* __restrict__ Whi, const __nv_bfloat16* __restrict__ Wlo,
    const float* __restrict__ bias, int K,
    float* __restrict__ f32out, int f32ld,
    __nv_bfloat16* __restrict__ phi, __nv_bfloat16* __restrict__ plo, int pld) {
    extern __shared__ char smem[];
    constexpr int WPL = BN * PKB;
    constexpr int SS  = 2 * APL + 2 * WPL;
    constexpr int NT8 = BN / 32;
    const int t = threadIdx.x;
    const int lane = t & 31, warp = t >> 5;
    const int wm = warp >> 2, wn = warp & 3;
    const int m0 = blockIdx.x * 128;
    const int ldw = K;

    float acc[2][NT8][4];
#pragma unroll
    for (int i = 0; i < 2; i++)
#pragma unroll
        for (int j = 0; j < NT8; j++)
#pragma unroll
            for (int v = 0; v < 4; v++) acc[i][j][v] = 0.0f;

    const int NC = K / 32;

    auto stage = [&](int buf, int c) {
        char* base = smem + buf * SS;
#pragma unroll
        for (int u = 0; u < 2; u++) {
            int e = t + u * 512;
            int pl = e >> 9, rem = e & 511;
            int row = rem >> 2, seg = rem & 3;
            const char* src = (const char*)(pl ? Alo : Ahi)
                + ((size_t)(m0 + row) * lda + c * 32) * 2 + seg * 16;
            cp16(smem_u32(base + pl * APL + row * PKB + seg * 16), src);
        }
#pragma unroll
        for (int u = 0; u < BN / 64; u++) {
            int e = t + u * 512;
            int pl = e / (BN * 4), rem = e % (BN * 4);
            int row = rem >> 2, seg = rem & 3;
            const char* src = (const char*)(pl ? Wlo : Whi)
                + ((size_t)row * ldw + c * 32) * 2 + seg * 16;
            cp16(smem_u32(base + 2 * APL + pl * WPL + row * PKB + seg * 16), src);
        }
        CP_COMMIT();
    };

    stage(0, 0);
    for (int c = 0; c < NC; c++) {
        if (c + 1 < NC) {
            stage((c + 1) & 1, c + 1);
            asm volatile("cp.async.wait_group 1;" ::: "memory");
        } else {
            asm volatile("cp.async.wait_group 0;" ::: "memory");
        }
        __syncthreads();
        char* base = smem + (c & 1) * SS;
#pragma unroll
        for (int kk = 0; kk < 2; kk++) {
            uint32_t afr[2][2][4];
#pragma unroll
            for (int pl = 0; pl < 2; pl++)
#pragma unroll
                for (int mt = 0; mt < 2; mt++) {
                    uint32_t a = smem_u32(base + pl * APL
                        + (wm * 32 + mt * 16 + (lane & 15)) * PKB
                        + (kk * 16 + (lane >> 4) * 8) * 2);
                    ldm_x4(afr[pl][mt], a);
                }
#pragma unroll
            for (int nt = 0; nt < NT8; nt++) {
                const char* bp = base + 2 * APL
                    + (wn * (BN / 4) + nt * 8 + (lane >> 2)) * PKB
                    + (kk * 16 + (lane & 3) * 2) * 2;
                uint32_t bh[2], bl[2];
                bh[0] = *(const uint32_t*)bp;
                bh[1] = *(const uint32_t*)(bp + 16);
                bl[0] = *(const uint32_t*)(bp + WPL);
                bl[1] = *(const uint32_t*)(bp + WPL + 16);
#pragma unroll
                for (int mt = 0; mt < 2; mt++) {
                    mma16816(acc[mt][nt], afr[0][mt], bh);
                    mma16816(acc[mt][nt], afr[0][mt], bl);
                    mma16816(acc[mt][nt], afr[1][mt], bh);
                }
            }
        }
        __syncthreads();
    }

#pragma unroll
    for (int mt = 0; mt < 2; mt++)
#pragma unroll
        for (int nt = 0; nt < NT8; nt++) {
            int row0 = m0 + wm * 32 + mt * 16 + (lane >> 2);
            int col = wn * (BN / 4) + nt * 8 + (lane & 3) * 2;
            float b0 = bias[col], b1 = bias[col + 1];
            float v0 = fmaxf(acc[mt][nt][0] + b0, 0.0f);
            float v1 = fmaxf(acc[mt][nt][1] + b1, 0.0f);
            float v2 = fmaxf(acc[mt][nt][2] + b0, 0.0f);
            float v3 = fmaxf(acc[mt][nt][3] + b1, 0.0f);
            if (f32out) {
                *(float2*)(f32out + (size_t)row0 * f32ld + col) = make_float2(v0, v1);
                *(float2*)(f32out + (size_t)(row0 + 8) * f32ld + col) = make_float2(v2, v3);
            }
            if (phi) {
                __nv_bfloat16 h0, l0, h1, l1;
                split_bf16(v0, h0, l0); split_bf16(v1, h1, l1);
                *(uint32_t*)((unsigned short*)phi + (size_t)row0 * pld + col) = pck(h0, h1);
                *(uint32_t*)((unsigned short*)plo + (size_t)row0 * pld + col) = pck(l0, l1);
                split_bf16(v2, h0, l0); split_bf16(v3, h1, l1);
                *(uint32_t*)((unsigned short*)phi + (size_t)(row0 + 8) * pld + col) = pck(h0, h1);
                *(uint32_t*)((unsigned short*)plo + (size_t)(row0 + 8) * pld + col) = pck(l0, l1);
            }
        }

    if (GMAX) {
        int b = m0 >> 12;
#pragma unroll
        for (int nt = 0; nt < NT8; nt++) {
            int col = wn * (BN / 4) + nt * 8 + (lane & 3) * 2;
            float b0 = bias[col], b1 = bias[col + 1];
            float mA = fmaxf(fmaxf(acc[0][nt][0], acc[0][nt][2]),
                             fmaxf(acc[1][nt][0], acc[1][nt][2])) + b0;
            float mB = fmaxf(fmaxf(acc[0][nt][1], acc[0][nt][3]),
                             fmaxf(acc[1][nt][1], acc[1][nt][3])) + b1;
            mA = fmaxf(mA, 0.0f); mB = fmaxf(mB, 0.0f);
#pragma unroll
            for (int o = 4; o < 32; o <<= 1) {
                mA = fmaxf(mA, __shfl_xor_sync(0xffffffffu, mA, o));
                mB = fmaxf(mB, __shfl_xor_sync(0xffffffffu, mB, o));
            }
            if ((lane >> 2) == 0) {
                atomicMax(&g_gmax[b * 256 + col],     __float_as_int(mA));
                atomicMax(&g_gmax[b * 256 + col + 1], __float_as_int(mB));
            }
        }
    }
}

// ---------------- MEGA: gemm1(interp,480->256) -> 256->128 -> 128->64 -> 1 ---
// smem regions (total 225280):
//   [0,      40960)  r3 tile, 4 chunks x (hi 5120 | lo 5120), persists
//   [40960, 163840)  phase1: gemm1 double-buffer pipeline (2 x 61440)
//   [163840,166912)  phase1: knn idx/weights
//   [40960, 204800)  phase2: h1 chunks, 8 x 20480 (overwrites pipeline+knn)
//   [204800,225280)  phase2: W2 single buffer (hi 10240 | lo 10240)
//   [40960, 122880)  phase3: h2 chunks, 4 x 20480 (overwrites h1 0-3)
//   [163840, ...)    phase4: reduction scratch
#define SS1    (2 * APL + 2 * 256 * PKB)   // 61440
#define W3CHK  (2 * 64 * PKB)              // 10240
#define H1CHK  (2 * APL)                   // 20480
#define G1OFF  40960
#define KOFF   163840
#define H1OFF  40960
#define W2OFF  204800
#define W2PL   (128 * PKB)                 // 10240
#define H2OFF  40960
#define SPOFF  163840
#define SMEGA  225280

__global__ void __launch_bounds__(512) tgemm_mega(
    const float* __restrict__ fall, const float* __restrict__ qp,
    const __nv_bfloat16* __restrict__ W1hi, const __nv_bfloat16* __restrict__ W1lo,
    const __nv_bfloat16* __restrict__ W2hi, const __nv_bfloat16* __restrict__ W2lo,
    const __nv_bfloat16* __restrict__ W3hi, const __nv_bfloat16* __restrict__ W3lo,
    const float* __restrict__ rb2, const float* __restrict__ rb3,
    const float* __restrict__ r4, const float* __restrict__ rb4,
    float* __restrict__ out) {
    extern __shared__ char smem[];
    const int t = threadIdx.x;
    const int lane = t & 31, warp = t >> 5;
    const int wm = warp >> 2, wn = warp & 3;
    const int m0 = blockIdx.x * 128;
    const int b  = m0 >> 14;

    int*   si  = (int*)(smem + KOFF);
    float* swt = (float*)(smem + KOFF + 1536);
    if (t < 128) {
#pragma unroll
        for (int j = 0; j < 3; j++) {
            si[t * 3 + j]  = g_knni[(m0 + t) * 3 + j];
            swt[t * 3 + j] = g_knnw[(m0 + t) * 3 + j];
        }
    }

    // r3 preload into [0, 40960): joins the first cp.async group
    {
        char* w3b = smem;
#pragma unroll
        for (int u = 0; u < 4; u++) {
            int e = t + u * 512;
            int pl = e >> 10, rem = e & 1023;
            int ck = rem >> 8, r2m = rem & 255;
            int row = r2m >> 2, seg = r2m & 3;
            const char* src = (const char*)(pl ? W3lo : W3hi)
                + ((size_t)row * 128 + ck * 32) * 2 + seg * 16;
            cp16(smem_u32(w3b + ck * W3CHK + pl * (64 * PKB) + row * PKB + seg * 16), src);
        }
    }

    // ================= PHASE 1: gemm1 480 -> 256 =================
    constexpr int NC1 = AGK / 32;   // 15
    float acc[2][8][4];
#pragma unroll
    for (int i = 0; i < 2; i++)
#pragma unroll
        for (int j = 0; j < 8; j++)
#pragma unroll
            for (int v = 0; v < 4; v++) acc[i][j][v] = 0.0f;

    auto stageW1 = [&](int buf, int c) {
        char* base = smem + G1OFF + buf * SS1;
#pragma unroll
        for (int u = 0; u < 4; u++) {
            int e = t + u * 512;
            int pl = e >> 10, rem = e & 1023;
            int row = rem >> 2, seg = rem & 3;
            const char* src = (const char*)(pl ? W1lo : W1hi)
                + ((size_t)row * AGK + c * 32) * 2 + seg * 16;
            cp16(smem_u32(base + 2 * APL + pl * (256 * PKB) + row * PKB + seg * 16), src);
        }
        CP_COMMIT();
    };

    auto stageA1 = [&](char* base, int c) {
        const int ch0 = c * 32;
#pragma unroll
        for (int u = 0; u < 2; u++) {
            int e = t + u * 512;
            int row = e >> 3, c4 = e & 7;
            int ch = ch0 + c4 * 4;
            float v0, v1, v2, v3;
            if (ch < 448) {
                const float* fr = fall + (size_t)(b * NP) * FDIM + ch;
                float4 A = *(const float4*)(fr + (size_t)si[row * 3 + 0] * FDIM);
                float4 B = *(const float4*)(fr + (size_t)si[row * 3 + 1] * FDIM);
                float4 C = *(const float4*)(fr + (size_t)si[row * 3 + 2] * FDIM);
                float wa = swt[row * 3 + 0], wb = swt[row * 3 + 1], wc = swt[row * 3 + 2];
                v0 = wa * A.x + wb * B.x + wc * C.x;
                v1 = wa * A.y + wb * B.y + wc * C.y;
                v2 = wa * A.z + wb * B.z + wc * C.z;
                v3 = wa * A.w + wb * B.w + wc * C.w;
            } else if (ch == 448) {
                int qi = (m0 + row) & (NQ - 1);
                v0 = qp[b * 3 * NQ + 0 * NQ + qi];
                v1 = qp[b * 3 * NQ + 1 * NQ + qi];
                v2 = qp[b * 3 * NQ + 2 * NQ + qi];
                v3 = 0.0f;
            } else {
                v0 = v1 = v2 = v3 = 0.0f;
            }
            __nv_bfloat16 h0, l0, h1, l1, h2, l2, h3, l3;
            split_bf16(v0, h0, l0); split_bf16(v1, h1, l1);
            split_bf16(v2, h2, l2); split_bf16(v3, h3, l3);
            int off = row * PKB + (c4 >> 1) * 16 + (c4 & 1) * 8;
            *(uint2*)(base + off)       = make_uint2(pck(h0, h1), pck(h2, h3));
            *(uint2*)(base + APL + off) = make_uint2(pck(l0, l1), pck(l2, l3));
        }
    };

    __syncthreads();   // si/swt visible before stageA uses them
    stageW1(0, 0);
    for (int c = 0; c < NC1; c++) {
        char* base = smem + G1OFF + (c & 1) * SS1;
        stageA1(base, c);
        if (c + 1 < NC1) {
            stageW1((c + 1) & 1, c + 1);
            asm volatile("cp.async.wait_group 1;" ::: "memory");
        } else {
            asm volatile("cp.async.wait_group 0;" ::: "memory");
        }
        __syncthreads();
#pragma unroll
        for (int kk = 0; kk < 2; kk++) {
            uint32_t afr[2][2][4];
#pragma unroll
            for (int pl = 0; pl < 2; pl++)
#pragma unroll
                for (int mt = 0; mt < 2; mt++) {
                    uint32_t a = smem_u32(base + pl * APL
                        + (wm * 32 + mt * 16 + (lane & 15)) * PKB
                        + (kk * 16 + (lane >> 4) * 8) * 2);
                    ldm_x4(afr[pl][mt], a);
                }
#pragma unroll
            for (int nt = 0; nt < 8; nt++) {
                const char* bp = base + 2 * APL
                    + (wn * 64 + nt * 8 + (lane >> 2)) * PKB
                    + (kk * 16 + (lane & 3) * 2) * 2;
                uint32_t bh[2], bl[2];
                bh[0] = *(const uint32_t*)bp;
                bh[1] = *(const uint32_t*)(bp + 16);
                bl[0] = *(const uint32_t*)(bp + 256 * PKB);
                bl[1] = *(const uint32_t*)(bp + 256 * PKB + 16);
#pragma unroll
                for (int mt = 0; mt < 2; mt++) {
                    mma16816(acc[mt][nt], afr[0][mt], bh);
                    mma16816(acc[mt][nt], afr[0][mt], bl);
                    mma16816(acc[mt][nt], afr[1][mt], bh);
                }
            }
        }
        __syncthreads();
    }

    // h1 = relu(acc + g_b1) -> smem chunk layout [H1OFF, +163840)
    {
        const float* bias = g_b1 + b * 256;
#pragma unroll
        for (int mt = 0; mt < 2; mt++)
#pragma unroll
            for (int nt = 0; nt < 8; nt++) {
                int rowl = wm * 32 + mt * 16 + (lane >> 2);
                int col = wn * 64 + nt * 8 + (lane & 3) * 2;
                float b0 = bias[col], b1 = bias[col + 1];
                float v0 = fmaxf(acc[mt][nt][0] + b0, 0.0f);
                float v1 = fmaxf(acc[mt][nt][1] + b1, 0.0f);
                float v2 = fmaxf(acc[mt][nt][2] + b0, 0.0f);
                float v3 = fmaxf(acc[mt][nt][3] + b1, 0.0f);
                char* ckb = smem + H1OFF + (col >> 5) * H1CHK;
                int ci = (col & 31) * 2;
                __nv_bfloat16 h0, l0, h1, l1;
                split_bf16(v0, h0, l0); split_bf16(v1, h1, l1);
                *(uint32_t*)(ckb + rowl * PKB + ci)       = pck(h0, h1);
                *(uint32_t*)(ckb + APL + rowl * PKB + ci) = pck(l0, l1);
                split_bf16(v2, h0, l0); split_bf16(v3, h1, l1);
                *(uint32_t*)(ckb + (rowl + 8) * PKB + ci)       = pck(h0, h1);
                *(uint32_t*)(ckb + APL + (rowl + 8) * PKB + ci) = pck(l0, l1);
            }
    }
    __syncthreads();

    // ================= PHASE 2: gemm2 256 -> 128 (W2 single buffer) ==========
    float acc2[2][4][4];
#pragma unroll
    for (int i = 0; i < 2; i++)
#pragma unroll
        for (int j = 0; j < 4; j++)
#pragma unroll
            for (int v = 0; v < 4; v++) acc2[i][j][v] = 0.0f;

    for (int c = 0; c < 8; c++) {
        // load W2 chunk c
#pragma unroll
        for (int u = 0; u < 2; u++) {
            int e = t + u * 512;
            int pl = e >> 9, rem = e & 511;
            int row = rem >> 2, seg = rem & 3;
            const char* src = (const char*)(pl ? W2lo : W2hi)
                + ((size_t)row * 256 + c * 32) * 2 + seg * 16;
            cp16(smem_u32(smem + W2OFF + pl * W2PL + row * PKB + seg * 16), src);
        }
        CP_COMMIT();
        asm volatile("cp.async.wait_group 0;" ::: "memory");
        __syncthreads();

        char* abase = smem + H1OFF + c * H1CHK;
#pragma unroll
        for (int kk = 0; kk < 2; kk++) {
            uint32_t afr[2][2][4];
#pragma unroll
            for (int pl = 0; pl < 2; pl++)
#pragma unroll
                for (int mt = 0; mt < 2; mt++) {
                    uint32_t a = smem_u32(abase + pl * APL
                        + (wm * 32 + mt * 16 + (lane & 15)) * PKB
                        + (kk * 16 + (lane >> 4) * 8) * 2);
                    ldm_x4(afr[pl][mt], a);
                }
#pragma unroll
            for (int nt = 0; nt < 4; nt++) {
                const char* bp = smem + W2OFF
                    + (wn * 32 + nt * 8 + (lane >> 2)) * PKB
                    + (kk * 16 + (lane & 3) * 2) * 2;
                uint32_t bh[2], bl[2];
                bh[0] = *(const uint32_t*)bp;
                bh[1] = *(const uint32_t*)(bp + 16);
                bl[0] = *(const uint32_t*)(bp + W2PL);
                bl[1] = *(const uint32_t*)(bp + W2PL + 16);
#pragma unroll
                for (int mt = 0; mt < 2; mt++) {
                    mma16816(acc2[mt][nt], afr[0][mt], bh);
                    mma16816(acc2[mt][nt], afr[0][mt], bl);
                    mma16816(acc2[mt][nt], afr[1][mt], bh);
                }
            }
        }
        __syncthreads();   // before next W2 overwrite
    }

    // h2 = relu(acc2 + rb2) -> smem chunks [H2OFF, +81920)
#pragma unroll
    for (int mt = 0; mt < 2; mt++)
#pragma unroll
        for (int nt = 0; nt < 4; nt++) {
            int rowl = wm * 32 + mt * 16 + (lane >> 2);
            int col = wn * 32 + nt * 8 + (lane & 3) * 2;
            float b0 = rb2[col], b1 = rb2[col + 1];
            float v0 = fmaxf(acc2[mt][nt][0] + b0, 0.0f);
            float v1 = fmaxf(acc2[mt][nt][1] + b1, 0.0f);
            float v2 = fmaxf(acc2[mt][nt][2] + b0, 0.0f);
            float v3 = fmaxf(acc2[mt][nt][3] + b1, 0.0f);
            char* ckb = smem + H2OFF + (col >> 5) * H1CHK;
            int ci = (col & 31) * 2;
            __nv_bfloat16 h0, l0, h1, l1;
            split_bf16(v0, h0, l0); split_bf16(v1, h1, l1);
            *(uint32_t*)(ckb + rowl * PKB + ci)       = pck(h0, h1);
            *(uint32_t*)(ckb + APL + rowl * PKB + ci) = pck(l0, l1);
            split_bf16(v2, h0, l0); split_bf16(v3, h1, l1);
            *(uint32_t*)(ckb + (rowl + 8) * PKB + ci)       = pck(h0, h1);
            *(uint32_t*)(ckb + APL + (rowl + 8) * PKB + ci) = pck(l0, l1);
        }
    __syncthreads();

    // ================= PHASE 3: gemm3 128 -> 64 (all smem) ===================
    float acc3[2][2][4];
#pragma unroll
    for (int i = 0; i < 2; i++)
#pragma unroll
        for (int j = 0; j < 2; j++)
#pragma unroll
            for (int v = 0; v < 4; v++) acc3[i][j][v] = 0.0f;

    for (int c = 0; c < 4; c++) {
        char* abase = smem + H2OFF + c * H1CHK;
        char* bbase = smem + c * W3CHK;
#pragma unroll
        for (int kk = 0; kk < 2; kk++) {
            uint32_t afr[2][2][4];
#pragma unroll
            for (int pl = 0; pl < 2; pl++)
#pragma unroll
                for (int mt = 0; mt < 2; mt++) {
                    uint32_t a = smem_u32(abase + pl * APL
                        + (wm * 32 + mt * 16 + (lane & 15)) * PKB
                        + (kk * 16 + (lane >> 4) * 8) * 2);
                    ldm_x4(afr[pl][mt], a);
                }
#pragma unroll
            for (int nt = 0; nt < 2; nt++) {
                const char* bp = bbase
                    + (wn * 16 + nt * 8 + (lane >> 2)) * PKB
                    + (kk * 16 + (lane & 3) * 2) * 2;
                uint32_t bh[2], bl[2];
                bh[0] = *(const uint32_t*)bp;
                bh[1] = *(const uint32_t*)(bp + 16);
                bl[0] = *(const uint32_t*)(bp + 64 * PKB);
                bl[1] = *(const uint32_t*)(bp + 64 * PKB + 16);
#pragma unroll
                for (int mt = 0; mt < 2; mt++) {
                    mma16816(acc3[mt][nt], afr[0][mt], bh);
                    mma16816(acc3[mt][nt], afr[0][mt], bl);
                    mma16816(acc3[mt][nt], afr[1][mt], bh);
                }
            }
        }
    }
    __syncthreads();

    // ================= PHASE 4: relu(.+rb3) dot r4, reduce ==================
    float part[2][2] = {{0.0f, 0.0f}, {0.0f, 0.0f}};
#pragma unroll
    for (int mt = 0; mt < 2; mt++)
#pragma unroll
        for (int nt = 0; nt < 2; nt++) {
            int col = wn * 16 + nt * 8 + (lane & 3) * 2;
            float b0 = rb3[col], b1 = rb3[col + 1];
            float r0 = r4[col], r1 = r4[col + 1];
            part[mt][0] += fmaxf(acc3[mt][nt][0] + b0, 0.0f) * r0
                         + fmaxf(acc3[mt][nt][1] + b1, 0.0f) * r1;
            part[mt][1] += fmaxf(acc3[mt][nt][2] + b0, 0.0f) * r0
                         + fmaxf(acc3[mt][nt][3] + b1, 0.0f) * r1;
        }
    float* sp = (float*)(smem + SPOFF);   // [128][4]
#pragma unroll
    for (int mt = 0; mt < 2; mt++)
#pragma unroll
        for (int h = 0; h < 2; h++) {
            float v = part[mt][h];
            v += __shfl_xor_sync(0xffffffffu, v, 1);
            v += __shfl_xor_sync(0xffffffffu, v, 2);
            if ((lane & 3) == 0)
                sp[(wm * 32 + mt * 16 + h * 8 + (lane >> 2)) * 4 + wn] = v;
        }
    __syncthreads();
    if (t < 128)
        out[m0 + t] = sp[t * 4] + sp[t * 4 + 1] + sp[t * 4 + 2] + sp[t * 4 + 3] + rb4[0];
}

// ---------------- launch -----------------------------------------------------
extern "C" void kernel_launch(void* const* d_in, const int* in_sizes, int n_in,
                              void* d_out, int out_size) {
    const float* op  = (const float*)d_in[0];
    const float* qp  = (const float*)d_in[1];
    const float* w1  = (const float*)d_in[2];
    const float* b1  = (const float*)d_in[3];
    const float* w2  = (const float*)d_in[4];
    const float* b2  = (const float*)d_in[5];
    const float* w3  = (const float*)d_in[6];
    const float* b3  = (const float*)d_in[7];
    const float* r1  = (const float*)d_in[8];
    const float* rb1 = (const float*)d_in[9];
    const float* r2  = (const float*)d_in[10];
    const float* rb2 = (const float*)d_in[11];
    const float* r3  = (const float*)d_in[12];
    const float* rb3 = (const float*)d_in[13];
    const float* r4  = (const float*)d_in[14];
    const float* rb4 = (const float*)d_in[15];
    float* out = (float*)d_out;

    float* p_fall;
    cudaGetSymbolAddress((void**)&p_fall, g_fall);
    __nv_bfloat16 *f1h, *f1l, *f2h, *f2l;
    __nv_bfloat16 *w2h, *w2l, *w3h, *w3l, *r1h, *r1l, *r2h, *r2l, *r3h, *r3l;
    cudaGetSymbolAddress((void**)&f1h, g_f1h);  cudaGetSymbolAddress((void**)&f1l, g_f1l);
    cudaGetSymbolAddress((void**)&f2h, g_f2h);  cudaGetSymbolAddress((void**)&f2l, g_f2l);
    cudaGetSymbolAddress((void**)&w2h, g_w2h);  cudaGetSymbolAddress((void**)&w2l, g_w2l);
    cudaGetSymbolAddress((void**)&w3h, g_w3h);  cudaGetSymbolAddress((void**)&w3l, g_w3l);
    cudaGetSymbolAddress((void**)&r1h, g_r1h);  cudaGetSymbolAddress((void**)&r1l, g_r1l);
    cudaGetSymbolAddress((void**)&r2h, g_r2h);  cudaGetSymbolAddress((void**)&r2l, g_r2l);
    cudaGetSymbolAddress((void**)&r3h, g_r3h);  cudaGetSymbolAddress((void**)&r3l, g_r3l);

    constexpr int SM256 = 2 * (2 * APL + 2 * 256 * PKB);   // 122880
    constexpr int SM128 = 2 * (2 * APL + 2 * 128 * PKB);   // 81920
    cudaFuncSetAttribute(tgemm_wide<256, true>,  cudaFuncAttributeMaxDynamicSharedMemorySize, SM256);
    cudaFuncSetAttribute(tgemm_wide<128, false>, cudaFuncAttributeMaxDynamicSharedMemorySize, SM128);
    cudaFuncSetAttribute(tgemm_mega, cudaFuncAttributeMaxDynamicSharedMemorySize, SMEGA);

    split_all_kernel<<<800, 256>>>(w2, w3, r1, r2, r3);
    gmax_zero_kernel<<<2, 256>>>();
    mlp1_kernel<<<MPTS / 8, 256>>>(op, w1, b1);
    // mlp2 64->128
    tgemm_wide<128, false><<<MPTS / 128, 512, SM128>>>(
        f1h, f1l, 64, w2h, w2l, b2, 64,
        p_fall + 64, FDIM, f2h, f2l, 128);
    // mlp3 128->256 + fused gmax
    tgemm_wide<256, true><<<MPTS / 128, 512, SM256>>>(
        f2h, f2l, 128, w3h, w3l, b3, 128,
        p_fall + 192, FDIM, nullptr, nullptr, 0);
    // gemm1 bias (rb1 + global-feature fold, fp32 exact)
    gbias_kernel<<<BATCH, 256>>>(r1, rb1);
    // knn: split halves + merge
    knn_part_kernel<<<dim3(NQ / 256, BATCH, 2), 256>>>(op, qp);
    knn_merge_kernel<<<NPTS / 256, 256>>>(op, qp);
    // mega regressor: interp+480->256->128->64->1, one kernel
    tgemm_mega<<<NPTS / 128, 512, SMEGA>>>(
        p_fall, qp, r1h, r1l, r2h, r2l, r3h, r3l, rb2, rb3, r4, rb4, out);
}

// round 11
// speedup vs baseline: 4.2305x; 1.0417x over previous
#include <cuda_runtime.h>
#include <cuda_bf16.h>
#include <math_constants.h>
#include <cstdint>

#define BATCH 2
#define NP    4096
#define NPH   2048           // half of NP (knn split)
#define NQ    16384
#define FDIM  448            // 64 + 128 + 256
#define AGK   480            // gemm1 K: 448 interp + 3 query + 29 pad
#define NPTS  (BATCH * NQ)   // 32768 query points
#define MPTS  (BATCH * NP)   // 8192 original points

// ---------------- scratch (device globals; no allocation allowed) -----------
__device__ float g_fall[MPTS * FDIM];          // point-major fp32 (f1|f2|f3)
__device__ int   g_gmax[BATCH * 256];
__device__ float g_b1[BATCH * 256];            // gemm1 bias incl. global feats
__device__ int   g_knni[NPTS * 3];
__device__ float g_knnw[NPTS * 3];
__device__ float g_kcd[NPTS * 6];              // knn candidates (2 halves x 3)
__device__ int   g_kci[NPTS * 6];
__device__ __nv_bfloat16 g_w2h[128 * 64],   g_w2l[128 * 64];
__device__ __nv_bfloat16 g_w3h[256 * 128],  g_w3l[256 * 128];
__device__ __nv_bfloat16 g_r1h[256 * AGK],  g_r1l[256 * AGK];   // remapped cols
__device__ __nv_bfloat16 g_r2h[128 * 256],  g_r2l[128 * 256];
__device__ __nv_bfloat16 g_r3h[64 * 128],   g_r3l[64 * 128];

// ---------------- helpers -----------------------------------------------------
__device__ __forceinline__ uint32_t smem_u32(const void* p) {
    uint32_t a;
    asm("{ .reg .u64 t; cvta.to.shared.u64 t, %1; cvt.u32.u64 %0, t; }" : "=r"(a) : "l"(p));
    return a;
}
__device__ __forceinline__ void cp16(uint32_t dst, const void* src) {
    asm volatile("cp.async.cg.shared.global [%0], [%1], 16;" :: "r"(dst), "l"(src));
}
#define CP_COMMIT() asm volatile("cp.async.commit_group;" ::: "memory")

__device__ __forceinline__ void ldm_x4(uint32_t* r, uint32_t addr) {
    asm volatile("ldmatrix.sync.aligned.m8n8.x4.shared.b16 {%0,%1,%2,%3}, [%4];"
                 : "=r"(r[0]), "=r"(r[1]), "=r"(r[2]), "=r"(r[3]) : "r"(addr));
}
__device__ __forceinline__ void mma16816(float* c, const uint32_t* a, const uint32_t* b) {
    asm volatile(
        "mma.sync.aligned.m16n8k16.row.col.f32.bf16.bf16.f32 "
        "{%0,%1,%2,%3}, {%4,%5,%6,%7}, {%8,%9}, {%0,%1,%2,%3};"
        : "+f"(c[0]), "+f"(c[1]), "+f"(c[2]), "+f"(c[3])
        : "r"(a[0]), "r"(a[1]), "r"(a[2]), "r"(a[3]), "r"(b[0]), "r"(b[1]));
}
__device__ __forceinline__ void split_bf16(float v, __nv_bfloat16& h, __nv_bfloat16& l) {
    h = __float2bfloat16(v);
    l = __float2bfloat16(v - __bfloat162float(h));
}
__device__ __forceinline__ uint32_t pck(__nv_bfloat16 a, __nv_bfloat16 b) {
    return (uint32_t)*(unsigned short*)&a | ((uint32_t)*(unsigned short*)&b << 16);
}

#define PKB 80                       // smem row pitch bytes (32 bf16 + 16B pad)
#define APL (128 * PKB)              // A plane bytes (10240)
#define H1CHK (2 * APL)              // one staged chunk: hi+lo planes (20480)

__global__ void gmax_zero_kernel() {
    int t = threadIdx.x + blockIdx.x * blockDim.x;
    if (t < BATCH * 256) g_gmax[t] = 0;
}

// ---------------- gemm1 bias: rb1 + global-feature contribution (fp32) -------
__global__ void __launch_bounds__(256) gbias_kernel(const float* __restrict__ r1,
                                                    const float* __restrict__ rb1) {
    int b = blockIdx.x, n = threadIdx.x;
    const float* wr = r1 + n * 707 + 451;
    float acc = rb1[n];
#pragma unroll 8
    for (int j = 0; j < 256; j++)
        acc = fmaf(wr[j], __int_as_float(g_gmax[b * 256 + j]), acc);
    g_b1[b * 256 + n] = acc;
}

// ---------------- single fused weight split (+pad, r1 remapped) --------------
__global__ void __launch_bounds__(256) split_all_kernel(
    const float* __restrict__ w2, const float* __restrict__ w3,
    const float* __restrict__ r1, const float* __restrict__ r2,
    const float* __restrict__ r3) {
    int i = blockIdx.x * 256 + threadIdx.x;
    if (i >= 204800) return;
    float v = 0.0f;
    __nv_bfloat16 *hi, *lo; int off;
    if (i < 8192) {
        off = i; hi = g_w2h; lo = g_w2l;
        v = w2[off];
    } else if (i < 40960) {
        off = i - 8192; hi = g_w3h; lo = g_w3l;
        v = w3[off];
    } else if (i < 163840) {
        off = i - 40960; hi = g_r1h; lo = g_r1l;
        int r = off / AGK, k = off - r * AGK;
        if (k < 448)      v = r1[r * 707 + 3 + k];     // interp channels
        else if (k < 451) v = r1[r * 707 + (k - 448)]; // query coords
    } else if (i < 196608) {
        off = i - 163840; hi = g_r2h; lo = g_r2l;
        v = r2[off];
    } else {
        off = i - 196608; hi = g_r3h; lo = g_r3l;
        v = r3[off];
    }
    __nv_bfloat16 h, l; split_bf16(v, h, l);
    hi[off] = h; lo[off] = l;
}

// ---------------- KNN part 1: top-3 within one half of the points ------------
__global__ void __launch_bounds__(256) knn_part_kernel(const float* __restrict__ op,
                                                       const float* __restrict__ qp) {
    __shared__ float4 sp[NPH];            // 32 KB
    int b = blockIdx.y, half = blockIdx.z;
    int tid = threadIdx.x;
    int jbase = half * NPH;
    for (int i = tid; i < NPH; i += 256) {
        float x = op[b * 3 * NP + 0 * NP + jbase + i];
        float y = op[b * 3 * NP + 1 * NP + jbase + i];
        float z = op[b * 3 * NP + 2 * NP + jbase + i];
        sp[i] = make_float4(x, y, z, fmaf(x, x, fmaf(y, y, z * z)));
    }
    __syncthreads();

    int q = blockIdx.x * 256 + tid;
    float qx = qp[b * 3 * NQ + 0 * NQ + q];
    float qy = qp[b * 3 * NQ + 1 * NQ + q];
    float qz = qp[b * 3 * NQ + 2 * NQ + q];
    float nx = -2.0f * qx, ny = -2.0f * qy, nz = -2.0f * qz;

    float d0 = CUDART_INF_F, d1 = CUDART_INF_F, d2 = CUDART_INF_F;
    int i0 = 0, i1 = 0, i2 = 0;
#pragma unroll 8
    for (int j = 0; j < NPH; j++) {
        float4 o = sp[j];
        float d = fmaf(o.x, nx, fmaf(o.y, ny, fmaf(o.z, nz, o.w)));
        if (d < d2) {
            if (d < d1) {
                d2 = d1; i2 = i1;
                if (d < d0) { d1 = d0; i1 = i0; d0 = d; i0 = j; }
                else        { d1 = d;  i1 = j; }
            } else { d2 = d; i2 = j; }
        }
    }
    int base = ((b * NQ + q) * 2 + half) * 3;
    g_kcd[base + 0] = d0; g_kci[base + 0] = jbase + i0;
    g_kcd[base + 1] = d1; g_kci[base + 1] = jbase + i1;
    g_kcd[base + 2] = d2; g_kci[base + 2] = jbase + i2;
}

// ---------------- KNN part 2: merge halves, compute weights ------------------
__global__ void __launch_bounds__(256) knn_merge_kernel(const float* __restrict__ op,
                                                        const float* __restrict__ qp) {
    int i = blockIdx.x * 256 + threadIdx.x;   // 0..NPTS-1
    int b = i >> 14, q = i & (NQ - 1);
    float d0 = CUDART_INF_F, d1 = CUDART_INF_F, d2 = CUDART_INF_F;
    int i0 = 0, i1 = 0, i2 = 0;
#pragma unroll
    for (int c = 0; c < 6; c++) {
        float d = g_kcd[i * 6 + c];
        int   j = g_kci[i * 6 + c];
        if (d < d2) {
            if (d < d1) {
                d2 = d1; i2 = i1;
                if (d < d0) { d1 = d0; i1 = i0; d0 = d; i0 = j; }
                else        { d1 = d;  i1 = j; }
            } else { d2 = d; i2 = j; }
        }
    }
    float qx = qp[b * 3 * NQ + 0 * NQ + q];
    float qy = qp[b * 3 * NQ + 1 * NQ + q];
    float qz = qp[b * 3 * NQ + 2 * NQ + q];
    int   ii[3] = {i0, i1, i2};
    float rc[3];
    float s = 0.0f;
#pragma unroll
    for (int k = 0; k < 3; k++) {
        float dx = op[b * 3 * NP + 0 * NP + ii[k]] - qx;
        float dy = op[b * 3 * NP + 1 * NP + ii[k]] - qy;
        float dz = op[b * 3 * NP + 2 * NP + ii[k]] - qz;
        float dist = sqrtf(fmaf(dx, dx, fmaf(dy, dy, dz * dz)));
        rc[k] = 1.0f / (dist + 1e-8f);
        s += rc[k];
    }
    float inv = 1.0f / s;
#pragma unroll
    for (int k = 0; k < 3; k++) {
        g_knni[i * 3 + k] = ii[k];
        g_knnw[i * 3 + k] = rc[k] * inv;
    }
}

// ---------------- FEATURE MEGA: mlp1 -> mlp2 -> mlp3 -> gmax, one kernel -----
// grid = MPTS/128 CTAs x 512 threads.  smem regions (164864 total):
//   [0,      40960)  f1 chunks (2 x 20480)
//   [40960, 122880)  f2 chunks (4 x 20480)
//   [122880,163840)  W buffer (W2: 2x10240 | W3: 2x20480)
//   [163840,164864)  w1 (192) + b1 (64) floats
#define FH1  0
#define FH2  40960
#define FWO  122880
#define FCO  163840
#define SMFEAT 164864

__global__ void __launch_bounds__(512) feature_mega(
    const float* __restrict__ op,
    const float* __restrict__ w1, const float* __restrict__ b1,
    const __nv_bfloat16* __restrict__ W2hi, const __nv_bfloat16* __restrict__ W2lo,
    const float* __restrict__ b2,
    const __nv_bfloat16* __restrict__ W3hi, const __nv_bfloat16* __restrict__ W3lo,
    const float* __restrict__ b3) {
    extern __shared__ char smem[];
    const int t = threadIdx.x;
    const int lane = t & 31, warp = t >> 5;
    const int wm = warp >> 2, wn = warp & 3;
    const int m0 = blockIdx.x * 128;
    const int b  = m0 >> 12;
    const int pt0 = m0 & (NP - 1);

    float* sw1 = (float*)(smem + FCO);
    float* sb1 = sw1 + 192;
    if (t < 192) sw1[t] = w1[t];
    else if (t < 256) sb1[t - 192] = b1[t - 192];
    __syncthreads();

    // ---- phase A: f1 = relu(w1*xyz + b1), fp32 to fall + smem chunks --------
#pragma unroll
    for (int u = 0; u < 2; u++) {
        int e = t + u * 512;
        int row = e >> 3, c8 = e & 7;
        int pt = pt0 + row;
        float x = op[b * 3 * NP + pt];
        float y = op[b * 3 * NP + NP + pt];
        float z = op[b * 3 * NP + 2 * NP + pt];
        float v[8];
        __nv_bfloat16 h[8], l[8];
#pragma unroll
        for (int j = 0; j < 8; j++) {
            int c = c8 * 8 + j;
            v[j] = fmaxf(fmaf(sw1[c*3], x, fmaf(sw1[c*3+1], y,
                        fmaf(sw1[c*3+2], z, sb1[c]))), 0.0f);
            split_bf16(v[j], h[j], l[j]);
        }
        float* fd = g_fall + (size_t)(m0 + row) * FDIM + c8 * 8;
        *(float4*)fd       = make_float4(v[0], v[1], v[2], v[3]);
        *(float4*)(fd + 4) = make_float4(v[4], v[5], v[6], v[7]);
        char* ckb = smem + FH1 + (c8 >> 2) * H1CHK;
        int off = row * PKB + (c8 & 3) * 16;
        *(uint4*)(ckb + off) =
            make_uint4(pck(h[0],h[1]), pck(h[2],h[3]), pck(h[4],h[5]), pck(h[6],h[7]));
        *(uint4*)(ckb + APL + off) =
            make_uint4(pck(l[0],l[1]), pck(l[2],l[3]), pck(l[4],l[5]), pck(l[6],l[7]));
    }
    __syncthreads();

    // ---- phase B: gemm 64 -> 128 (W2 streamed per chunk) --------------------
    constexpr int W2PL = 128 * PKB;   // 10240
    float acc2[2][4][4];
#pragma unroll
    for (int i = 0; i < 2; i++)
#pragma unroll
        for (int j = 0; j < 4; j++)
#pragma unroll
            for (int v = 0; v < 4; v++) acc2[i][j][v] = 0.0f;

    for (int c = 0; c < 2; c++) {
#pragma unroll
        for (int u = 0; u < 2; u++) {
            int e = t + u * 512;
            int pl = e >> 9, rem = e & 511;
            int row = rem >> 2, seg = rem & 3;
            const char* src = (const char*)(pl ? W2lo : W2hi)
                + ((size_t)row * 64 + c * 32) * 2 + seg * 16;
            cp16(smem_u32(smem + FWO + pl * W2PL + row * PKB + seg * 16), src);
        }
        CP_COMMIT();
        asm volatile("cp.async.wait_group 0;" ::: "memory");
        __syncthreads();

        char* abase = smem + FH1 + c * H1CHK;
#pragma unroll
        for (int kk = 0; kk < 2; kk++) {
            uint32_t afr[2][2][4];
#pragma unroll
            for (int pl = 0; pl < 2; pl++)
#pragma unroll
                for (int mt = 0; mt < 2; mt++) {
                    uint32_t a = smem_u32(abase + pl * APL
                        + (wm * 32 + mt * 16 + (lane & 15)) * PKB
                        + (kk * 16 + (lane >> 4) * 8) * 2);
                    ldm_x4(afr[pl][mt], a);
                }
#pragma unroll
            for (int nt = 0; nt < 4; nt++) {
                const char* bp = smem + FWO
                    + (wn * 32 + nt * 8 + (lane >> 2)) * PKB
                    + (kk * 16 + (lane & 3) * 2) * 2;
                uint32_t bh[2], bl[2];
                bh[0] = *(const uint32_t*)bp;
                bh[1] = *(const uint32_t*)(bp + 16);
                bl[0] = *(const uint32_t*)(bp + W2PL);
                bl[1] = *(const uint32_t*)(bp + W2PL + 16);
#pragma unroll
                for (int mt = 0; mt < 2; mt++) {
                    mma16816(acc2[mt][nt], afr[0][mt], bh);
                    mma16816(acc2[mt][nt], afr[0][mt], bl);
                    mma16816(acc2[mt][nt], afr[1][mt], bh);
                }
            }
        }
        __syncthreads();
    }

    // f2 = relu(acc2 + b2): fp32 to fall col 64.. + smem chunks
#pragma unroll
    for (int mt = 0; mt < 2; mt++)
#pragma unroll
        for (int nt = 0; nt < 4; nt++) {
            int rowl = wm * 32 + mt * 16 + (lane >> 2);
            int col = wn * 32 + nt * 8 + (lane & 3) * 2;
            float b0 = b2[col], b1v = b2[col + 1];
            float v0 = fmaxf(acc2[mt][nt][0] + b0, 0.0f);
            float v1 = fmaxf(acc2[mt][nt][1] + b1v, 0.0f);
            float v2 = fmaxf(acc2[mt][nt][2] + b0, 0.0f);
            float v3 = fmaxf(acc2[mt][nt][3] + b1v, 0.0f);
            *(float2*)(g_fall + (size_t)(m0 + rowl) * FDIM + 64 + col) = make_float2(v0, v1);
            *(float2*)(g_fall + (size_t)(m0 + rowl + 8) * FDIM + 64 + col) = make_float2(v2, v3);
            char* ckb = smem + FH2 + (col >> 5) * H1CHK;
            int ci = (col & 31) * 2;
            __nv_bfloat16 h0, l0, h1, l1;
            split_bf16(v0, h0, l0); split_bf16(v1, h1, l1);
            *(uint32_t*)(ckb + rowl * PKB + ci)       = pck(h0, h1);
            *(uint32_t*)(ckb + APL + rowl * PKB + ci) = pck(l0, l1);
            split_bf16(v2, h0, l0); split_bf16(v3, h1, l1);
            *(uint32_t*)(ckb + (rowl + 8) * PKB + ci)       = pck(h0, h1);
            *(uint32_t*)(ckb + APL + (rowl + 8) * PKB + ci) = pck(l0, l1);
        }
    __syncthreads();

    // ---- phase C: gemm 128 -> 256 (W3 streamed per chunk) -------------------
    constexpr int W3PL = 256 * PKB;   // 20480
    float acc3[2][8][4];
#pragma unroll
    for (int i = 0; i < 2; i++)
#pragma unroll
        for (int j = 0; j < 8; j++)
#pragma unroll
            for (int v = 0; v < 4; v++) acc3[i][j][v] = 0.0f;

    for (int c = 0; c < 4; c++) {
#pragma unroll
        for (int u = 0; u < 4; u++) {
            int e = t + u * 512;
            int pl = e >> 10, rem = e & 1023;
            int row = rem >> 2, seg = rem & 3;
            const char* src = (const char*)(pl ? W3lo : W3hi)
                + ((size_t)row * 128 + c * 32) * 2 + seg * 16;
            cp16(smem_u32(smem + FWO + pl * W3PL + row * PKB + seg * 16), src);
        }
        CP_COMMIT();
        asm volatile("cp.async.wait_group 0;" ::: "memory");
        __syncthreads();

        char* abase = smem + FH2 + c * H1CHK;
#pragma unroll
        for (int kk = 0; kk < 2; kk++) {
            uint32_t afr[2][2][4];
#pragma unroll
            for (int pl = 0; pl < 2; pl++)
#pragma unroll
                for (int mt = 0; mt < 2; mt++) {
                    uint32_t a = smem_u32(abase + pl * APL
                        + (wm * 32 + mt * 16 + (lane & 15)) * PKB
                        + (kk * 16 + (lane >> 4) * 8) * 2);
                    ldm_x4(afr[pl][mt], a);
                }
#pragma unroll
            for (int nt = 0; nt < 8; nt++) {
                const char* bp = smem + FWO
                    + (wn * 64 + nt * 8 + (lane >> 2)) * PKB
                    + (kk * 16 + (lane & 3) * 2) * 2;
                uint32_t bh[2], bl[2];
                bh[0] = *(const uint32_t*)bp;
                bh[1] = *(const uint32_t*)(bp + 16);
                bl[0] = *(const uint32_t*)(bp + W3PL);
                bl[1] = *(const uint32_t*)(bp + W3PL + 16);
#pragma unroll
                for (int mt = 0; mt < 2; mt++) {
                    mma16816(acc3[mt][nt], afr[0][mt], bh);
                    mma16816(acc3[mt][nt], afr[0][mt], bl);
                    mma16816(acc3[mt][nt], afr[1][mt], bh);
                }
            }
        }
        __syncthreads();
    }

    // f3 = relu(acc3 + b3): fp32 to fall col 192.. + fused gmax
#pragma unroll
    for (int mt = 0; mt < 2; mt++)
#pragma unroll
        for (int nt = 0; nt < 8; nt++) {
            int rowl = wm * 32 + mt * 16 + (lane >> 2);
            int col = wn * 64 + nt * 8 + (lane & 3) * 2;
            float b0 = b3[col], b1v = b3[col + 1];
            float v0 = fmaxf(acc3[mt][nt][0] + b0, 0.0f);
            float v1 = fmaxf(acc3[mt][nt][1] + b1v, 0.0f);
            float v2 = fmaxf(acc3[mt][nt][2] + b0, 0.0f);
            float v3 = fmaxf(acc3[mt][nt][3] + b1v, 0.0f);
            *(float2*)(g_fall + (size_t)(m0 + rowl) * FDIM + 192 + col) = make_float2(v0, v1);
            *(float2*)(g_fall + (size_t)(m0 + rowl + 8) * FDIM + 192 + col) = make_float2(v2, v3);
        }
#pragma unroll
    for (int nt = 0; nt < 8; nt++) {
        int col = wn * 64 + nt * 8 + (lane & 3) * 2;
        float b0 = b3[col], b1v = b3[col + 1];
        float mA = fmaxf(fmaxf(acc3[0][nt][0], acc3[0][nt][2]),
                         fmaxf(acc3[1][nt][0], acc3[1][nt][2])) + b0;
        float mB = fmaxf(fmaxf(acc3[0][nt][1], acc3[0][nt][3]),
                         fmaxf(acc3[1][nt][1], acc3[1][nt][3])) + b1v;
        mA = fmaxf(mA, 0.0f); mB = fmaxf(mB, 0.0f);
#pragma unroll
        for (int o = 4; o < 32; o <<= 1) {
            mA = fmaxf(mA, __shfl_xor_sync(0xffffffffu, mA, o));
            mB = fmaxf(mB, __shfl_xor_sync(0xffffffffu, mB, o));
        }
        if ((lane >> 2) == 0) {
            atomicMax(&g_gmax[b * 256 + col],     __float_as_int(mA));
            atomicMax(&g_gmax[b * 256 + col + 1], __float_as_int(mB));
        }
    }
}

// ---------------- MEGA: gemm1(interp,480->256) -> 256->128 -> 128->64 -> 1 ---
#define SS1    (2 * APL + 2 * 256 * PKB)   // 61440
#define W3CHK  (2 * 64 * PKB)              // 10240
#define G1OFF  40960
#define KOFF   163840
#define H1OFF  40960
#define W2OFF  204800
#define W2PLM  (128 * PKB)                 // 10240
#define H2OFF  40960
#define SPOFF  163840
#define SMEGA  225280

__global__ void __launch_bounds__(512) tgemm_mega(
    const float* __restrict__ fall, const float* __restrict__ qp,
    const __nv_bfloat16* __restrict__ W1hi, const __nv_bfloat16* __restrict__ W1lo,
    const __nv_bfloat16* __restrict__ W2hi, const __nv_bfloat16* __restrict__ W2lo,
    const __nv_bfloat16* __restrict__ W3hi, const __nv_bfloat16* __restrict__ W3lo,
    const float* __restrict__ rb2, const float* __restrict__ rb3,
    const float* __restrict__ r4, const float* __restrict__ rb4,
    float* __restrict__ out) {
    extern __shared__ char smem[];
    const int t = threadIdx.x;
    const int lane = t & 31, warp = t >> 5;
    const int wm = warp >> 2, wn = warp & 3;
    const int m0 = blockIdx.x * 128;
    const int b  = m0 >> 14;

    int*   si  = (int*)(smem + KOFF);
    float* swt = (float*)(smem + KOFF + 1536);
    if (t < 128) {
#pragma unroll
        for (int j = 0; j < 3; j++) {
            si[t * 3 + j]  = g_knni[(m0 + t) * 3 + j];
            swt[t * 3 + j] = g_knnw[(m0 + t) * 3 + j];
        }
    }

    // r3 preload into [0, 40960): joins the first cp.async group
    {
        char* w3b = smem;
#pragma unroll
        for (int u = 0; u < 4; u++) {
            int e = t + u * 512;
            int pl = e >> 10, rem = e & 1023;
            int ck = rem >> 8, r2m = rem & 255;
            int row = r2m >> 2, seg = r2m & 3;
            const char* src = (const char*)(pl ? W3lo : W3hi)
                + ((size_t)row * 128 + ck * 32) * 2 + seg * 16;
            cp16(smem_u32(w3b + ck * W3CHK + pl * (64 * PKB) + row * PKB + seg * 16), src);
        }
    }

    // ================= PHASE 1: gemm1 480 -> 256 =================
    constexpr int NC1 = AGK / 32;   // 15
    float acc[2][8][4];
#pragma unroll
    for (int i = 0; i < 2; i++)
#pragma unroll
        for (int j = 0; j < 8; j++)
#pragma unroll
            for (int v = 0; v < 4; v++) acc[i][j][v] = 0.0f;

    auto stageW1 = [&](int buf, int c) {
        char* base = smem + G1OFF + buf * SS1;
#pragma unroll
        for (int u = 0; u < 4; u++) {
            int e = t + u * 512;
            int pl = e >> 10, rem = e & 1023;
            int row = rem >> 2, seg = rem & 3;
            const char* src = (const char*)(pl ? W1lo : W1hi)
                + ((size_t)row * AGK + c * 32) * 2 + seg * 16;
            cp16(smem_u32(base + 2 * APL + pl * (256 * PKB) + row * PKB + seg * 16), src);
        }
        CP_COMMIT();
    };

    auto stageA1 = [&](char* base, int c) {
        const int ch0 = c * 32;
#pragma unroll
        for (int u = 0; u < 2; u++) {
            int e = t + u * 512;
            int row = e >> 3, c4 = e & 7;
            int ch = ch0 + c4 * 4;
            float v0, v1, v2, v3;
            if (ch < 448) {
                const float* fr = fall + (size_t)(b * NP) * FDIM + ch;
                float4 A = *(const float4*)(fr + (size_t)si[row * 3 + 0] * FDIM);
                float4 B = *(const float4*)(fr + (size_t)si[row * 3 + 1] * FDIM);
                float4 C = *(const float4*)(fr + (size_t)si[row * 3 + 2] * FDIM);
                float wa = swt[row * 3 + 0], wb = swt[row * 3 + 1], wc = swt[row * 3 + 2];
                v0 = wa * A.x + wb * B.x + wc * C.x;
                v1 = wa * A.y + wb * B.y + wc * C.y;
                v2 = wa * A.z + wb * B.z + wc * C.z;
                v3 = wa * A.w + wb * B.w + wc * C.w;
            } else if (ch == 448) {
                int qi = (m0 + row) & (NQ - 1);
                v0 = qp[b * 3 * NQ + 0 * NQ + qi];
                v1 = qp[b * 3 * NQ + 1 * NQ + qi];
                v2 = qp[b * 3 * NQ + 2 * NQ + qi];
                v3 = 0.0f;
            } else {
                v0 = v1 = v2 = v3 = 0.0f;
            }
            __nv_bfloat16 h0, l0, h1, l1, h2, l2, h3, l3;
            split_bf16(v0, h0, l0); split_bf16(v1, h1, l1);
            split_bf16(v2, h2, l2); split_bf16(v3, h3, l3);
            int off = row * PKB + (c4 >> 1) * 16 + (c4 & 1) * 8;
            *(uint2*)(base + off)       = make_uint2(pck(h0, h1), pck(h2, h3));
            *(uint2*)(base + APL + off) = make_uint2(pck(l0, l1), pck(l2, l3));
        }
    };

    __syncthreads();   // si/swt visible before stageA uses them
    stageW1(0, 0);
    for (int c = 0; c < NC1; c++) {
        char* base = smem + G1OFF + (c & 1) * SS1;
        stageA1(base, c);
        if (c + 1 < NC1) {
            stageW1((c + 1) & 1, c + 1);
            asm volatile("cp.async.wait_group 1;" ::: "memory");
        } else {
            asm volatile("cp.async.wait_group 0;" ::: "memory");
        }
        __syncthreads();
#pragma unroll
        for (int kk = 0; kk < 2; kk++) {
            uint32_t afr[2][2][4];
#pragma unroll
            for (int pl = 0; pl < 2; pl++)
#pragma unroll
                for (int mt = 0; mt < 2; mt++) {
                    uint32_t a = smem_u32(base + pl * APL
                        + (wm * 32 + mt * 16 + (lane & 15)) * PKB
                        + (kk * 16 + (lane >> 4) * 8) * 2);
                    ldm_x4(afr[pl][mt], a);
                }
#pragma unroll
            for (int nt = 0; nt < 8; nt++) {
                const char* bp = base + 2 * APL
                    + (wn * 64 + nt * 8 + (lane >> 2)) * PKB
                    + (kk * 16 + (lane & 3) * 2) * 2;
                uint32_t bh[2], bl[2];
                bh[0] = *(const uint32_t*)bp;
                bh[1] = *(const uint32_t*)(bp + 16);
                bl[0] = *(const uint32_t*)(bp + 256 * PKB);
                bl[1] = *(const uint32_t*)(bp + 256 * PKB + 16);
#pragma unroll
                for (int mt = 0; mt < 2; mt++) {
                    mma16816(acc[mt][nt], afr[0][mt], bh);
                    mma16816(acc[mt][nt], afr[0][mt], bl);
                    mma16816(acc[mt][nt], afr[1][mt], bh);
                }
            }
        }
        __syncthreads();
    }

    // h1 = relu(acc + g_b1) -> smem chunk layout
    {
        const float* bias = g_b1 + b * 256;
#pragma unroll
        for (int mt = 0; mt < 2; mt++)
#pragma unroll
            for (int nt = 0; nt < 8; nt++) {
                int rowl = wm * 32 + mt * 16 + (lane >> 2);
                int col = wn * 64 + nt * 8 + (lane & 3) * 2;
                float b0 = bias[col], b1 = bias[col + 1];
                float v0 = fmaxf(acc[mt][nt][0] + b0, 0.0f);
                float v1 = fmaxf(acc[mt][nt][1] + b1, 0.0f);
                float v2 = fmaxf(acc[mt][nt][2] + b0, 0.0f);
                float v3 = fmaxf(acc[mt][nt][3] + b1, 0.0f);
                char* ckb = smem + H1OFF + (col >> 5) * H1CHK;
                int ci = (col & 31) * 2;
                __nv_bfloat16 h0, l0, h1, l1;
                split_bf16(v0, h0, l0); split_bf16(v1, h1, l1);
                *(uint32_t*)(ckb + rowl * PKB + ci)       = pck(h0, h1);
                *(uint32_t*)(ckb + APL + rowl * PKB + ci) = pck(l0, l1);
                split_bf16(v2, h0, l0); split_bf16(v3, h1, l1);
                *(uint32_t*)(ckb + (rowl + 8) * PKB + ci)       = pck(h0, h1);
                *(uint32_t*)(ckb + APL + (rowl + 8) * PKB + ci) = pck(l0, l1);
            }
    }
    __syncthreads();

    // ================= PHASE 2: gemm2 256 -> 128 (W2 single buffer) ==========
    float acc2[2][4][4];
#pragma unroll
    for (int i = 0; i < 2; i++)
#pragma unroll
        for (int j = 0; j < 4; j++)
#pragma unroll
            for (int v = 0; v < 4; v++) acc2[i][j][v] = 0.0f;

    for (int c = 0; c < 8; c++) {
#pragma unroll
        for (int u = 0; u < 2; u++) {
            int e = t + u * 512;
            int pl = e >> 9, rem = e & 511;
            int row = rem >> 2, seg = rem & 3;
            const char* src = (const char*)(pl ? W2lo : W2hi)
                + ((size_t)row * 256 + c * 32) * 2 + seg * 16;
            cp16(smem_u32(smem + W2OFF + pl * W2PLM + row * PKB + seg * 16), src);
        }
        CP_COMMIT();
        asm volatile("cp.async.wait_group 0;" ::: "memory");
        __syncthreads();

        char* abase = smem + H1OFF + c * H1CHK;
#pragma unroll
        for (int kk = 0; kk < 2; kk++) {
            uint32_t afr[2][2][4];
#pragma unroll
            for (int pl = 0; pl < 2; pl++)
#pragma unroll
                for (int mt = 0; mt < 2; mt++) {
                    uint32_t a = smem_u32(abase + pl * APL
                        + (wm * 32 + mt * 16 + (lane & 15)) * PKB
                        + (kk * 16 + (lane >> 4) * 8) * 2);
                    ldm_x4(afr[pl][mt], a);
                }
#pragma unroll
            for (int nt = 0; nt < 4; nt++) {
                const char* bp = smem + W2OFF
                    + (wn * 32 + nt * 8 + (lane >> 2)) * PKB
                    + (kk * 16 + (lane & 3) * 2) * 2;
                uint32_t bh[2], bl[2];
                bh[0] = *(const uint32_t*)bp;
                bh[1] = *(const uint32_t*)(bp + 16);
                bl[0] = *(const uint32_t*)(bp + W2PLM);
                bl[1] = *(const uint32_t*)(bp + W2PLM + 16);
#pragma unroll
                for (int mt = 0; mt < 2; mt++) {
                    mma16816(acc2[mt][nt], afr[0][mt], bh);
                    mma16816(acc2[mt][nt], afr[0][mt], bl);
                    mma16816(acc2[mt][nt], afr[1][mt], bh);
                }
            }
        }
        __syncthreads();
    }

    // h2 = relu(acc2 + rb2) -> smem chunks
#pragma unroll
    for (int mt = 0; mt < 2; mt++)
#pragma unroll
        for (int nt = 0; nt < 4; nt++) {
            int rowl = wm * 32 + mt * 16 + (lane >> 2);
            int col = wn * 32 + nt * 8 + (lane & 3) * 2;
            float b0 = rb2[col], b1 = rb2[col + 1];
            float v0 = fmaxf(acc2[mt][nt][0] + b0, 0.0f);
            float v1 = fmaxf(acc2[mt][nt][1] + b1, 0.0f);
            float v2 = fmaxf(acc2[mt][nt][2] + b0, 0.0f);
            float v3 = fmaxf(acc2[mt][nt][3] + b1, 0.0f);
            char* ckb = smem + H2OFF + (col >> 5) * H1CHK;
            int ci = (col & 31) * 2;
            __nv_bfloat16 h0, l0, h1, l1;
            split_bf16(v0, h0, l0); split_bf16(v1, h1, l1);
            *(uint32_t*)(ckb + rowl * PKB + ci)       = pck(h0, h1);
            *(uint32_t*)(ckb + APL + rowl * PKB + ci) = pck(l0, l1);
            split_bf16(v2, h0, l0); split_bf16(v3, h1, l1);
            *(uint32_t*)(ckb + (rowl + 8) * PKB + ci)       = pck(h0, h1);
            *(uint32_t*)(ckb + APL + (rowl + 8) * PKB + ci) = pck(l0, l1);
        }
    __syncthreads();

    // ================= PHASE 3: gemm3 128 -> 64 (all smem) ===================
    float acc3[2][2][4];
#pragma unroll
    for (int i = 0; i < 2; i++)
#pragma unroll
        for (int j = 0; j < 2; j++)
#pragma unroll
            for (int v = 0; v < 4; v++) acc3[i][j][v] = 0.0f;

    for (int c = 0; c < 4; c++) {
        char* abase = smem + H2OFF + c * H1CHK;
        char* bbase = smem + c * W3CHK;
#pragma unroll
        for (int kk = 0; kk < 2; kk++) {
            uint32_t afr[2][2][4];
#pragma unroll
            for (int pl = 0; pl < 2; pl++)
#pragma unroll
                for (int mt = 0; mt < 2; mt++) {
                    uint32_t a = smem_u32(abase + pl * APL
                        + (wm * 32 + mt * 16 + (lane & 15)) * PKB
                        + (kk * 16 + (lane >> 4) * 8) * 2);
                    ldm_x4(afr[pl][mt], a);
                }
#pragma unroll
            for (int nt = 0; nt < 2; nt++) {
                const char* bp = bbase
                    + (wn * 16 + nt * 8 + (lane >> 2)) * PKB
                    + (kk * 16 + (lane & 3) * 2) * 2;
                uint32_t bh[2], bl[2];
                bh[0] = *(const uint32_t*)bp;
                bh[1] = *(const uint32_t*)(bp + 16);
                bl[0] = *(const uint32_t*)(bp + 64 * PKB);
                bl[1] = *(const uint32_t*)(bp + 64 * PKB + 16);
#pragma unroll
                for (int mt = 0; mt < 2; mt++) {
                    mma16816(acc3[mt][nt], afr[0][mt], bh);
                    mma16816(acc3[mt][nt], afr[0][mt], bl);
                    mma16816(acc3[mt][nt], afr[1][mt], bh);
                }
            }
        }
    }
    __syncthreads();

    // ================= PHASE 4: relu(.+rb3) dot r4, reduce ==================
    float part[2][2] = {{0.0f, 0.0f}, {0.0f, 0.0f}};
#pragma unroll
    for (int mt = 0; mt < 2; mt++)
#pragma unroll
        for (int nt = 0; nt < 2; nt++) {
            int col = wn * 16 + nt * 8 + (lane & 3) * 2;
            float b0 = rb3[col], b1 = rb3[col + 1];
            float r0 = r4[col], r1 = r4[col + 1];
            part[mt][0] += fmaxf(acc3[mt][nt][0] + b0, 0.0f) * r0
                         + fmaxf(acc3[mt][nt][1] + b1, 0.0f) * r1;
            part[mt][1] += fmaxf(acc3[mt][nt][2] + b0, 0.0f) * r0
                         + fmaxf(acc3[mt][nt][3] + b1, 0.0f) * r1;
        }
    float* sp = (float*)(smem + SPOFF);   // [128][4]
#pragma unroll
    for (int mt = 0; mt < 2; mt++)
#pragma unroll
        for (int h = 0; h < 2; h++) {
            float v = part[mt][h];
            v += __shfl_xor_sync(0xffffffffu, v, 1);
            v += __shfl_xor_sync(0xffffffffu, v, 2);
            if ((lane & 3) == 0)
                sp[(wm * 32 + mt * 16 + h * 8 + (lane >> 2)) * 4 + wn] = v;
        }
    __syncthreads();
    if (t < 128)
        out[m0 + t] = sp[t * 4] + sp[t * 4 + 1] + sp[t * 4 + 2] + sp[t * 4 + 3] + rb4[0];
}

// ---------------- launch -----------------------------------------------------
extern "C" void kernel_launch(void* const* d_in, const int* in_sizes, int n_in,
                              void* d_out, int out_size) {
    const float* op  = (const float*)d_in[0];
    const float* qp  = (const float*)d_in[1];
    const float* w1  = (const float*)d_in[2];
    const float* b1  = (const float*)d_in[3];
    const float* w2  = (const float*)d_in[4];
    const float* b2  = (const float*)d_in[5];
    const float* w3  = (const float*)d_in[6];
    const float* b3  = (const float*)d_in[7];
    const float* r1  = (const float*)d_in[8];
    const float* rb1 = (const float*)d_in[9];
    const float* r2  = (const float*)d_in[10];
    const float* rb2 = (const float*)d_in[11];
    const float* r3  = (const float*)d_in[12];
    const float* rb3 = (const float*)d_in[13];
    const float* r4  = (const float*)d_in[14];
    const float* rb4 = (const float*)d_in[15];
    float* out = (float*)d_out;

    float* p_fall;
    cudaGetSymbolAddress((void**)&p_fall, g_fall);
    __nv_bfloat16 *w2h, *w2l, *w3h, *w3l, *r1h, *r1l, *r2h, *r2l, *r3h, *r3l;
    cudaGetSymbolAddress((void**)&w2h, g_w2h);  cudaGetSymbolAddress((void**)&w2l, g_w2l);
    cudaGetSymbolAddress((void**)&w3h, g_w3h);  cudaGetSymbolAddress((void**)&w3l, g_w3l);
    cudaGetSymbolAddress((void**)&r1h, g_r1h);  cudaGetSymbolAddress((void**)&r1l, g_r1l);
    cudaGetSymbolAddress((void**)&r2h, g_r2h);  cudaGetSymbolAddress((void**)&r2l, g_r2l);
    cudaGetSymbolAddress((void**)&r3h, g_r3h);  cudaGetSymbolAddress((void**)&r3l, g_r3l);

    cudaFuncSetAttribute(feature_mega, cudaFuncAttributeMaxDynamicSharedMemorySize, SMFEAT);
    cudaFuncSetAttribute(tgemm_mega,   cudaFuncAttributeMaxDynamicSharedMemorySize, SMEGA);

    // fork: knn runs concurrently with the feature/weight chain
    cudaStream_t s2;
    cudaEvent_t e1, e2;
    cudaStreamCreateWithFlags(&s2, cudaStreamNonBlocking);
    cudaEventCreateWithFlags(&e1, cudaEventDisableTiming);
    cudaEventCreateWithFlags(&e2, cudaEventDisableTiming);
    cudaEventRecord(e1, 0);
    cudaStreamWaitEvent(s2, e1, 0);
    knn_part_kernel<<<dim3(NQ / 256, BATCH, 2), 256, 0, s2>>>(op, qp);
    knn_merge_kernel<<<NPTS / 256, 256, 0, s2>>>(op, qp);
    cudaEventRecord(e2, s2);

    // main stream: weights + features + bias fold
    split_all_kernel<<<800, 256>>>(w2, w3, r1, r2, r3);
    gmax_zero_kernel<<<2, 256>>>();
    feature_mega<<<MPTS / 128, 512, SMFEAT>>>(op, w1, b1, w2h, w2l, b2, w3h, w3l, b3);
    gbias_kernel<<<BATCH, 256>>>(r1, rb1);

    // join and run the regressor mega
    cudaStreamWaitEvent((cudaStream_t)0, e2, 0);
    tgemm_mega<<<NPTS / 128, 512, SMEGA>>>(
        p_fall, qp, r1h, r1l, r2h, r2l, r3h, r3l, rb2, rb3, r4, rb4, out);
}